// round 11
// baseline (speedup 1.0000x reference)
#include <cuda_runtime.h>
#include <math.h>

#define T_  1024
#define B_  2
#define E_  1024
#define H_  16
#define D_  64
#define TB_ 2048
#define RB_ 4094

// ---------------- scratch ----------------
__device__ float g_Win [3 * E_ * E_];
__device__ float g_Wpos[E_ * E_];
__device__ float g_Wout[E_ * E_];
__device__ float g_bin [3 * E_];
__device__ float g_bpos[E_];
__device__ float g_bout[E_];
__device__ float g_rw  [E_];
__device__ float g_rr  [E_];
__device__ float g_qkv [TB_ * 3 * E_];
__device__ float g_r   [RB_ * E_];
__device__ float g_att [TB_ * E_];

// ---------------- tf32 helpers ----------------
__device__ __forceinline__ unsigned f2tf(float f) {
    unsigned r; asm("cvt.rna.tf32.f32 %0, %1;" : "=r"(r) : "f"(f)); return r;
}
__device__ __forceinline__ void split2(float v, float& hi, float& lo) {
    hi = __uint_as_float(f2tf(v));
    lo = __uint_as_float(f2tf(v - hi));
}
__device__ __forceinline__ float4 splitpk(float a, float b) {
    float h0, l0, h1, l1;
    split2(a, h0, l0); split2(b, h1, l1);
    return make_float4(h0, l0, h1, l1);
}
__device__ __forceinline__ void mma8(float* c, const float* a, const float* b) {
    asm volatile("mma.sync.aligned.m16n8k8.row.col.f32.tf32.tf32.f32 "
                 "{%0,%1,%2,%3},{%4,%5,%6,%7},{%8,%9},{%0,%1,%2,%3};"
                 : "+f"(c[0]), "+f"(c[1]), "+f"(c[2]), "+f"(c[3])
                 : "r"(__float_as_uint(a[0])), "r"(__float_as_uint(a[1])),
                   "r"(__float_as_uint(a[2])), "r"(__float_as_uint(a[3])),
                   "r"(__float_as_uint(b[0])), "r"(__float_as_uint(b[1])));
}
__device__ __forceinline__ void mma3(float* c, const float* ah, const float* al,
                                     const float* bh, const float* bl) {
    mma8(c, ah, bh);
    mma8(c, ah, bl);
    mma8(c, al, bh);
}

// ---------------- fused hypernet ----------------
#define HN0 3145728
#define HN1 (HN0 + 1048576)
#define HN2 (HN1 + 1048576)
#define HN3 (HN2 + 3072)
#define HN4 (HN3 + 1024)
#define HN5 (HN4 + 1024)
#define HN6 (HN5 + 1024)
#define HN7 (HN6 + 1024)

__global__ __launch_bounds__(256) void hyper_all(
    const float* __restrict__ w_in,  const float* __restrict__ w_pos,
    const float* __restrict__ w_out, const float* __restrict__ b_in,
    const float* __restrict__ b_pos, const float* __restrict__ b_out,
    const float* __restrict__ rwb,   const float* __restrict__ rrb,
    const float* __restrict__ f,
    float* __restrict__ oWin,  float* __restrict__ oWpos,
    float* __restrict__ oWout, float* __restrict__ obin,
    float* __restrict__ obpos, float* __restrict__ obout,
    float* __restrict__ orw,   float* __restrict__ orr)
{
    int idx = blockIdx.x * blockDim.x + threadIdx.x;
    if (idx >= HN7) return;
    const float* src; float* dst; int off;
    if      (idx < HN0) { src = w_in;  dst = oWin;  off = idx; }
    else if (idx < HN1) { src = w_pos; dst = oWpos; off = idx - HN0; }
    else if (idx < HN2) { src = w_out; dst = oWout; off = idx - HN1; }
    else if (idx < HN3) { src = b_in;  dst = obin;  off = idx - HN2; }
    else if (idx < HN4) { src = b_pos; dst = obpos; off = idx - HN3; }
    else if (idx < HN5) { src = b_out; dst = obout; off = idx - HN4; }
    else if (idx < HN6) { src = rwb;   dst = orw;   off = idx - HN5; }
    else                { src = rrb;   dst = orr;   off = idx - HN6; }
    const float4* wp = (const float4*)(src + (size_t)off * 8);
    float4 a = wp[0], b = wp[1];
    float4 f0 = *(const float4*)f;
    float4 f1 = *(const float4*)(f + 4);
    dst[off] = a.x*f0.x + a.y*f0.y + a.z*f0.z + a.w*f0.w
             + b.x*f1.x + b.y*f1.y + b.z*f1.z + b.w*f1.w;
}

// ---------------- 3xtf32 NT GEMM with register double-buffer (R10, unchanged) --
#define GA_H 0
#define GA_L 4608
#define GB_H 9216
#define GB_L 13824
#define GEMM_SMEM (18432 * 4)

__global__ __launch_bounds__(256) void gemm3(const float* __restrict__ A,
                                             const float* __restrict__ Bm,
                                             const float* __restrict__ bias,
                                             float* __restrict__ C,
                                             int M, int N, int K)
{
    extern __shared__ float sm[];
    int bm = blockIdx.y * 128, bn = blockIdx.x * 128;
    int tid = threadIdx.x;
    int w = tid >> 5, lane = tid & 31;
    int g = lane >> 2, tg = lane & 3;
    int wm = w & 1, wn = w >> 1;
    float acc[4][4][4] = {};

    float4 pa[4], pb[4];
#pragma unroll
    for (int it = 0; it < 4; it++) {
        int t = tid + 256 * it;
        int row = t >> 3, kq = (t & 7) << 2;
        int m = bm + row;
        pa[it] = (m < M) ? *(const float4*)(A + (size_t)m * K + kq)
                         : make_float4(0.f, 0.f, 0.f, 0.f);
        pb[it] = *(const float4*)(Bm + (size_t)(bn + row) * K + kq);
    }

    for (int k0 = 0; k0 < K; k0 += 32) {
#pragma unroll
        for (int it = 0; it < 4; it++) {
            int t = tid + 256 * it;
            int row = t >> 3, kq = (t & 7) << 2;
            float4 ah, al;
            split2(pa[it].x, ah.x, al.x); split2(pa[it].y, ah.y, al.y);
            split2(pa[it].z, ah.z, al.z); split2(pa[it].w, ah.w, al.w);
            *(float4*)&sm[GA_H + row * 36 + kq] = ah;
            *(float4*)&sm[GA_L + row * 36 + kq] = al;
            float4 bh, bl;
            split2(pb[it].x, bh.x, bl.x); split2(pb[it].y, bh.y, bl.y);
            split2(pb[it].z, bh.z, bl.z); split2(pb[it].w, bh.w, bl.w);
            *(float4*)&sm[GB_H + row * 36 + kq] = bh;
            *(float4*)&sm[GB_L + row * 36 + kq] = bl;
        }
        __syncthreads();

        if (k0 + 32 < K) {
#pragma unroll
            for (int it = 0; it < 4; it++) {
                int t = tid + 256 * it;
                int row = t >> 3, kq = (t & 7) << 2;
                int m = bm + row;
                pa[it] = (m < M) ? *(const float4*)(A + (size_t)m * K + k0 + 32 + kq)
                                 : make_float4(0.f, 0.f, 0.f, 0.f);
                pb[it] = *(const float4*)(Bm + (size_t)(bn + row) * K + k0 + 32 + kq);
            }
        }

#pragma unroll
        for (int ks = 0; ks < 4; ks++) {
            float ah[4][4], al[4][4], bh[4][2], bl[4][2];
#pragma unroll
            for (int mi = 0; mi < 4; mi++) {
                int r0 = (wm * 64 + mi * 16 + g) * 36 + ks * 8 + tg;
                ah[mi][0] = sm[GA_H + r0];
                ah[mi][1] = sm[GA_H + r0 + 8 * 36];
                ah[mi][2] = sm[GA_H + r0 + 4];
                ah[mi][3] = sm[GA_H + r0 + 8 * 36 + 4];
                al[mi][0] = sm[GA_L + r0];
                al[mi][1] = sm[GA_L + r0 + 8 * 36];
                al[mi][2] = sm[GA_L + r0 + 4];
                al[mi][3] = sm[GA_L + r0 + 8 * 36 + 4];
            }
#pragma unroll
            for (int ni = 0; ni < 4; ni++) {
                int r0 = (wn * 32 + ni * 8 + g) * 36 + ks * 8 + tg;
                bh[ni][0] = sm[GB_H + r0];
                bh[ni][1] = sm[GB_H + r0 + 4];
                bl[ni][0] = sm[GB_L + r0];
                bl[ni][1] = sm[GB_L + r0 + 4];
            }
#pragma unroll
            for (int mi = 0; mi < 4; mi++)
#pragma unroll
                for (int ni = 0; ni < 4; ni++)
                    mma3(acc[mi][ni], ah[mi], al[mi], bh[ni], bl[ni]);
        }
        __syncthreads();
    }

#pragma unroll
    for (int mi = 0; mi < 4; mi++)
#pragma unroll
        for (int ni = 0; ni < 4; ni++) {
            int m0 = bm + wm * 64 + mi * 16 + g;
            int n0 = bn + wn * 32 + ni * 8 + tg * 2;
            float bb0 = bias[n0], bb1 = bias[n0 + 1];
            if (m0 < M) {
                float2 o = {acc[mi][ni][0] + bb0, acc[mi][ni][1] + bb1};
                *(float2*)(C + (size_t)m0 * N + n0) = o;
            }
            if (m0 + 8 < M) {
                float2 o = {acc[mi][ni][2] + bb0, acc[mi][ni][3] + bb1};
                *(float2*)(C + (size_t)(m0 + 8) * N + n0) = o;
            }
        }
}

// ---------------- fused attention: persistent q, interleaved hi/lo, prefetch ---
// layouts (float offsets):
//   QW/QR: 64 rows x 64 k interleaved, stride 136 (persistent across j loop)
//   AK: 128 x 16 interleaved, stride 40; AR: 192 x 16 interleaved, stride 40
//   AG aliases AK/AR after scores; AP aliases AG after shift; AV after AP
#define QW_  0
#define QR_  8704
#define AK   17408
#define AR   22528
#define AG   17408
#define AP   17408
#define AV   25856
#define ARMX 34560
#define ARSM 34816
#define ATTN_SMEM (35072 * 4)
#define SC_ 0.125f

__global__ __launch_bounds__(256) void attn_fused(const float* __restrict__ qkv,
                                                  const float* __restrict__ rproj,
                                                  const float* __restrict__ rw,
                                                  const float* __restrict__ rr,
                                                  float* __restrict__ att)
{
    extern __shared__ float sm[];
    const int bh = blockIdx.y;
    const int b = bh / H_, h = bh % H_;
    const int i0 = blockIdx.x * 64;
    const int tid = threadIdx.x;
    const int w = tid >> 5, lane = tid & 31;
    const int g = lane >> 2, tg = lane & 3;
    const int wi = w >> 2, wj = w & 3;

    // ---- persistent q staging: qw=(q+rw), qr=(q+rr), split+interleaved
#pragma unroll
    for (int it = 0; it < 4; it++) {
        int idx = tid + 256 * it;
        int row = idx >> 4, kq = (idx & 15) << 2;
        float4 qv = *(const float4*)(qkv + (size_t)((i0 + row) * B_ + b) * (3 * E_) + h * D_ + kq);
        float4 rwv = *(const float4*)(rw + h * D_ + kq);
        float4 rrv = *(const float4*)(rr + h * D_ + kq);
        *(float4*)&sm[QW_ + row * 136 + kq * 2]     = splitpk(qv.x + rwv.x, qv.y + rwv.y);
        *(float4*)&sm[QW_ + row * 136 + kq * 2 + 4] = splitpk(qv.z + rwv.z, qv.w + rwv.w);
        *(float4*)&sm[QR_ + row * 136 + kq * 2]     = splitpk(qv.x + rrv.x, qv.y + rrv.y);
        *(float4*)&sm[QR_ + row * 136 + kq * 2 + 4] = splitpk(qv.z + rrv.z, qv.w + rrv.w);
    }

    float m_run[2][2] = {{-1e30f, -1e30f}, {-1e30f, -1e30f}};
    float l_run[2][2] = {};
    float accO[2][2][4] = {};

    for (int j0 = 0; j0 < T_; j0 += 128) {
        const int pmin = j0 - i0 + (T_ - 64);
        float accA[2][4][4] = {};
        float accG[2][6][4] = {};

        // prefetch chunk 0 (k, r)
        float4 pk[2], prr[3];
#pragma unroll
        for (int it = 0; it < 2; it++) {
            int t = tid + 256 * it;
            int il = t >> 2, kq = (t & 3) << 2;
            pk[it] = *(const float4*)(qkv + (size_t)((j0 + il) * B_ + b) * (3 * E_) + E_ + h * D_ + kq);
        }
#pragma unroll
        for (int it = 0; it < 3; it++) {
            int t = tid + 256 * it;
            int pl = t >> 2, kq = (t & 3) << 2;
            prr[it] = (pl < 191)
                ? *(const float4*)(rproj + (size_t)((pmin + pl) * B_ + b) * E_ + h * D_ + kq)
                : make_float4(0.f, 0.f, 0.f, 0.f);
        }

        for (int c = 0; c < 4; c++) {
            __syncthreads();
            // store k/r split+interleaved
#pragma unroll
            for (int it = 0; it < 2; it++) {
                int t = tid + 256 * it;
                int il = t >> 2, kq = (t & 3) << 2;
                *(float4*)&sm[AK + il * 40 + kq * 2]     = splitpk(pk[it].x, pk[it].y);
                *(float4*)&sm[AK + il * 40 + kq * 2 + 4] = splitpk(pk[it].z, pk[it].w);
            }
#pragma unroll
            for (int it = 0; it < 3; it++) {
                int t = tid + 256 * it;
                int pl = t >> 2, kq = (t & 3) << 2;
                *(float4*)&sm[AR + pl * 40 + kq * 2]     = splitpk(prr[it].x, prr[it].y);
                *(float4*)&sm[AR + pl * 40 + kq * 2 + 4] = splitpk(prr[it].z, prr[it].w);
            }
            __syncthreads();
            // prefetch chunk c+1 during compute
            if (c < 3) {
                const int col0n = h * D_ + (c + 1) * 16;
#pragma unroll
                for (int it = 0; it < 2; it++) {
                    int t = tid + 256 * it;
                    int il = t >> 2, kq = (t & 3) << 2;
                    pk[it] = *(const float4*)(qkv + (size_t)((j0 + il) * B_ + b) * (3 * E_) + E_ + col0n + kq);
                }
#pragma unroll
                for (int it = 0; it < 3; it++) {
                    int t = tid + 256 * it;
                    int pl = t >> 2, kq = (t & 3) << 2;
                    prr[it] = (pl < 191)
                        ? *(const float4*)(rproj + (size_t)((pmin + pl) * B_ + b) * E_ + col0n + kq)
                        : make_float4(0.f, 0.f, 0.f, 0.f);
                }
            }
#pragma unroll
            for (int ks = 0; ks < 2; ks++) {
                float aW[2][4], aWl[2][4], aR_[2][4], aRl[2][4];
#pragma unroll
                for (int mi = 0; mi < 2; mi++) {
                    int ra = (wi * 32 + mi * 16 + g) * 136 + (c * 16 + ks * 8 + tg) * 2;
                    float2 t0 = *(float2*)&sm[QW_ + ra];
                    float2 t1 = *(float2*)&sm[QW_ + ra + 1088];
                    float2 t2 = *(float2*)&sm[QW_ + ra + 8];
                    float2 t3 = *(float2*)&sm[QW_ + ra + 1096];
                    aW[mi][0] = t0.x; aWl[mi][0] = t0.y;
                    aW[mi][1] = t1.x; aWl[mi][1] = t1.y;
                    aW[mi][2] = t2.x; aWl[mi][2] = t2.y;
                    aW[mi][3] = t3.x; aWl[mi][3] = t3.y;
                    t0 = *(float2*)&sm[QR_ + ra];
                    t1 = *(float2*)&sm[QR_ + ra + 1088];
                    t2 = *(float2*)&sm[QR_ + ra + 8];
                    t3 = *(float2*)&sm[QR_ + ra + 1096];
                    aR_[mi][0] = t0.x; aRl[mi][0] = t0.y;
                    aR_[mi][1] = t1.x; aRl[mi][1] = t1.y;
                    aR_[mi][2] = t2.x; aRl[mi][2] = t2.y;
                    aR_[mi][3] = t3.x; aRl[mi][3] = t3.y;
                }
#pragma unroll
                for (int nj = 0; nj < 4; nj++) {
                    int rb = (wj * 32 + nj * 8 + g) * 40 + (ks * 8 + tg) * 2;
                    float2 b0 = *(float2*)&sm[AK + rb];
                    float2 b1 = *(float2*)&sm[AK + rb + 8];
                    float bhf[2] = {b0.x, b1.x}, blf[2] = {b0.y, b1.y};
                    mma3(accA[0][nj], aW[0], aWl[0], bhf, blf);
                    mma3(accA[1][nj], aW[1], aWl[1], bhf, blf);
                }
#pragma unroll
                for (int ng = 0; ng < 6; ng++) {
                    int rb = (wj * 48 + ng * 8 + g) * 40 + (ks * 8 + tg) * 2;
                    float2 b0 = *(float2*)&sm[AR + rb];
                    float2 b1 = *(float2*)&sm[AR + rb + 8];
                    float bhf[2] = {b0.x, b1.x}, blf[2] = {b0.y, b1.y};
                    mma3(accG[0][ng], aR_[0], aRl[0], bhf, blf);
                    mma3(accG[1][ng], aR_[1], aRl[1], bhf, blf);
                }
            }
        }
        __syncthreads();

        // stage G[64][196] (aliases AK/AR)
#pragma unroll
        for (int mi = 0; mi < 2; mi++)
#pragma unroll
            for (int ng = 0; ng < 6; ng++) {
                int row = wi * 32 + mi * 16 + g;
                int cc = wj * 48 + ng * 8 + tg * 2;
                sm[AG + row * 196 + cc]           = accG[mi][ng][0];
                sm[AG + row * 196 + cc + 1]       = accG[mi][ng][1];
                sm[AG + (row + 8) * 196 + cc]     = accG[mi][ng][2];
                sm[AG + (row + 8) * 196 + cc + 1] = accG[mi][ng][3];
            }
        __syncthreads();

        float tmax[2][2] = {{-1e30f, -1e30f}, {-1e30f, -1e30f}};
#pragma unroll
        for (int mi = 0; mi < 2; mi++)
#pragma unroll
            for (int nj = 0; nj < 4; nj++) {
                int il = wi * 32 + mi * 16 + g;
                int jl = wj * 32 + nj * 8 + tg * 2;
                int il2 = il + 8;
                accA[mi][nj][0] += sm[AG + il * 196 + (jl - il + 63)];
                accA[mi][nj][1] += sm[AG + il * 196 + (jl + 1 - il + 63)];
                accA[mi][nj][2] += sm[AG + il2 * 196 + (jl - il2 + 63)];
                accA[mi][nj][3] += sm[AG + il2 * 196 + (jl + 1 - il2 + 63)];
                tmax[mi][0] = fmaxf(tmax[mi][0], fmaxf(accA[mi][nj][0], accA[mi][nj][1]));
                tmax[mi][1] = fmaxf(tmax[mi][1], fmaxf(accA[mi][nj][2], accA[mi][nj][3]));
            }
#pragma unroll
        for (int mi = 0; mi < 2; mi++)
#pragma unroll
            for (int rp = 0; rp < 2; rp++) {
                float v = tmax[mi][rp];
                v = fmaxf(v, __shfl_xor_sync(0xffffffffu, v, 1));
                v = fmaxf(v, __shfl_xor_sync(0xffffffffu, v, 2));
                tmax[mi][rp] = v;
            }
        if (tg == 0) {
#pragma unroll
            for (int mi = 0; mi < 2; mi++)
#pragma unroll
                for (int rp = 0; rp < 2; rp++) {
                    int row = wi * 32 + mi * 16 + g + rp * 8;
                    sm[ARMX + row * 4 + wj] = tmax[mi][rp];
                }
        }
        __syncthreads();

        float mnew[2][2], fsc[2][2];
#pragma unroll
        for (int mi = 0; mi < 2; mi++)
#pragma unroll
            for (int rp = 0; rp < 2; rp++) {
                int row = wi * 32 + mi * 16 + g + rp * 8;
                float mt = fmaxf(fmaxf(sm[ARMX + row * 4 + 0], sm[ARMX + row * 4 + 1]),
                                 fmaxf(sm[ARMX + row * 4 + 2], sm[ARMX + row * 4 + 3]));
                mnew[mi][rp] = fmaxf(m_run[mi][rp], mt);
                fsc[mi][rp] = __expf((m_run[mi][rp] - mnew[mi][rp]) * SC_);
            }

        float tsum[2][2] = {};
#pragma unroll
        for (int mi = 0; mi < 2; mi++)
#pragma unroll
            for (int nj = 0; nj < 4; nj++) {
                int il = wi * 32 + mi * 16 + g;
                int jl = wj * 32 + nj * 8 + tg * 2;
                float p0 = __expf((accA[mi][nj][0] - mnew[mi][0]) * SC_);
                float p1 = __expf((accA[mi][nj][1] - mnew[mi][0]) * SC_);
                float p2 = __expf((accA[mi][nj][2] - mnew[mi][1]) * SC_);
                float p3 = __expf((accA[mi][nj][3] - mnew[mi][1]) * SC_);
                tsum[mi][0] += p0 + p1;
                tsum[mi][1] += p2 + p3;
                sm[AP + il * 132 + jl]           = __uint_as_float(f2tf(p0));
                sm[AP + il * 132 + jl + 1]       = __uint_as_float(f2tf(p1));
                sm[AP + (il + 8) * 132 + jl]     = __uint_as_float(f2tf(p2));
                sm[AP + (il + 8) * 132 + jl + 1] = __uint_as_float(f2tf(p3));
            }

        // prefetch V tile for jc=0 (overlaps reductions)
        float4 pv[4];
#pragma unroll
        for (int it = 0; it < 4; it++) {
            int t = tid + 256 * it;
            int row = t >> 4, dq = (t & 15) << 2;
            pv[it] = *(const float4*)(qkv + (size_t)((j0 + row) * B_ + b) * (3 * E_)
                                      + 2 * E_ + h * D_ + dq);
        }

#pragma unroll
        for (int mi = 0; mi < 2; mi++)
#pragma unroll
            for (int rp = 0; rp < 2; rp++) {
                float v = tsum[mi][rp];
                v += __shfl_xor_sync(0xffffffffu, v, 1);
                v += __shfl_xor_sync(0xffffffffu, v, 2);
                tsum[mi][rp] = v;
            }
        if (tg == 0) {
#pragma unroll
            for (int mi = 0; mi < 2; mi++)
#pragma unroll
                for (int rp = 0; rp < 2; rp++) {
                    int row = wi * 32 + mi * 16 + g + rp * 8;
                    sm[ARSM + row * 4 + wj] = tsum[mi][rp];
                }
        }
        __syncthreads();

#pragma unroll
        for (int mi = 0; mi < 2; mi++)
#pragma unroll
            for (int rp = 0; rp < 2; rp++) {
                int row = wi * 32 + mi * 16 + g + rp * 8;
                float lt = sm[ARSM + row * 4 + 0] + sm[ARSM + row * 4 + 1]
                         + sm[ARSM + row * 4 + 2] + sm[ARSM + row * 4 + 3];
                l_run[mi][rp] = l_run[mi][rp] * fsc[mi][rp] + lt;
                m_run[mi][rp] = mnew[mi][rp];
            }
#pragma unroll
        for (int mi = 0; mi < 2; mi++)
#pragma unroll
            for (int nd = 0; nd < 2; nd++) {
                accO[mi][nd][0] *= fsc[mi][0];
                accO[mi][nd][1] *= fsc[mi][0];
                accO[mi][nd][2] *= fsc[mi][1];
                accO[mi][nd][3] *= fsc[mi][1];
            }

        // PV: V interleaved stride 136
        for (int jc = 0; jc < 2; jc++) {
            __syncthreads();
#pragma unroll
            for (int it = 0; it < 4; it++) {
                int t = tid + 256 * it;
                int row = t >> 4, dq = (t & 15) << 2;
                *(float4*)&sm[AV + row * 136 + dq * 2]     = splitpk(pv[it].x, pv[it].y);
                *(float4*)&sm[AV + row * 136 + dq * 2 + 4] = splitpk(pv[it].z, pv[it].w);
            }
            __syncthreads();
            if (jc == 0) {
#pragma unroll
                for (int it = 0; it < 4; it++) {
                    int t = tid + 256 * it;
                    int row = t >> 4, dq = (t & 15) << 2;
                    pv[it] = *(const float4*)(qkv + (size_t)((j0 + 64 + row) * B_ + b) * (3 * E_)
                                              + 2 * E_ + h * D_ + dq);
                }
            }
#pragma unroll
            for (int ks = 0; ks < 8; ks++) {
                float a[2][4];
#pragma unroll
                for (int mi = 0; mi < 2; mi++) {
                    int r0 = (wi * 32 + mi * 16 + g) * 132 + jc * 64 + ks * 8 + tg;
                    a[mi][0] = sm[AP + r0];
                    a[mi][1] = sm[AP + r0 + 8 * 132];
                    a[mi][2] = sm[AP + r0 + 4];
                    a[mi][3] = sm[AP + r0 + 8 * 132 + 4];
                }
#pragma unroll
                for (int nd = 0; nd < 2; nd++) {
                    int col = wj * 16 + nd * 8 + g;
                    float2 v0 = *(float2*)&sm[AV + (ks * 8 + tg) * 136 + col * 2];
                    float2 v1 = *(float2*)&sm[AV + (ks * 8 + tg + 4) * 136 + col * 2];
                    float vh[2] = {v0.x, v1.x}, vl[2] = {v0.y, v1.y};
#pragma unroll
                    for (int mi = 0; mi < 2; mi++) {
                        mma8(accO[mi][nd], a[mi], vh);
                        mma8(accO[mi][nd], a[mi], vl);
                    }
                }
            }
        }
    }

    float inv[2][2];
#pragma unroll
    for (int mi = 0; mi < 2; mi++)
#pragma unroll
        for (int rp = 0; rp < 2; rp++)
            inv[mi][rp] = 1.0f / l_run[mi][rp];
#pragma unroll
    for (int mi = 0; mi < 2; mi++)
#pragma unroll
        for (int nd = 0; nd < 2; nd++) {
            int row = wi * 32 + mi * 16 + g;
            int col = h * D_ + wj * 16 + nd * 8 + tg * 2;
            float2 o0 = {accO[mi][nd][0] * inv[mi][0], accO[mi][nd][1] * inv[mi][0]};
            float2 o1 = {accO[mi][nd][2] * inv[mi][1], accO[mi][nd][3] * inv[mi][1]};
            *(float2*)(att + (size_t)((i0 + row) * B_ + b) * E_ + col) = o0;
            *(float2*)(att + (size_t)((i0 + row + 8) * B_ + b) * E_ + col) = o1;
        }
}

// ---------------- launch ----------------
extern "C" void kernel_launch(void* const* d_in, const int* in_sizes, int n_in,
                              void* d_out, int out_size)
{
    (void)in_sizes; (void)n_in; (void)out_size;
    const float* input  = (const float*)d_in[0];
    const float* pos    = (const float*)d_in[1];
    const float* factor = (const float*)d_in[2];
    const float* w_in   = (const float*)d_in[3];
    const float* w_pos  = (const float*)d_in[4];
    const float* w_out  = (const float*)d_in[5];
    const float* bw_in  = (const float*)d_in[6];
    const float* bw_pos = (const float*)d_in[7];
    const float* bw_out = (const float*)d_in[8];
    const float* rwb    = (const float*)d_in[9];
    const float* rrb    = (const float*)d_in[10];

    float *pWin, *pWpos, *pWout, *pbin, *pbpos, *pbout, *prw, *prr,
          *pqkv, *pr, *patt;
    cudaGetSymbolAddress((void**)&pWin,  g_Win);
    cudaGetSymbolAddress((void**)&pWpos, g_Wpos);
    cudaGetSymbolAddress((void**)&pWout, g_Wout);
    cudaGetSymbolAddress((void**)&pbin,  g_bin);
    cudaGetSymbolAddress((void**)&pbpos, g_bpos);
    cudaGetSymbolAddress((void**)&pbout, g_bout);
    cudaGetSymbolAddress((void**)&prw,   g_rw);
    cudaGetSymbolAddress((void**)&prr,   g_rr);
    cudaGetSymbolAddress((void**)&pqkv,  g_qkv);
    cudaGetSymbolAddress((void**)&pr,    g_r);
    cudaGetSymbolAddress((void**)&patt,  g_att);

    cudaFuncSetAttribute(gemm3,      cudaFuncAttributeMaxDynamicSharedMemorySize, GEMM_SMEM);
    cudaFuncSetAttribute(attn_fused, cudaFuncAttributeMaxDynamicSharedMemorySize, ATTN_SMEM);

    // 1) hypernet
    hyper_all<<<(HN7 + 255) / 256, 256>>>(w_in, w_pos, w_out, bw_in, bw_pos, bw_out,
                                          rwb, rrb, factor,
                                          pWin, pWpos, pWout, pbin, pbpos, pbout, prw, prr);

    // 2) projections (3xtf32, register double-buffered)
    gemm3<<<dim3(3 * E_ / 128, TB_ / 128), 256, GEMM_SMEM>>>(input, pWin, pbin, pqkv, TB_, 3 * E_, E_);
    gemm3<<<dim3(E_ / 128, (RB_ + 127) / 128), 256, GEMM_SMEM>>>(pos, pWpos, pbpos, pr, RB_, E_, E_);

    // 3) fused attention (persistent q, interleaved smem, gmem prefetch)
    attn_fused<<<dim3(T_ / 64, B_ * H_), 256, ATTN_SMEM>>>(pqkv, pr, prw, prr, patt);

    // 4) output projection -> d_out
    gemm3<<<dim3(E_ / 128, TB_ / 128), 256, GEMM_SMEM>>>(patt, pWout, pbout, (float*)d_out, TB_, E_, E_);
}

// round 12
// speedup vs baseline: 1.1014x; 1.1014x over previous
#include <cuda_runtime.h>
#include <math.h>

#define T_  1024
#define B_  2
#define E_  1024
#define H_  16
#define D_  64
#define TB_ 2048
#define RB_ 4094

// ---------------- scratch ----------------
__device__ float g_Win [3 * E_ * E_];
__device__ float g_Wpos[E_ * E_];
__device__ float g_Wout[E_ * E_];
__device__ float g_bin [3 * E_];
__device__ float g_bpos[E_];
__device__ float g_bout[E_];
__device__ float g_rw  [E_];
__device__ float g_rr  [E_];
__device__ float g_qkv [TB_ * 3 * E_];
__device__ float g_r   [RB_ * E_];
__device__ float g_att [TB_ * E_];

// ---------------- tf32 helpers ----------------
__device__ __forceinline__ unsigned f2tf(float f) {
    unsigned r; asm("cvt.rna.tf32.f32 %0, %1;" : "=r"(r) : "f"(f)); return r;
}
__device__ __forceinline__ void split2(float v, float& hi, float& lo) {
    hi = __uint_as_float(f2tf(v));
    lo = __uint_as_float(f2tf(v - hi));
}
__device__ __forceinline__ void mma8(float* c, const float* a, const float* b) {
    asm volatile("mma.sync.aligned.m16n8k8.row.col.f32.tf32.tf32.f32 "
                 "{%0,%1,%2,%3},{%4,%5,%6,%7},{%8,%9},{%0,%1,%2,%3};"
                 : "+f"(c[0]), "+f"(c[1]), "+f"(c[2]), "+f"(c[3])
                 : "r"(__float_as_uint(a[0])), "r"(__float_as_uint(a[1])),
                   "r"(__float_as_uint(a[2])), "r"(__float_as_uint(a[3])),
                   "r"(__float_as_uint(b[0])), "r"(__float_as_uint(b[1])));
}
__device__ __forceinline__ void mma3(float* c, const float* ah, const float* al,
                                     const float* bh, const float* bl) {
    mma8(c, ah, bh);
    mma8(c, ah, bl);
    mma8(c, al, bh);
}

// ---------------- fused hypernet ----------------
#define HN0 3145728
#define HN1 (HN0 + 1048576)
#define HN2 (HN1 + 1048576)
#define HN3 (HN2 + 3072)
#define HN4 (HN3 + 1024)
#define HN5 (HN4 + 1024)
#define HN6 (HN5 + 1024)
#define HN7 (HN6 + 1024)

__global__ __launch_bounds__(256) void hyper_all(
    const float* __restrict__ w_in,  const float* __restrict__ w_pos,
    const float* __restrict__ w_out, const float* __restrict__ b_in,
    const float* __restrict__ b_pos, const float* __restrict__ b_out,
    const float* __restrict__ rwb,   const float* __restrict__ rrb,
    const float* __restrict__ f,
    float* __restrict__ oWin,  float* __restrict__ oWpos,
    float* __restrict__ oWout, float* __restrict__ obin,
    float* __restrict__ obpos, float* __restrict__ obout,
    float* __restrict__ orw,   float* __restrict__ orr)
{
    int idx = blockIdx.x * blockDim.x + threadIdx.x;
    if (idx >= HN7) return;
    const float* src; float* dst; int off;
    if      (idx < HN0) { src = w_in;  dst = oWin;  off = idx; }
    else if (idx < HN1) { src = w_pos; dst = oWpos; off = idx - HN0; }
    else if (idx < HN2) { src = w_out; dst = oWout; off = idx - HN1; }
    else if (idx < HN3) { src = b_in;  dst = obin;  off = idx - HN2; }
    else if (idx < HN4) { src = b_pos; dst = obpos; off = idx - HN3; }
    else if (idx < HN5) { src = b_out; dst = obout; off = idx - HN4; }
    else if (idx < HN6) { src = rwb;   dst = orw;   off = idx - HN5; }
    else                { src = rrb;   dst = orr;   off = idx - HN6; }
    const float4* wp = (const float4*)(src + (size_t)off * 8);
    float4 a = wp[0], b = wp[1];
    float4 f0 = *(const float4*)f;
    float4 f1 = *(const float4*)(f + 4);
    dst[off] = a.x*f0.x + a.y*f0.y + a.z*f0.z + a.w*f0.w
             + b.x*f1.x + b.y*f1.y + b.z*f1.z + b.w*f1.w;
}

// ---------------- 3xtf32 NT GEMM with register double-buffer (R10, unchanged) --
#define GA_H 0
#define GA_L 4608
#define GB_H 9216
#define GB_L 13824
#define GEMM_SMEM (18432 * 4)

__global__ __launch_bounds__(256) void gemm3(const float* __restrict__ A,
                                             const float* __restrict__ Bm,
                                             const float* __restrict__ bias,
                                             float* __restrict__ C,
                                             int M, int N, int K)
{
    extern __shared__ float sm[];
    int bm = blockIdx.y * 128, bn = blockIdx.x * 128;
    int tid = threadIdx.x;
    int w = tid >> 5, lane = tid & 31;
    int g = lane >> 2, tg = lane & 3;
    int wm = w & 1, wn = w >> 1;
    float acc[4][4][4] = {};

    float4 pa[4], pb[4];
#pragma unroll
    for (int it = 0; it < 4; it++) {
        int t = tid + 256 * it;
        int row = t >> 3, kq = (t & 7) << 2;
        int m = bm + row;
        pa[it] = (m < M) ? *(const float4*)(A + (size_t)m * K + kq)
                         : make_float4(0.f, 0.f, 0.f, 0.f);
        pb[it] = *(const float4*)(Bm + (size_t)(bn + row) * K + kq);
    }

    for (int k0 = 0; k0 < K; k0 += 32) {
#pragma unroll
        for (int it = 0; it < 4; it++) {
            int t = tid + 256 * it;
            int row = t >> 3, kq = (t & 7) << 2;
            float4 ah, al;
            split2(pa[it].x, ah.x, al.x); split2(pa[it].y, ah.y, al.y);
            split2(pa[it].z, ah.z, al.z); split2(pa[it].w, ah.w, al.w);
            *(float4*)&sm[GA_H + row * 36 + kq] = ah;
            *(float4*)&sm[GA_L + row * 36 + kq] = al;
            float4 bh, bl;
            split2(pb[it].x, bh.x, bl.x); split2(pb[it].y, bh.y, bl.y);
            split2(pb[it].z, bh.z, bl.z); split2(pb[it].w, bh.w, bl.w);
            *(float4*)&sm[GB_H + row * 36 + kq] = bh;
            *(float4*)&sm[GB_L + row * 36 + kq] = bl;
        }
        __syncthreads();

        if (k0 + 32 < K) {
#pragma unroll
            for (int it = 0; it < 4; it++) {
                int t = tid + 256 * it;
                int row = t >> 3, kq = (t & 7) << 2;
                int m = bm + row;
                pa[it] = (m < M) ? *(const float4*)(A + (size_t)m * K + k0 + 32 + kq)
                                 : make_float4(0.f, 0.f, 0.f, 0.f);
                pb[it] = *(const float4*)(Bm + (size_t)(bn + row) * K + k0 + 32 + kq);
            }
        }

#pragma unroll
        for (int ks = 0; ks < 4; ks++) {
            float ah[4][4], al[4][4], bh[4][2], bl[4][2];
#pragma unroll
            for (int mi = 0; mi < 4; mi++) {
                int r0 = (wm * 64 + mi * 16 + g) * 36 + ks * 8 + tg;
                ah[mi][0] = sm[GA_H + r0];
                ah[mi][1] = sm[GA_H + r0 + 8 * 36];
                ah[mi][2] = sm[GA_H + r0 + 4];
                ah[mi][3] = sm[GA_H + r0 + 8 * 36 + 4];
                al[mi][0] = sm[GA_L + r0];
                al[mi][1] = sm[GA_L + r0 + 8 * 36];
                al[mi][2] = sm[GA_L + r0 + 4];
                al[mi][3] = sm[GA_L + r0 + 8 * 36 + 4];
            }
#pragma unroll
            for (int ni = 0; ni < 4; ni++) {
                int r0 = (wn * 32 + ni * 8 + g) * 36 + ks * 8 + tg;
                bh[ni][0] = sm[GB_H + r0];
                bh[ni][1] = sm[GB_H + r0 + 4];
                bl[ni][0] = sm[GB_L + r0];
                bl[ni][1] = sm[GB_L + r0 + 4];
            }
#pragma unroll
            for (int mi = 0; mi < 4; mi++)
#pragma unroll
                for (int ni = 0; ni < 4; ni++)
                    mma3(acc[mi][ni], ah[mi], al[mi], bh[ni], bl[ni]);
        }
        __syncthreads();
    }

#pragma unroll
    for (int mi = 0; mi < 4; mi++)
#pragma unroll
        for (int ni = 0; ni < 4; ni++) {
            int m0 = bm + wm * 64 + mi * 16 + g;
            int n0 = bn + wn * 32 + ni * 8 + tg * 2;
            float bb0 = bias[n0], bb1 = bias[n0 + 1];
            if (m0 < M) {
                float2 o = {acc[mi][ni][0] + bb0, acc[mi][ni][1] + bb1};
                *(float2*)(C + (size_t)m0 * N + n0) = o;
            }
            if (m0 + 8 < M) {
                float2 o = {acc[mi][ni][2] + bb0, acc[mi][ni][3] + bb1};
                *(float2*)(C + (size_t)(m0 + 8) * N + n0) = o;
            }
        }
}

// ---------------- fused attention: persistent scalar q, chunk-32 k/r -----------
// QWH/QWL/QRH/QRL: 64 x 64k, stride 68 (68 mod 32 = 4, conflict-free), persistent
// KH/KL: 128 x 32k stride 36; RH/RL: 192 x 32k stride 36 (2 chunks per j-iter)
// G[64][196], P[64][132], VH/VL[64][72] alias the k/r region after scores
#define QWH  0
#define QWL  4352
#define QRH  8704
#define QRL  13056
#define AKH  17408
#define AKL  22016
#define ARH  26624
#define ARL  33536
#define AG   17408
#define AP   17408
#define AVH  25856
#define AVL  30464
#define ARMX 40448
#define ARSM 40704
#define ATTN_SMEM (40960 * 4)
#define SC_ 0.125f

__global__ __launch_bounds__(256) void attn_fused(const float* __restrict__ qkv,
                                                  const float* __restrict__ rproj,
                                                  const float* __restrict__ rw,
                                                  const float* __restrict__ rr,
                                                  float* __restrict__ att)
{
    extern __shared__ float sm[];
    const int bh = blockIdx.y;
    const int b = bh / H_, h = bh % H_;
    const int i0 = blockIdx.x * 64;
    const int tid = threadIdx.x;
    const int w = tid >> 5, lane = tid & 31;
    const int g = lane >> 2, tg = lane & 3;
    const int wi = w >> 2, wj = w & 3;

    // ---- persistent q staging (once per CTA): 64 rows x 64 k
#pragma unroll
    for (int it = 0; it < 4; it++) {
        int idx = tid + 256 * it;
        int row = idx >> 4, kq = (idx & 15) << 2;
        float4 qv = *(const float4*)(qkv + (size_t)((i0 + row) * B_ + b) * (3 * E_) + h * D_ + kq);
        float4 rwv = *(const float4*)(rw + h * D_ + kq);
        float4 rrv = *(const float4*)(rr + h * D_ + kq);
        float4 hw, lw, hr, lr;
        split2(qv.x + rwv.x, hw.x, lw.x); split2(qv.y + rwv.y, hw.y, lw.y);
        split2(qv.z + rwv.z, hw.z, lw.z); split2(qv.w + rwv.w, hw.w, lw.w);
        split2(qv.x + rrv.x, hr.x, lr.x); split2(qv.y + rrv.y, hr.y, lr.y);
        split2(qv.z + rrv.z, hr.z, lr.z); split2(qv.w + rrv.w, hr.w, lr.w);
        *(float4*)&sm[QWH + row * 68 + kq] = hw;
        *(float4*)&sm[QWL + row * 68 + kq] = lw;
        *(float4*)&sm[QRH + row * 68 + kq] = hr;
        *(float4*)&sm[QRL + row * 68 + kq] = lr;
    }

    float m_run[2][2] = {{-1e30f, -1e30f}, {-1e30f, -1e30f}};
    float l_run[2][2] = {};
    float accO[2][2][4] = {};

    for (int j0 = 0; j0 < T_; j0 += 128) {
        const int pmin = j0 - i0 + (T_ - 64);
        float accA[2][4][4] = {};
        float accG[2][6][4] = {};

        for (int c = 0; c < 2; c++) {
            const int col0 = h * D_ + c * 32;
            __syncthreads();
            // k: 128 rows x 32 k (4 float4/thread)
#pragma unroll
            for (int it = 0; it < 4; it++) {
                int t = tid + 256 * it;
                int il = t >> 3, kq = (t & 7) << 2;
                float4 kv = *(const float4*)(qkv + (size_t)((j0 + il) * B_ + b) * (3 * E_) + E_ + col0 + kq);
                float4 hk, lk;
                split2(kv.x, hk.x, lk.x); split2(kv.y, hk.y, lk.y);
                split2(kv.z, hk.z, lk.z); split2(kv.w, hk.w, lk.w);
                *(float4*)&sm[AKH + il * 36 + kq] = hk;
                *(float4*)&sm[AKL + il * 36 + kq] = lk;
            }
            // r window: 191 real + zero (192 rows x 32 k, 6 float4/thread)
#pragma unroll
            for (int it = 0; it < 6; it++) {
                int t = tid + 256 * it;
                int pl = t >> 3, kq = (t & 7) << 2;
                float4 rv = (pl < 191)
                    ? *(const float4*)(rproj + (size_t)((pmin + pl) * B_ + b) * E_ + col0 + kq)
                    : make_float4(0.f, 0.f, 0.f, 0.f);
                float4 hh, ll;
                split2(rv.x, hh.x, ll.x); split2(rv.y, hh.y, ll.y);
                split2(rv.z, hh.z, ll.z); split2(rv.w, hh.w, ll.w);
                *(float4*)&sm[ARH + pl * 36 + kq] = hh;
                *(float4*)&sm[ARL + pl * 36 + kq] = ll;
            }
            __syncthreads();
#pragma unroll
            for (int ks = 0; ks < 4; ks++) {
                float aWh[2][4], aWl[2][4], aRh[2][4], aRl[2][4];
#pragma unroll
                for (int mi = 0; mi < 2; mi++) {
                    int rq = (wi * 32 + mi * 16 + g) * 68 + c * 32 + ks * 8 + tg;
                    aWh[mi][0] = sm[QWH + rq];
                    aWh[mi][1] = sm[QWH + rq + 8 * 68];
                    aWh[mi][2] = sm[QWH + rq + 4];
                    aWh[mi][3] = sm[QWH + rq + 8 * 68 + 4];
                    aWl[mi][0] = sm[QWL + rq];
                    aWl[mi][1] = sm[QWL + rq + 8 * 68];
                    aWl[mi][2] = sm[QWL + rq + 4];
                    aWl[mi][3] = sm[QWL + rq + 8 * 68 + 4];
                    aRh[mi][0] = sm[QRH + rq];
                    aRh[mi][1] = sm[QRH + rq + 8 * 68];
                    aRh[mi][2] = sm[QRH + rq + 4];
                    aRh[mi][3] = sm[QRH + rq + 8 * 68 + 4];
                    aRl[mi][0] = sm[QRL + rq];
                    aRl[mi][1] = sm[QRL + rq + 8 * 68];
                    aRl[mi][2] = sm[QRL + rq + 4];
                    aRl[mi][3] = sm[QRL + rq + 8 * 68 + 4];
                }
#pragma unroll
                for (int nj = 0; nj < 4; nj++) {
                    float bhf[2], blf[2];
                    int r0 = (wj * 32 + nj * 8 + g) * 36 + ks * 8 + tg;
                    bhf[0] = sm[AKH + r0]; bhf[1] = sm[AKH + r0 + 4];
                    blf[0] = sm[AKL + r0]; blf[1] = sm[AKL + r0 + 4];
                    mma3(accA[0][nj], aWh[0], aWl[0], bhf, blf);
                    mma3(accA[1][nj], aWh[1], aWl[1], bhf, blf);
                }
#pragma unroll
                for (int ng = 0; ng < 6; ng++) {
                    float bhf[2], blf[2];
                    int r0 = (wj * 48 + ng * 8 + g) * 36 + ks * 8 + tg;
                    bhf[0] = sm[ARH + r0]; bhf[1] = sm[ARH + r0 + 4];
                    blf[0] = sm[ARL + r0]; blf[1] = sm[ARL + r0 + 4];
                    mma3(accG[0][ng], aRh[0], aRl[0], bhf, blf);
                    mma3(accG[1][ng], aRh[1], aRl[1], bhf, blf);
                }
            }
        }
        __syncthreads();

        // stage G[64][196] (aliases k/r region)
#pragma unroll
        for (int mi = 0; mi < 2; mi++)
#pragma unroll
            for (int ng = 0; ng < 6; ng++) {
                int row = wi * 32 + mi * 16 + g;
                int cc = wj * 48 + ng * 8 + tg * 2;
                sm[AG + row * 196 + cc]           = accG[mi][ng][0];
                sm[AG + row * 196 + cc + 1]       = accG[mi][ng][1];
                sm[AG + (row + 8) * 196 + cc]     = accG[mi][ng][2];
                sm[AG + (row + 8) * 196 + cc + 1] = accG[mi][ng][3];
            }
        __syncthreads();

        float tmax[2][2] = {{-1e30f, -1e30f}, {-1e30f, -1e30f}};
#pragma unroll
        for (int mi = 0; mi < 2; mi++)
#pragma unroll
            for (int nj = 0; nj < 4; nj++) {
                int il = wi * 32 + mi * 16 + g;
                int jl = wj * 32 + nj * 8 + tg * 2;
                int il2 = il + 8;
                accA[mi][nj][0] += sm[AG + il * 196 + (jl - il + 63)];
                accA[mi][nj][1] += sm[AG + il * 196 + (jl + 1 - il + 63)];
                accA[mi][nj][2] += sm[AG + il2 * 196 + (jl - il2 + 63)];
                accA[mi][nj][3] += sm[AG + il2 * 196 + (jl + 1 - il2 + 63)];
                tmax[mi][0] = fmaxf(tmax[mi][0], fmaxf(accA[mi][nj][0], accA[mi][nj][1]));
                tmax[mi][1] = fmaxf(tmax[mi][1], fmaxf(accA[mi][nj][2], accA[mi][nj][3]));
            }
#pragma unroll
        for (int mi = 0; mi < 2; mi++)
#pragma unroll
            for (int rp = 0; rp < 2; rp++) {
                float v = tmax[mi][rp];
                v = fmaxf(v, __shfl_xor_sync(0xffffffffu, v, 1));
                v = fmaxf(v, __shfl_xor_sync(0xffffffffu, v, 2));
                tmax[mi][rp] = v;
            }
        if (tg == 0) {
#pragma unroll
            for (int mi = 0; mi < 2; mi++)
#pragma unroll
                for (int rp = 0; rp < 2; rp++) {
                    int row = wi * 32 + mi * 16 + g + rp * 8;
                    sm[ARMX + row * 4 + wj] = tmax[mi][rp];
                }
        }
        __syncthreads();

        float mnew[2][2], fsc[2][2];
#pragma unroll
        for (int mi = 0; mi < 2; mi++)
#pragma unroll
            for (int rp = 0; rp < 2; rp++) {
                int row = wi * 32 + mi * 16 + g + rp * 8;
                float mt = fmaxf(fmaxf(sm[ARMX + row * 4 + 0], sm[ARMX + row * 4 + 1]),
                                 fmaxf(sm[ARMX + row * 4 + 2], sm[ARMX + row * 4 + 3]));
                mnew[mi][rp] = fmaxf(m_run[mi][rp], mt);
                fsc[mi][rp] = __expf((m_run[mi][rp] - mnew[mi][rp]) * SC_);
            }

        float tsum[2][2] = {};
#pragma unroll
        for (int mi = 0; mi < 2; mi++)
#pragma unroll
            for (int nj = 0; nj < 4; nj++) {
                int il = wi * 32 + mi * 16 + g;
                int jl = wj * 32 + nj * 8 + tg * 2;
                float p0 = __expf((accA[mi][nj][0] - mnew[mi][0]) * SC_);
                float p1 = __expf((accA[mi][nj][1] - mnew[mi][0]) * SC_);
                float p2 = __expf((accA[mi][nj][2] - mnew[mi][1]) * SC_);
                float p3 = __expf((accA[mi][nj][3] - mnew[mi][1]) * SC_);
                tsum[mi][0] += p0 + p1;
                tsum[mi][1] += p2 + p3;
                sm[AP + il * 132 + jl]           = __uint_as_float(f2tf(p0));
                sm[AP + il * 132 + jl + 1]       = __uint_as_float(f2tf(p1));
                sm[AP + (il + 8) * 132 + jl]     = __uint_as_float(f2tf(p2));
                sm[AP + (il + 8) * 132 + jl + 1] = __uint_as_float(f2tf(p3));
            }
#pragma unroll
        for (int mi = 0; mi < 2; mi++)
#pragma unroll
            for (int rp = 0; rp < 2; rp++) {
                float v = tsum[mi][rp];
                v += __shfl_xor_sync(0xffffffffu, v, 1);
                v += __shfl_xor_sync(0xffffffffu, v, 2);
                tsum[mi][rp] = v;
            }
        if (tg == 0) {
#pragma unroll
            for (int mi = 0; mi < 2; mi++)
#pragma unroll
                for (int rp = 0; rp < 2; rp++) {
                    int row = wi * 32 + mi * 16 + g + rp * 8;
                    sm[ARSM + row * 4 + wj] = tsum[mi][rp];
                }
        }
        __syncthreads();

#pragma unroll
        for (int mi = 0; mi < 2; mi++)
#pragma unroll
            for (int rp = 0; rp < 2; rp++) {
                int row = wi * 32 + mi * 16 + g + rp * 8;
                float lt = sm[ARSM + row * 4 + 0] + sm[ARSM + row * 4 + 1]
                         + sm[ARSM + row * 4 + 2] + sm[ARSM + row * 4 + 3];
                l_run[mi][rp] = l_run[mi][rp] * fsc[mi][rp] + lt;
                m_run[mi][rp] = mnew[mi][rp];
            }
#pragma unroll
        for (int mi = 0; mi < 2; mi++)
#pragma unroll
            for (int nd = 0; nd < 2; nd++) {
                accO[mi][nd][0] *= fsc[mi][0];
                accO[mi][nd][1] *= fsc[mi][0];
                accO[mi][nd][2] *= fsc[mi][1];
                accO[mi][nd][3] *= fsc[mi][1];
            }

        // PV (R10-identical structure, V at new offsets)
        for (int jc = 0; jc < 2; jc++) {
            __syncthreads();
#pragma unroll
            for (int it = 0; it < 4; it++) {
                int t = tid + 256 * it;
                int row = t >> 4, dq = (t & 15) << 2;
                float4 vv = *(const float4*)(qkv + (size_t)((j0 + jc * 64 + row) * B_ + b) * (3 * E_)
                                             + 2 * E_ + h * D_ + dq);
                float4 hh, ll;
                split2(vv.x, hh.x, ll.x); split2(vv.y, hh.y, ll.y);
                split2(vv.z, hh.z, ll.z); split2(vv.w, hh.w, ll.w);
                *(float4*)&sm[AVH + row * 72 + dq] = hh;
                *(float4*)&sm[AVL + row * 72 + dq] = ll;
            }
            __syncthreads();
#pragma unroll
            for (int ks = 0; ks < 8; ks++) {
                float a[2][4];
#pragma unroll
                for (int mi = 0; mi < 2; mi++) {
                    int r0 = (wi * 32 + mi * 16 + g) * 132 + jc * 64 + ks * 8 + tg;
                    a[mi][0] = sm[AP + r0];
                    a[mi][1] = sm[AP + r0 + 8 * 132];
                    a[mi][2] = sm[AP + r0 + 4];
                    a[mi][3] = sm[AP + r0 + 8 * 132 + 4];
                }
#pragma unroll
                for (int nd = 0; nd < 2; nd++) {
                    int col = wj * 16 + nd * 8 + g;
                    float bhf[2], blf[2];
                    bhf[0] = sm[AVH + (ks * 8 + tg) * 72 + col];
                    bhf[1] = sm[AVH + (ks * 8 + tg + 4) * 72 + col];
                    blf[0] = sm[AVL + (ks * 8 + tg) * 72 + col];
                    blf[1] = sm[AVL + (ks * 8 + tg + 4) * 72 + col];
#pragma unroll
                    for (int mi = 0; mi < 2; mi++) {
                        mma8(accO[mi][nd], a[mi], bhf);
                        mma8(accO[mi][nd], a[mi], blf);
                    }
                }
            }
        }
    }

    float inv[2][2];
#pragma unroll
    for (int mi = 0; mi < 2; mi++)
#pragma unroll
        for (int rp = 0; rp < 2; rp++)
            inv[mi][rp] = 1.0f / l_run[mi][rp];
#pragma unroll
    for (int mi = 0; mi < 2; mi++)
#pragma unroll
        for (int nd = 0; nd < 2; nd++) {
            int row = wi * 32 + mi * 16 + g;
            int col = h * D_ + wj * 16 + nd * 8 + tg * 2;
            float2 o0 = {accO[mi][nd][0] * inv[mi][0], accO[mi][nd][1] * inv[mi][0]};
            float2 o1 = {accO[mi][nd][2] * inv[mi][1], accO[mi][nd][3] * inv[mi][1]};
            *(float2*)(att + (size_t)((i0 + row) * B_ + b) * E_ + col) = o0;
            *(float2*)(att + (size_t)((i0 + row + 8) * B_ + b) * E_ + col) = o1;
        }
}

// ---------------- launch ----------------
extern "C" void kernel_launch(void* const* d_in, const int* in_sizes, int n_in,
                              void* d_out, int out_size)
{
    (void)in_sizes; (void)n_in; (void)out_size;
    const float* input  = (const float*)d_in[0];
    const float* pos    = (const float*)d_in[1];
    const float* factor = (const float*)d_in[2];
    const float* w_in   = (const float*)d_in[3];
    const float* w_pos  = (const float*)d_in[4];
    const float* w_out  = (const float*)d_in[5];
    const float* bw_in  = (const float*)d_in[6];
    const float* bw_pos = (const float*)d_in[7];
    const float* bw_out = (const float*)d_in[8];
    const float* rwb    = (const float*)d_in[9];
    const float* rrb    = (const float*)d_in[10];

    float *pWin, *pWpos, *pWout, *pbin, *pbpos, *pbout, *prw, *prr,
          *pqkv, *pr, *patt;
    cudaGetSymbolAddress((void**)&pWin,  g_Win);
    cudaGetSymbolAddress((void**)&pWpos, g_Wpos);
    cudaGetSymbolAddress((void**)&pWout, g_Wout);
    cudaGetSymbolAddress((void**)&pbin,  g_bin);
    cudaGetSymbolAddress((void**)&pbpos, g_bpos);
    cudaGetSymbolAddress((void**)&pbout, g_bout);
    cudaGetSymbolAddress((void**)&prw,   g_rw);
    cudaGetSymbolAddress((void**)&prr,   g_rr);
    cudaGetSymbolAddress((void**)&pqkv,  g_qkv);
    cudaGetSymbolAddress((void**)&pr,    g_r);
    cudaGetSymbolAddress((void**)&patt,  g_att);

    cudaFuncSetAttribute(gemm3,      cudaFuncAttributeMaxDynamicSharedMemorySize, GEMM_SMEM);
    cudaFuncSetAttribute(attn_fused, cudaFuncAttributeMaxDynamicSharedMemorySize, ATTN_SMEM);

    // 1) hypernet
    hyper_all<<<(HN7 + 255) / 256, 256>>>(w_in, w_pos, w_out, bw_in, bw_pos, bw_out,
                                          rwb, rrb, factor,
                                          pWin, pWpos, pWout, pbin, pbpos, pbout, prw, prr);

    // 2) projections (3xtf32, register double-buffered)
    gemm3<<<dim3(3 * E_ / 128, TB_ / 128), 256, GEMM_SMEM>>>(input, pWin, pbin, pqkv, TB_, 3 * E_, E_);
    gemm3<<<dim3(E_ / 128, (RB_ + 127) / 128), 256, GEMM_SMEM>>>(pos, pWpos, pbpos, pr, RB_, E_, E_);

    // 3) fused attention (persistent scalar q, chunk-32 k/r)
    attn_fused<<<dim3(T_ / 64, B_ * H_), 256, ATTN_SMEM>>>(pqkv, pr, prw, prr, patt);

    // 4) output projection -> d_out
    gemm3<<<dim3(E_ / 128, TB_ / 128), 256, GEMM_SMEM>>>(patt, pWout, pbout, (float*)d_out, TB_, E_, E_);
}

// round 13
// speedup vs baseline: 1.1307x; 1.0266x over previous
#include <cuda_runtime.h>
#include <math.h>

#define T_  1024
#define B_  2
#define E_  1024
#define H_  16
#define D_  64
#define TB_ 2048
#define RB_ 4094

// ---------------- scratch ----------------
__device__ float g_Win [3 * E_ * E_];
__device__ float g_Wpos[E_ * E_];
__device__ float g_Wout[E_ * E_];
__device__ float g_bin [3 * E_];
__device__ float g_bpos[E_];
__device__ float g_bout[E_];
__device__ float g_rw  [E_];
__device__ float g_rr  [E_];
__device__ float g_qkv [TB_ * 3 * E_];
__device__ float g_r   [RB_ * E_];
__device__ float g_att [TB_ * E_];

// ---------------- tf32 helpers ----------------
__device__ __forceinline__ unsigned f2tf(float f) {
    unsigned r; asm("cvt.rna.tf32.f32 %0, %1;" : "=r"(r) : "f"(f)); return r;
}
__device__ __forceinline__ void split2(float v, float& hi, float& lo) {
    hi = __uint_as_float(f2tf(v));
    lo = __uint_as_float(f2tf(v - hi));
}
__device__ __forceinline__ void mma8(float* c, const float* a, const float* b) {
    asm volatile("mma.sync.aligned.m16n8k8.row.col.f32.tf32.tf32.f32 "
                 "{%0,%1,%2,%3},{%4,%5,%6,%7},{%8,%9},{%0,%1,%2,%3};"
                 : "+f"(c[0]), "+f"(c[1]), "+f"(c[2]), "+f"(c[3])
                 : "r"(__float_as_uint(a[0])), "r"(__float_as_uint(a[1])),
                   "r"(__float_as_uint(a[2])), "r"(__float_as_uint(a[3])),
                   "r"(__float_as_uint(b[0])), "r"(__float_as_uint(b[1])));
}
__device__ __forceinline__ void mma3(float* c, const float* ah, const float* al,
                                     const float* bh, const float* bl) {
    mma8(c, ah, bh);
    mma8(c, ah, bl);
    mma8(c, al, bh);
}

// ---------------- fused hypernet ----------------
#define HN0 3145728
#define HN1 (HN0 + 1048576)
#define HN2 (HN1 + 1048576)
#define HN3 (HN2 + 3072)
#define HN4 (HN3 + 1024)
#define HN5 (HN4 + 1024)
#define HN6 (HN5 + 1024)
#define HN7 (HN6 + 1024)

__global__ __launch_bounds__(256) void hyper_all(
    const float* __restrict__ w_in,  const float* __restrict__ w_pos,
    const float* __restrict__ w_out, const float* __restrict__ b_in,
    const float* __restrict__ b_pos, const float* __restrict__ b_out,
    const float* __restrict__ rwb,   const float* __restrict__ rrb,
    const float* __restrict__ f,
    float* __restrict__ oWin,  float* __restrict__ oWpos,
    float* __restrict__ oWout, float* __restrict__ obin,
    float* __restrict__ obpos, float* __restrict__ obout,
    float* __restrict__ orw,   float* __restrict__ orr)
{
    int idx = blockIdx.x * blockDim.x + threadIdx.x;
    if (idx >= HN7) return;
    const float* src; float* dst; int off;
    if      (idx < HN0) { src = w_in;  dst = oWin;  off = idx; }
    else if (idx < HN1) { src = w_pos; dst = oWpos; off = idx - HN0; }
    else if (idx < HN2) { src = w_out; dst = oWout; off = idx - HN1; }
    else if (idx < HN3) { src = b_in;  dst = obin;  off = idx - HN2; }
    else if (idx < HN4) { src = b_pos; dst = obpos; off = idx - HN3; }
    else if (idx < HN5) { src = b_out; dst = obout; off = idx - HN4; }
    else if (idx < HN6) { src = rwb;   dst = orw;   off = idx - HN5; }
    else                { src = rrb;   dst = orr;   off = idx - HN6; }
    const float4* wp = (const float4*)(src + (size_t)off * 8);
    float4 a = wp[0], b = wp[1];
    float4 f0 = *(const float4*)f;
    float4 f1 = *(const float4*)(f + 4);
    dst[off] = a.x*f0.x + a.y*f0.y + a.z*f0.z + a.w*f0.w
             + b.x*f1.x + b.y*f1.y + b.z*f1.z + b.w*f1.w;
}

// ---------------- 3xtf32 NT GEMM with register double-buffer (unchanged) -------
#define GA_H 0
#define GA_L 4608
#define GB_H 9216
#define GB_L 13824
#define GEMM_SMEM (18432 * 4)

__global__ __launch_bounds__(256) void gemm3(const float* __restrict__ A,
                                             const float* __restrict__ Bm,
                                             const float* __restrict__ bias,
                                             float* __restrict__ C,
                                             int M, int N, int K)
{
    extern __shared__ float sm[];
    int bm = blockIdx.y * 128, bn = blockIdx.x * 128;
    int tid = threadIdx.x;
    int w = tid >> 5, lane = tid & 31;
    int g = lane >> 2, tg = lane & 3;
    int wm = w & 1, wn = w >> 1;
    float acc[4][4][4] = {};

    float4 pa[4], pb[4];
#pragma unroll
    for (int it = 0; it < 4; it++) {
        int t = tid + 256 * it;
        int row = t >> 3, kq = (t & 7) << 2;
        int m = bm + row;
        pa[it] = (m < M) ? *(const float4*)(A + (size_t)m * K + kq)
                         : make_float4(0.f, 0.f, 0.f, 0.f);
        pb[it] = *(const float4*)(Bm + (size_t)(bn + row) * K + kq);
    }

    for (int k0 = 0; k0 < K; k0 += 32) {
#pragma unroll
        for (int it = 0; it < 4; it++) {
            int t = tid + 256 * it;
            int row = t >> 3, kq = (t & 7) << 2;
            float4 ah, al;
            split2(pa[it].x, ah.x, al.x); split2(pa[it].y, ah.y, al.y);
            split2(pa[it].z, ah.z, al.z); split2(pa[it].w, ah.w, al.w);
            *(float4*)&sm[GA_H + row * 36 + kq] = ah;
            *(float4*)&sm[GA_L + row * 36 + kq] = al;
            float4 bh, bl;
            split2(pb[it].x, bh.x, bl.x); split2(pb[it].y, bh.y, bl.y);
            split2(pb[it].z, bh.z, bl.z); split2(pb[it].w, bh.w, bl.w);
            *(float4*)&sm[GB_H + row * 36 + kq] = bh;
            *(float4*)&sm[GB_L + row * 36 + kq] = bl;
        }
        __syncthreads();

        if (k0 + 32 < K) {
#pragma unroll
            for (int it = 0; it < 4; it++) {
                int t = tid + 256 * it;
                int row = t >> 3, kq = (t & 7) << 2;
                int m = bm + row;
                pa[it] = (m < M) ? *(const float4*)(A + (size_t)m * K + k0 + 32 + kq)
                                 : make_float4(0.f, 0.f, 0.f, 0.f);
                pb[it] = *(const float4*)(Bm + (size_t)(bn + row) * K + k0 + 32 + kq);
            }
        }

#pragma unroll
        for (int ks = 0; ks < 4; ks++) {
            float ah[4][4], al[4][4], bh[4][2], bl[4][2];
#pragma unroll
            for (int mi = 0; mi < 4; mi++) {
                int r0 = (wm * 64 + mi * 16 + g) * 36 + ks * 8 + tg;
                ah[mi][0] = sm[GA_H + r0];
                ah[mi][1] = sm[GA_H + r0 + 8 * 36];
                ah[mi][2] = sm[GA_H + r0 + 4];
                ah[mi][3] = sm[GA_H + r0 + 8 * 36 + 4];
                al[mi][0] = sm[GA_L + r0];
                al[mi][1] = sm[GA_L + r0 + 8 * 36];
                al[mi][2] = sm[GA_L + r0 + 4];
                al[mi][3] = sm[GA_L + r0 + 8 * 36 + 4];
            }
#pragma unroll
            for (int ni = 0; ni < 4; ni++) {
                int r0 = (wn * 32 + ni * 8 + g) * 36 + ks * 8 + tg;
                bh[ni][0] = sm[GB_H + r0];
                bh[ni][1] = sm[GB_H + r0 + 4];
                bl[ni][0] = sm[GB_L + r0];
                bl[ni][1] = sm[GB_L + r0 + 4];
            }
#pragma unroll
            for (int mi = 0; mi < 4; mi++)
#pragma unroll
                for (int ni = 0; ni < 4; ni++)
                    mma3(acc[mi][ni], ah[mi], al[mi], bh[ni], bl[ni]);
        }
        __syncthreads();
    }

#pragma unroll
    for (int mi = 0; mi < 4; mi++)
#pragma unroll
        for (int ni = 0; ni < 4; ni++) {
            int m0 = bm + wm * 64 + mi * 16 + g;
            int n0 = bn + wn * 32 + ni * 8 + tg * 2;
            float bb0 = bias[n0], bb1 = bias[n0 + 1];
            if (m0 < M) {
                float2 o = {acc[mi][ni][0] + bb0, acc[mi][ni][1] + bb1};
                *(float2*)(C + (size_t)m0 * N + n0) = o;
            }
            if (m0 + 8 < M) {
                float2 o = {acc[mi][ni][2] + bb0, acc[mi][ni][3] + bb1};
                *(float2*)(C + (size_t)(m0 + 8) * N + n0) = o;
            }
        }
}

// ---------------- fused attention: R12 + k/r register prefetch -----------------
#define QWH  0
#define QWL  4352
#define QRH  8704
#define QRL  13056
#define AKH  17408
#define AKL  22016
#define ARH  26624
#define ARL  33536
#define AG   17408
#define AP   17408
#define AVH  25856
#define AVL  30464
#define ARMX 40448
#define ARSM 40704
#define ATTN_SMEM (40960 * 4)
#define SC_ 0.125f

__global__ __launch_bounds__(256) void attn_fused(const float* __restrict__ qkv,
                                                  const float* __restrict__ rproj,
                                                  const float* __restrict__ rr,
                                                  const float* __restrict__ rw,
                                                  float* __restrict__ att);

__global__ __launch_bounds__(256) void attn_fused_impl(const float* __restrict__ qkv,
                                                       const float* __restrict__ rproj,
                                                       const float* __restrict__ rw,
                                                       const float* __restrict__ rr,
                                                       float* __restrict__ att)
{
    extern __shared__ float sm[];
    const int bh = blockIdx.y;
    const int b = bh / H_, h = bh % H_;
    const int i0 = blockIdx.x * 64;
    const int tid = threadIdx.x;
    const int w = tid >> 5, lane = tid & 31;
    const int g = lane >> 2, tg = lane & 3;
    const int wi = w >> 2, wj = w & 3;

    // ---- persistent q staging (once per CTA): 64 rows x 64 k
#pragma unroll
    for (int it = 0; it < 4; it++) {
        int idx = tid + 256 * it;
        int row = idx >> 4, kq = (idx & 15) << 2;
        float4 qv = *(const float4*)(qkv + (size_t)((i0 + row) * B_ + b) * (3 * E_) + h * D_ + kq);
        float4 rwv = *(const float4*)(rw + h * D_ + kq);
        float4 rrv = *(const float4*)(rr + h * D_ + kq);
        float4 hw, lw, hr, lr;
        split2(qv.x + rwv.x, hw.x, lw.x); split2(qv.y + rwv.y, hw.y, lw.y);
        split2(qv.z + rwv.z, hw.z, lw.z); split2(qv.w + rwv.w, hw.w, lw.w);
        split2(qv.x + rrv.x, hr.x, lr.x); split2(qv.y + rrv.y, hr.y, lr.y);
        split2(qv.z + rrv.z, hr.z, lr.z); split2(qv.w + rrv.w, hr.w, lr.w);
        *(float4*)&sm[QWH + row * 68 + kq] = hw;
        *(float4*)&sm[QWL + row * 68 + kq] = lw;
        *(float4*)&sm[QRH + row * 68 + kq] = hr;
        *(float4*)&sm[QRL + row * 68 + kq] = lr;
    }

    float m_run[2][2] = {{-1e30f, -1e30f}, {-1e30f, -1e30f}};
    float l_run[2][2] = {};
    float accO[2][2][4] = {};

    // prefetch chunk 0 of j0=0
    float4 pk[4], pr6[6];
    {
        const int col0 = h * D_;
        const int pmin0 = T_ - 64 - i0;
#pragma unroll
        for (int it = 0; it < 4; it++) {
            int t = tid + 256 * it;
            int il = t >> 3, kq = (t & 7) << 2;
            pk[it] = *(const float4*)(qkv + (size_t)(il * B_ + b) * (3 * E_) + E_ + col0 + kq);
        }
#pragma unroll
        for (int it = 0; it < 6; it++) {
            int t = tid + 256 * it;
            int pl = t >> 3, kq = (t & 7) << 2;
            pr6[it] = (pl < 191)
                ? *(const float4*)(rproj + (size_t)((pmin0 + pl) * B_ + b) * E_ + col0 + kq)
                : make_float4(0.f, 0.f, 0.f, 0.f);
        }
    }

    for (int j0 = 0; j0 < T_; j0 += 128) {
        const int pmin = j0 - i0 + (T_ - 64);
        float accA[2][4][4] = {};
        float accG[2][6][4] = {};

        for (int c = 0; c < 2; c++) {
            __syncthreads();
            // store prefetched k/r (split) to smem
#pragma unroll
            for (int it = 0; it < 4; it++) {
                int t = tid + 256 * it;
                int il = t >> 3, kq = (t & 7) << 2;
                float4 hk, lk;
                split2(pk[it].x, hk.x, lk.x); split2(pk[it].y, hk.y, lk.y);
                split2(pk[it].z, hk.z, lk.z); split2(pk[it].w, hk.w, lk.w);
                *(float4*)&sm[AKH + il * 36 + kq] = hk;
                *(float4*)&sm[AKL + il * 36 + kq] = lk;
            }
#pragma unroll
            for (int it = 0; it < 6; it++) {
                int t = tid + 256 * it;
                int pl = t >> 3, kq = (t & 7) << 2;
                float4 hh, ll;
                split2(pr6[it].x, hh.x, ll.x); split2(pr6[it].y, hh.y, ll.y);
                split2(pr6[it].z, hh.z, ll.z); split2(pr6[it].w, hh.w, ll.w);
                *(float4*)&sm[ARH + pl * 36 + kq] = hh;
                *(float4*)&sm[ARL + pl * 36 + kq] = ll;
            }
            __syncthreads();

            // prefetch chunk c+1 (same j) during compute
            if (c == 0) {
                const int col0n = h * D_ + 32;
#pragma unroll
                for (int it = 0; it < 4; it++) {
                    int t = tid + 256 * it;
                    int il = t >> 3, kq = (t & 7) << 2;
                    pk[it] = *(const float4*)(qkv + (size_t)((j0 + il) * B_ + b) * (3 * E_) + E_ + col0n + kq);
                }
#pragma unroll
                for (int it = 0; it < 6; it++) {
                    int t = tid + 256 * it;
                    int pl = t >> 3, kq = (t & 7) << 2;
                    pr6[it] = (pl < 191)
                        ? *(const float4*)(rproj + (size_t)((pmin + pl) * B_ + b) * E_ + col0n + kq)
                        : make_float4(0.f, 0.f, 0.f, 0.f);
                }
            }

#pragma unroll
            for (int ks = 0; ks < 4; ks++) {
                float aWh[2][4], aWl[2][4], aRh[2][4], aRl[2][4];
#pragma unroll
                for (int mi = 0; mi < 2; mi++) {
                    int rq = (wi * 32 + mi * 16 + g) * 68 + c * 32 + ks * 8 + tg;
                    aWh[mi][0] = sm[QWH + rq];
                    aWh[mi][1] = sm[QWH + rq + 8 * 68];
                    aWh[mi][2] = sm[QWH + rq + 4];
                    aWh[mi][3] = sm[QWH + rq + 8 * 68 + 4];
                    aWl[mi][0] = sm[QWL + rq];
                    aWl[mi][1] = sm[QWL + rq + 8 * 68];
                    aWl[mi][2] = sm[QWL + rq + 4];
                    aWl[mi][3] = sm[QWL + rq + 8 * 68 + 4];
                    aRh[mi][0] = sm[QRH + rq];
                    aRh[mi][1] = sm[QRH + rq + 8 * 68];
                    aRh[mi][2] = sm[QRH + rq + 4];
                    aRh[mi][3] = sm[QRH + rq + 8 * 68 + 4];
                    aRl[mi][0] = sm[QRL + rq];
                    aRl[mi][1] = sm[QRL + rq + 8 * 68];
                    aRl[mi][2] = sm[QRL + rq + 4];
                    aRl[mi][3] = sm[QRL + rq + 8 * 68 + 4];
                }
#pragma unroll
                for (int nj = 0; nj < 4; nj++) {
                    float bhf[2], blf[2];
                    int r0 = (wj * 32 + nj * 8 + g) * 36 + ks * 8 + tg;
                    bhf[0] = sm[AKH + r0]; bhf[1] = sm[AKH + r0 + 4];
                    blf[0] = sm[AKL + r0]; blf[1] = sm[AKL + r0 + 4];
                    mma3(accA[0][nj], aWh[0], aWl[0], bhf, blf);
                    mma3(accA[1][nj], aWh[1], aWl[1], bhf, blf);
                }
#pragma unroll
                for (int ng = 0; ng < 6; ng++) {
                    float bhf[2], blf[2];
                    int r0 = (wj * 48 + ng * 8 + g) * 36 + ks * 8 + tg;
                    bhf[0] = sm[ARH + r0]; bhf[1] = sm[ARH + r0 + 4];
                    blf[0] = sm[ARL + r0]; blf[1] = sm[ARL + r0 + 4];
                    mma3(accG[0][ng], aRh[0], aRl[0], bhf, blf);
                    mma3(accG[1][ng], aRh[1], aRl[1], bhf, blf);
                }
            }
        }

        // prefetch chunk 0 of next j (overlaps G-stage/softmax/PV below)
        if (j0 + 128 < T_) {
            const int j0n = j0 + 128;
            const int pminN = j0n - i0 + (T_ - 64);
            const int col0 = h * D_;
#pragma unroll
            for (int it = 0; it < 4; it++) {
                int t = tid + 256 * it;
                int il = t >> 3, kq = (t & 7) << 2;
                pk[it] = *(const float4*)(qkv + (size_t)((j0n + il) * B_ + b) * (3 * E_) + E_ + col0 + kq);
            }
#pragma unroll
            for (int it = 0; it < 6; it++) {
                int t = tid + 256 * it;
                int pl = t >> 3, kq = (t & 7) << 2;
                pr6[it] = (pl < 191)
                    ? *(const float4*)(rproj + (size_t)((pminN + pl) * B_ + b) * E_ + col0 + kq)
                    : make_float4(0.f, 0.f, 0.f, 0.f);
            }
        }
        __syncthreads();

        // stage G[64][196] (aliases k/r region)
#pragma unroll
        for (int mi = 0; mi < 2; mi++)
#pragma unroll
            for (int ng = 0; ng < 6; ng++) {
                int row = wi * 32 + mi * 16 + g;
                int cc = wj * 48 + ng * 8 + tg * 2;
                sm[AG + row * 196 + cc]           = accG[mi][ng][0];
                sm[AG + row * 196 + cc + 1]       = accG[mi][ng][1];
                sm[AG + (row + 8) * 196 + cc]     = accG[mi][ng][2];
                sm[AG + (row + 8) * 196 + cc + 1] = accG[mi][ng][3];
            }
        __syncthreads();

        float tmax[2][2] = {{-1e30f, -1e30f}, {-1e30f, -1e30f}};
#pragma unroll
        for (int mi = 0; mi < 2; mi++)
#pragma unroll
            for (int nj = 0; nj < 4; nj++) {
                int il = wi * 32 + mi * 16 + g;
                int jl = wj * 32 + nj * 8 + tg * 2;
                int il2 = il + 8;
                accA[mi][nj][0] += sm[AG + il * 196 + (jl - il + 63)];
                accA[mi][nj][1] += sm[AG + il * 196 + (jl + 1 - il + 63)];
                accA[mi][nj][2] += sm[AG + il2 * 196 + (jl - il2 + 63)];
                accA[mi][nj][3] += sm[AG + il2 * 196 + (jl + 1 - il2 + 63)];
                tmax[mi][0] = fmaxf(tmax[mi][0], fmaxf(accA[mi][nj][0], accA[mi][nj][1]));
                tmax[mi][1] = fmaxf(tmax[mi][1], fmaxf(accA[mi][nj][2], accA[mi][nj][3]));
            }
#pragma unroll
        for (int mi = 0; mi < 2; mi++)
#pragma unroll
            for (int rp = 0; rp < 2; rp++) {
                float v = tmax[mi][rp];
                v = fmaxf(v, __shfl_xor_sync(0xffffffffu, v, 1));
                v = fmaxf(v, __shfl_xor_sync(0xffffffffu, v, 2));
                tmax[mi][rp] = v;
            }
        if (tg == 0) {
#pragma unroll
            for (int mi = 0; mi < 2; mi++)
#pragma unroll
                for (int rp = 0; rp < 2; rp++) {
                    int row = wi * 32 + mi * 16 + g + rp * 8;
                    sm[ARMX + row * 4 + wj] = tmax[mi][rp];
                }
        }
        __syncthreads();

        float mnew[2][2], fsc[2][2];
#pragma unroll
        for (int mi = 0; mi < 2; mi++)
#pragma unroll
            for (int rp = 0; rp < 2; rp++) {
                int row = wi * 32 + mi * 16 + g + rp * 8;
                float mt = fmaxf(fmaxf(sm[ARMX + row * 4 + 0], sm[ARMX + row * 4 + 1]),
                                 fmaxf(sm[ARMX + row * 4 + 2], sm[ARMX + row * 4 + 3]));
                mnew[mi][rp] = fmaxf(m_run[mi][rp], mt);
                fsc[mi][rp] = __expf((m_run[mi][rp] - mnew[mi][rp]) * SC_);
            }

        float tsum[2][2] = {};
#pragma unroll
        for (int mi = 0; mi < 2; mi++)
#pragma unroll
            for (int nj = 0; nj < 4; nj++) {
                int il = wi * 32 + mi * 16 + g;
                int jl = wj * 32 + nj * 8 + tg * 2;
                float p0 = __expf((accA[mi][nj][0] - mnew[mi][0]) * SC_);
                float p1 = __expf((accA[mi][nj][1] - mnew[mi][0]) * SC_);
                float p2 = __expf((accA[mi][nj][2] - mnew[mi][1]) * SC_);
                float p3 = __expf((accA[mi][nj][3] - mnew[mi][1]) * SC_);
                tsum[mi][0] += p0 + p1;
                tsum[mi][1] += p2 + p3;
                sm[AP + il * 132 + jl]           = __uint_as_float(f2tf(p0));
                sm[AP + il * 132 + jl + 1]       = __uint_as_float(f2tf(p1));
                sm[AP + (il + 8) * 132 + jl]     = __uint_as_float(f2tf(p2));
                sm[AP + (il + 8) * 132 + jl + 1] = __uint_as_float(f2tf(p3));
            }
#pragma unroll
        for (int mi = 0; mi < 2; mi++)
#pragma unroll
            for (int rp = 0; rp < 2; rp++) {
                float v = tsum[mi][rp];
                v += __shfl_xor_sync(0xffffffffu, v, 1);
                v += __shfl_xor_sync(0xffffffffu, v, 2);
                tsum[mi][rp] = v;
            }
        if (tg == 0) {
#pragma unroll
            for (int mi = 0; mi < 2; mi++)
#pragma unroll
                for (int rp = 0; rp < 2; rp++) {
                    int row = wi * 32 + mi * 16 + g + rp * 8;
                    sm[ARSM + row * 4 + wj] = tsum[mi][rp];
                }
        }
        __syncthreads();

#pragma unroll
        for (int mi = 0; mi < 2; mi++)
#pragma unroll
            for (int rp = 0; rp < 2; rp++) {
                int row = wi * 32 + mi * 16 + g + rp * 8;
                float lt = sm[ARSM + row * 4 + 0] + sm[ARSM + row * 4 + 1]
                         + sm[ARSM + row * 4 + 2] + sm[ARSM + row * 4 + 3];
                l_run[mi][rp] = l_run[mi][rp] * fsc[mi][rp] + lt;
                m_run[mi][rp] = mnew[mi][rp];
            }
#pragma unroll
        for (int mi = 0; mi < 2; mi++)
#pragma unroll
            for (int nd = 0; nd < 2; nd++) {
                accO[mi][nd][0] *= fsc[mi][0];
                accO[mi][nd][1] *= fsc[mi][0];
                accO[mi][nd][2] *= fsc[mi][1];
                accO[mi][nd][3] *= fsc[mi][1];
            }

        // PV (R12-identical)
        for (int jc = 0; jc < 2; jc++) {
            __syncthreads();
#pragma unroll
            for (int it = 0; it < 4; it++) {
                int t = tid + 256 * it;
                int row = t >> 4, dq = (t & 15) << 2;
                float4 vv = *(const float4*)(qkv + (size_t)((j0 + jc * 64 + row) * B_ + b) * (3 * E_)
                                             + 2 * E_ + h * D_ + dq);
                float4 hh, ll;
                split2(vv.x, hh.x, ll.x); split2(vv.y, hh.y, ll.y);
                split2(vv.z, hh.z, ll.z); split2(vv.w, hh.w, ll.w);
                *(float4*)&sm[AVH + row * 72 + dq] = hh;
                *(float4*)&sm[AVL + row * 72 + dq] = ll;
            }
            __syncthreads();
#pragma unroll
            for (int ks = 0; ks < 8; ks++) {
                float a[2][4];
#pragma unroll
                for (int mi = 0; mi < 2; mi++) {
                    int r0 = (wi * 32 + mi * 16 + g) * 132 + jc * 64 + ks * 8 + tg;
                    a[mi][0] = sm[AP + r0];
                    a[mi][1] = sm[AP + r0 + 8 * 132];
                    a[mi][2] = sm[AP + r0 + 4];
                    a[mi][3] = sm[AP + r0 + 8 * 132 + 4];
                }
#pragma unroll
                for (int nd = 0; nd < 2; nd++) {
                    int col = wj * 16 + nd * 8 + g;
                    float bhf[2], blf[2];
                    bhf[0] = sm[AVH + (ks * 8 + tg) * 72 + col];
                    bhf[1] = sm[AVH + (ks * 8 + tg + 4) * 72 + col];
                    blf[0] = sm[AVL + (ks * 8 + tg) * 72 + col];
                    blf[1] = sm[AVL + (ks * 8 + tg + 4) * 72 + col];
#pragma unroll
                    for (int mi = 0; mi < 2; mi++) {
                        mma8(accO[mi][nd], a[mi], bhf);
                        mma8(accO[mi][nd], a[mi], blf);
                    }
                }
            }
        }
    }

    float inv[2][2];
#pragma unroll
    for (int mi = 0; mi < 2; mi++)
#pragma unroll
        for (int rp = 0; rp < 2; rp++)
            inv[mi][rp] = 1.0f / l_run[mi][rp];
#pragma unroll
    for (int mi = 0; mi < 2; mi++)
#pragma unroll
        for (int nd = 0; nd < 2; nd++) {
            int row = wi * 32 + mi * 16 + g;
            int col = h * D_ + wj * 16 + nd * 8 + tg * 2;
            float2 o0 = {accO[mi][nd][0] * inv[mi][0], accO[mi][nd][1] * inv[mi][0]};
            float2 o1 = {accO[mi][nd][2] * inv[mi][1], accO[mi][nd][3] * inv[mi][1]};
            *(float2*)(att + (size_t)((i0 + row) * B_ + b) * E_ + col) = o0;
            *(float2*)(att + (size_t)((i0 + row + 8) * B_ + b) * E_ + col) = o1;
        }
}

// ---------------- launch ----------------
extern "C" void kernel_launch(void* const* d_in, const int* in_sizes, int n_in,
                              void* d_out, int out_size)
{
    (void)in_sizes; (void)n_in; (void)out_size;
    const float* input  = (const float*)d_in[0];
    const float* pos    = (const float*)d_in[1];
    const float* factor = (const float*)d_in[2];
    const float* w_in   = (const float*)d_in[3];
    const float* w_pos  = (const float*)d_in[4];
    const float* w_out  = (const float*)d_in[5];
    const float* bw_in  = (const float*)d_in[6];
    const float* bw_pos = (const float*)d_in[7];
    const float* bw_out = (const float*)d_in[8];
    const float* rwb    = (const float*)d_in[9];
    const float* rrb    = (const float*)d_in[10];

    float *pWin, *pWpos, *pWout, *pbin, *pbpos, *pbout, *prw, *prr,
          *pqkv, *pr, *patt;
    cudaGetSymbolAddress((void**)&pWin,  g_Win);
    cudaGetSymbolAddress((void**)&pWpos, g_Wpos);
    cudaGetSymbolAddress((void**)&pWout, g_Wout);
    cudaGetSymbolAddress((void**)&pbin,  g_bin);
    cudaGetSymbolAddress((void**)&pbpos, g_bpos);
    cudaGetSymbolAddress((void**)&pbout, g_bout);
    cudaGetSymbolAddress((void**)&prw,   g_rw);
    cudaGetSymbolAddress((void**)&prr,   g_rr);
    cudaGetSymbolAddress((void**)&pqkv,  g_qkv);
    cudaGetSymbolAddress((void**)&pr,    g_r);
    cudaGetSymbolAddress((void**)&patt,  g_att);

    cudaFuncSetAttribute(gemm3,           cudaFuncAttributeMaxDynamicSharedMemorySize, GEMM_SMEM);
    cudaFuncSetAttribute(attn_fused_impl, cudaFuncAttributeMaxDynamicSharedMemorySize, ATTN_SMEM);

    // 1) hypernet
    hyper_all<<<(HN7 + 255) / 256, 256>>>(w_in, w_pos, w_out, bw_in, bw_pos, bw_out,
                                          rwb, rrb, factor,
                                          pWin, pWpos, pWout, pbin, pbpos, pbout, prw, prr);

    // 2) projections (3xtf32, register double-buffered)
    gemm3<<<dim3(3 * E_ / 128, TB_ / 128), 256, GEMM_SMEM>>>(input, pWin, pbin, pqkv, TB_, 3 * E_, E_);
    gemm3<<<dim3(E_ / 128, (RB_ + 127) / 128), 256, GEMM_SMEM>>>(pos, pWpos, pbpos, pr, RB_, E_, E_);

    // 3) fused attention (persistent q, chunk-32 k/r, register prefetch)
    attn_fused_impl<<<dim3(T_ / 64, B_ * H_), 256, ATTN_SMEM>>>(pqkv, pr, prw, prr, patt);

    // 4) output projection -> d_out
    gemm3<<<dim3(E_ / 128, TB_ / 128), 256, GEMM_SMEM>>>(patt, pWout, pbout, (float*)d_out, TB_, E_, E_);
}

// round 14
// speedup vs baseline: 1.1312x; 1.0005x over previous
#include <cuda_runtime.h>
#include <math.h>

#define T_  1024
#define B_  2
#define E_  1024
#define H_  16
#define D_  64
#define TB_ 2048
#define RB_ 4094

// ---------------- scratch ----------------
__device__ float g_Win [3 * E_ * E_];
__device__ float g_Wpos[E_ * E_];
__device__ float g_Wout[E_ * E_];
__device__ float g_bin [3 * E_];
__device__ float g_bpos[E_];
__device__ float g_bout[E_];
__device__ float g_rw  [E_];
__device__ float g_rr  [E_];
__device__ float g_qkv [TB_ * 3 * E_];
__device__ float g_r   [RB_ * E_];
__device__ float g_att [TB_ * E_];

// ---------------- tf32 helpers ----------------
__device__ __forceinline__ unsigned f2tf(float f) {
    unsigned r; asm("cvt.rna.tf32.f32 %0, %1;" : "=r"(r) : "f"(f)); return r;
}
__device__ __forceinline__ void split2(float v, float& hi, float& lo) {
    hi = __uint_as_float(f2tf(v));
    lo = __uint_as_float(f2tf(v - hi));
}
__device__ __forceinline__ void mma8(float* c, const float* a, const float* b) {
    asm volatile("mma.sync.aligned.m16n8k8.row.col.f32.tf32.tf32.f32 "
                 "{%0,%1,%2,%3},{%4,%5,%6,%7},{%8,%9},{%0,%1,%2,%3};"
                 : "+f"(c[0]), "+f"(c[1]), "+f"(c[2]), "+f"(c[3])
                 : "r"(__float_as_uint(a[0])), "r"(__float_as_uint(a[1])),
                   "r"(__float_as_uint(a[2])), "r"(__float_as_uint(a[3])),
                   "r"(__float_as_uint(b[0])), "r"(__float_as_uint(b[1])));
}
__device__ __forceinline__ void mma3(float* c, const float* ah, const float* al,
                                     const float* bh, const float* bl) {
    mma8(c, ah, bh);
    mma8(c, ah, bl);
    mma8(c, al, bh);
}

// ---------------- fused hypernet ----------------
#define HN0 3145728
#define HN1 (HN0 + 1048576)
#define HN2 (HN1 + 1048576)
#define HN3 (HN2 + 3072)
#define HN4 (HN3 + 1024)
#define HN5 (HN4 + 1024)
#define HN6 (HN5 + 1024)
#define HN7 (HN6 + 1024)

__global__ __launch_bounds__(256) void hyper_all(
    const float* __restrict__ w_in,  const float* __restrict__ w_pos,
    const float* __restrict__ w_out, const float* __restrict__ b_in,
    const float* __restrict__ b_pos, const float* __restrict__ b_out,
    const float* __restrict__ rwb,   const float* __restrict__ rrb,
    const float* __restrict__ f,
    float* __restrict__ oWin,  float* __restrict__ oWpos,
    float* __restrict__ oWout, float* __restrict__ obin,
    float* __restrict__ obpos, float* __restrict__ obout,
    float* __restrict__ orw,   float* __restrict__ orr)
{
    int idx = blockIdx.x * blockDim.x + threadIdx.x;
    if (idx >= HN7) return;
    const float* src; float* dst; int off;
    if      (idx < HN0) { src = w_in;  dst = oWin;  off = idx; }
    else if (idx < HN1) { src = w_pos; dst = oWpos; off = idx - HN0; }
    else if (idx < HN2) { src = w_out; dst = oWout; off = idx - HN1; }
    else if (idx < HN3) { src = b_in;  dst = obin;  off = idx - HN2; }
    else if (idx < HN4) { src = b_pos; dst = obpos; off = idx - HN3; }
    else if (idx < HN5) { src = b_out; dst = obout; off = idx - HN4; }
    else if (idx < HN6) { src = rwb;   dst = orw;   off = idx - HN5; }
    else                { src = rrb;   dst = orr;   off = idx - HN6; }
    const float4* wp = (const float4*)(src + (size_t)off * 8);
    float4 a = wp[0], b = wp[1];
    float4 f0 = *(const float4*)f;
    float4 f1 = *(const float4*)(f + 4);
    dst[off] = a.x*f0.x + a.y*f0.y + a.z*f0.z + a.w*f0.w
             + b.x*f1.x + b.y*f1.y + b.z*f1.z + b.w*f1.w;
}

// ---------------- 3xtf32 NT GEMM: reg prefetch + smem double-buffer ------------
// buffer layout (floats): A_H 0, A_L 4608, B_H 9216, B_L 13824; buffer size 18432
#define GA_H 0
#define GA_L 4608
#define GB_H 9216
#define GB_L 13824
#define GBUF 18432
#define GEMM_SMEM (2 * GBUF * 4)

__global__ __launch_bounds__(256) void gemm3(const float* __restrict__ A,
                                             const float* __restrict__ Bm,
                                             const float* __restrict__ bias,
                                             float* __restrict__ C,
                                             int M, int N, int K)
{
    extern __shared__ float sm[];
    int bm = blockIdx.y * 128, bn = blockIdx.x * 128;
    int tid = threadIdx.x;
    int w = tid >> 5, lane = tid & 31;
    int g = lane >> 2, tg = lane & 3;
    int wm = w & 1, wn = w >> 1;
    float acc[4][4][4] = {};

    float4 pa[4], pb[4];
#pragma unroll
    for (int it = 0; it < 4; it++) {
        int t = tid + 256 * it;
        int row = t >> 3, kq = (t & 7) << 2;
        int m = bm + row;
        pa[it] = (m < M) ? *(const float4*)(A + (size_t)m * K + kq)
                         : make_float4(0.f, 0.f, 0.f, 0.f);
        pb[it] = *(const float4*)(Bm + (size_t)(bn + row) * K + kq);
    }
    // split-store tile 0 into buffer 0
#pragma unroll
    for (int it = 0; it < 4; it++) {
        int t = tid + 256 * it;
        int row = t >> 3, kq = (t & 7) << 2;
        float4 ah, al;
        split2(pa[it].x, ah.x, al.x); split2(pa[it].y, ah.y, al.y);
        split2(pa[it].z, ah.z, al.z); split2(pa[it].w, ah.w, al.w);
        *(float4*)&sm[GA_H + row * 36 + kq] = ah;
        *(float4*)&sm[GA_L + row * 36 + kq] = al;
        float4 bh, bl;
        split2(pb[it].x, bh.x, bl.x); split2(pb[it].y, bh.y, bl.y);
        split2(pb[it].z, bh.z, bl.z); split2(pb[it].w, bh.w, bl.w);
        *(float4*)&sm[GB_H + row * 36 + kq] = bh;
        *(float4*)&sm[GB_L + row * 36 + kq] = bl;
    }
    __syncthreads();

    for (int k0 = 0; k0 < K; k0 += 32) {
        const int cur = (k0 >> 5) & 1;
        const float* bc = sm + cur * GBUF;
        float* bn_ = sm + (cur ^ 1) * GBUF;
        const bool more = (k0 + 32 < K);

        // prefetch next tile from gmem (latency overlaps compute below)
        if (more) {
#pragma unroll
            for (int it = 0; it < 4; it++) {
                int t = tid + 256 * it;
                int row = t >> 3, kq = (t & 7) << 2;
                int m = bm + row;
                pa[it] = (m < M) ? *(const float4*)(A + (size_t)m * K + k0 + 32 + kq)
                                 : make_float4(0.f, 0.f, 0.f, 0.f);
                pb[it] = *(const float4*)(Bm + (size_t)(bn + row) * K + k0 + 32 + kq);
            }
        }

        // compute from current buffer
#pragma unroll
        for (int ks = 0; ks < 4; ks++) {
            float ah[4][4], al[4][4], bh[4][2], bl[4][2];
#pragma unroll
            for (int mi = 0; mi < 4; mi++) {
                int r0 = (wm * 64 + mi * 16 + g) * 36 + ks * 8 + tg;
                ah[mi][0] = bc[GA_H + r0];
                ah[mi][1] = bc[GA_H + r0 + 8 * 36];
                ah[mi][2] = bc[GA_H + r0 + 4];
                ah[mi][3] = bc[GA_H + r0 + 8 * 36 + 4];
                al[mi][0] = bc[GA_L + r0];
                al[mi][1] = bc[GA_L + r0 + 8 * 36];
                al[mi][2] = bc[GA_L + r0 + 4];
                al[mi][3] = bc[GA_L + r0 + 8 * 36 + 4];
            }
#pragma unroll
            for (int ni = 0; ni < 4; ni++) {
                int r0 = (wn * 32 + ni * 8 + g) * 36 + ks * 8 + tg;
                bh[ni][0] = bc[GB_H + r0];
                bh[ni][1] = bc[GB_H + r0 + 4];
                bl[ni][0] = bc[GB_L + r0];
                bl[ni][1] = bc[GB_L + r0 + 4];
            }
#pragma unroll
            for (int mi = 0; mi < 4; mi++)
#pragma unroll
                for (int ni = 0; ni < 4; ni++)
                    mma3(acc[mi][ni], ah[mi], al[mi], bh[ni], bl[ni]);
        }

        // split-store next tile into other buffer (safe: readers fenced last iter)
        if (more) {
#pragma unroll
            for (int it = 0; it < 4; it++) {
                int t = tid + 256 * it;
                int row = t >> 3, kq = (t & 7) << 2;
                float4 ah, al;
                split2(pa[it].x, ah.x, al.x); split2(pa[it].y, ah.y, al.y);
                split2(pa[it].z, ah.z, al.z); split2(pa[it].w, ah.w, al.w);
                *(float4*)&bn_[GA_H + row * 36 + kq] = ah;
                *(float4*)&bn_[GA_L + row * 36 + kq] = al;
                float4 bh, bl;
                split2(pb[it].x, bh.x, bl.x); split2(pb[it].y, bh.y, bl.y);
                split2(pb[it].z, bh.z, bl.z); split2(pb[it].w, bh.w, bl.w);
                *(float4*)&bn_[GB_H + row * 36 + kq] = bh;
                *(float4*)&bn_[GB_L + row * 36 + kq] = bl;
            }
        }
        __syncthreads();
    }

#pragma unroll
    for (int mi = 0; mi < 4; mi++)
#pragma unroll
        for (int ni = 0; ni < 4; ni++) {
            int m0 = bm + wm * 64 + mi * 16 + g;
            int n0 = bn + wn * 32 + ni * 8 + tg * 2;
            float bb0 = bias[n0], bb1 = bias[n0 + 1];
            if (m0 < M) {
                float2 o = {acc[mi][ni][0] + bb0, acc[mi][ni][1] + bb1};
                *(float2*)(C + (size_t)m0 * N + n0) = o;
            }
            if (m0 + 8 < M) {
                float2 o = {acc[mi][ni][2] + bb0, acc[mi][ni][3] + bb1};
                *(float2*)(C + (size_t)(m0 + 8) * N + n0) = o;
            }
        }
}

// ---------------- fused attention (R13-identical) ------------------------------
#define QWH  0
#define QWL  4352
#define QRH  8704
#define QRL  13056
#define AKH  17408
#define AKL  22016
#define ARH  26624
#define ARL  33536
#define AG   17408
#define AP   17408
#define AVH  25856
#define AVL  30464
#define ARMX 40448
#define ARSM 40704
#define ATTN_SMEM (40960 * 4)
#define SC_ 0.125f

__global__ __launch_bounds__(256) void attn_fused_impl(const float* __restrict__ qkv,
                                                       const float* __restrict__ rproj,
                                                       const float* __restrict__ rw,
                                                       const float* __restrict__ rr,
                                                       float* __restrict__ att)
{
    extern __shared__ float sm[];
    const int bh = blockIdx.y;
    const int b = bh / H_, h = bh % H_;
    const int i0 = blockIdx.x * 64;
    const int tid = threadIdx.x;
    const int w = tid >> 5, lane = tid & 31;
    const int g = lane >> 2, tg = lane & 3;
    const int wi = w >> 2, wj = w & 3;

#pragma unroll
    for (int it = 0; it < 4; it++) {
        int idx = tid + 256 * it;
        int row = idx >> 4, kq = (idx & 15) << 2;
        float4 qv = *(const float4*)(qkv + (size_t)((i0 + row) * B_ + b) * (3 * E_) + h * D_ + kq);
        float4 rwv = *(const float4*)(rw + h * D_ + kq);
        float4 rrv = *(const float4*)(rr + h * D_ + kq);
        float4 hw, lw, hr, lr;
        split2(qv.x + rwv.x, hw.x, lw.x); split2(qv.y + rwv.y, hw.y, lw.y);
        split2(qv.z + rwv.z, hw.z, lw.z); split2(qv.w + rwv.w, hw.w, lw.w);
        split2(qv.x + rrv.x, hr.x, lr.x); split2(qv.y + rrv.y, hr.y, lr.y);
        split2(qv.z + rrv.z, hr.z, lr.z); split2(qv.w + rrv.w, hr.w, lr.w);
        *(float4*)&sm[QWH + row * 68 + kq] = hw;
        *(float4*)&sm[QWL + row * 68 + kq] = lw;
        *(float4*)&sm[QRH + row * 68 + kq] = hr;
        *(float4*)&sm[QRL + row * 68 + kq] = lr;
    }

    float m_run[2][2] = {{-1e30f, -1e30f}, {-1e30f, -1e30f}};
    float l_run[2][2] = {};
    float accO[2][2][4] = {};

    float4 pk[4], pr6[6];
    {
        const int col0 = h * D_;
        const int pmin0 = T_ - 64 - i0;
#pragma unroll
        for (int it = 0; it < 4; it++) {
            int t = tid + 256 * it;
            int il = t >> 3, kq = (t & 7) << 2;
            pk[it] = *(const float4*)(qkv + (size_t)(il * B_ + b) * (3 * E_) + E_ + col0 + kq);
        }
#pragma unroll
        for (int it = 0; it < 6; it++) {
            int t = tid + 256 * it;
            int pl = t >> 3, kq = (t & 7) << 2;
            pr6[it] = (pl < 191)
                ? *(const float4*)(rproj + (size_t)((pmin0 + pl) * B_ + b) * E_ + col0 + kq)
                : make_float4(0.f, 0.f, 0.f, 0.f);
        }
    }

    for (int j0 = 0; j0 < T_; j0 += 128) {
        const int pmin = j0 - i0 + (T_ - 64);
        float accA[2][4][4] = {};
        float accG[2][6][4] = {};

        for (int c = 0; c < 2; c++) {
            __syncthreads();
#pragma unroll
            for (int it = 0; it < 4; it++) {
                int t = tid + 256 * it;
                int il = t >> 3, kq = (t & 7) << 2;
                float4 hk, lk;
                split2(pk[it].x, hk.x, lk.x); split2(pk[it].y, hk.y, lk.y);
                split2(pk[it].z, hk.z, lk.z); split2(pk[it].w, hk.w, lk.w);
                *(float4*)&sm[AKH + il * 36 + kq] = hk;
                *(float4*)&sm[AKL + il * 36 + kq] = lk;
            }
#pragma unroll
            for (int it = 0; it < 6; it++) {
                int t = tid + 256 * it;
                int pl = t >> 3, kq = (t & 7) << 2;
                float4 hh, ll;
                split2(pr6[it].x, hh.x, ll.x); split2(pr6[it].y, hh.y, ll.y);
                split2(pr6[it].z, hh.z, ll.z); split2(pr6[it].w, hh.w, ll.w);
                *(float4*)&sm[ARH + pl * 36 + kq] = hh;
                *(float4*)&sm[ARL + pl * 36 + kq] = ll;
            }
            __syncthreads();

            if (c == 0) {
                const int col0n = h * D_ + 32;
#pragma unroll
                for (int it = 0; it < 4; it++) {
                    int t = tid + 256 * it;
                    int il = t >> 3, kq = (t & 7) << 2;
                    pk[it] = *(const float4*)(qkv + (size_t)((j0 + il) * B_ + b) * (3 * E_) + E_ + col0n + kq);
                }
#pragma unroll
                for (int it = 0; it < 6; it++) {
                    int t = tid + 256 * it;
                    int pl = t >> 3, kq = (t & 7) << 2;
                    pr6[it] = (pl < 191)
                        ? *(const float4*)(rproj + (size_t)((pmin + pl) * B_ + b) * E_ + col0n + kq)
                        : make_float4(0.f, 0.f, 0.f, 0.f);
                }
            }

#pragma unroll
            for (int ks = 0; ks < 4; ks++) {
                float aWh[2][4], aWl[2][4], aRh[2][4], aRl[2][4];
#pragma unroll
                for (int mi = 0; mi < 2; mi++) {
                    int rq = (wi * 32 + mi * 16 + g) * 68 + c * 32 + ks * 8 + tg;
                    aWh[mi][0] = sm[QWH + rq];
                    aWh[mi][1] = sm[QWH + rq + 8 * 68];
                    aWh[mi][2] = sm[QWH + rq + 4];
                    aWh[mi][3] = sm[QWH + rq + 8 * 68 + 4];
                    aWl[mi][0] = sm[QWL + rq];
                    aWl[mi][1] = sm[QWL + rq + 8 * 68];
                    aWl[mi][2] = sm[QWL + rq + 4];
                    aWl[mi][3] = sm[QWL + rq + 8 * 68 + 4];
                    aRh[mi][0] = sm[QRH + rq];
                    aRh[mi][1] = sm[QRH + rq + 8 * 68];
                    aRh[mi][2] = sm[QRH + rq + 4];
                    aRh[mi][3] = sm[QRH + rq + 8 * 68 + 4];
                    aRl[mi][0] = sm[QRL + rq];
                    aRl[mi][1] = sm[QRL + rq + 8 * 68];
                    aRl[mi][2] = sm[QRL + rq + 4];
                    aRl[mi][3] = sm[QRL + rq + 8 * 68 + 4];
                }
#pragma unroll
                for (int nj = 0; nj < 4; nj++) {
                    float bhf[2], blf[2];
                    int r0 = (wj * 32 + nj * 8 + g) * 36 + ks * 8 + tg;
                    bhf[0] = sm[AKH + r0]; bhf[1] = sm[AKH + r0 + 4];
                    blf[0] = sm[AKL + r0]; blf[1] = sm[AKL + r0 + 4];
                    mma3(accA[0][nj], aWh[0], aWl[0], bhf, blf);
                    mma3(accA[1][nj], aWh[1], aWl[1], bhf, blf);
                }
#pragma unroll
                for (int ng = 0; ng < 6; ng++) {
                    float bhf[2], blf[2];
                    int r0 = (wj * 48 + ng * 8 + g) * 36 + ks * 8 + tg;
                    bhf[0] = sm[ARH + r0]; bhf[1] = sm[ARH + r0 + 4];
                    blf[0] = sm[ARL + r0]; blf[1] = sm[ARL + r0 + 4];
                    mma3(accG[0][ng], aRh[0], aRl[0], bhf, blf);
                    mma3(accG[1][ng], aRh[1], aRl[1], bhf, blf);
                }
            }
        }

        if (j0 + 128 < T_) {
            const int j0n = j0 + 128;
            const int pminN = j0n - i0 + (T_ - 64);
            const int col0 = h * D_;
#pragma unroll
            for (int it = 0; it < 4; it++) {
                int t = tid + 256 * it;
                int il = t >> 3, kq = (t & 7) << 2;
                pk[it] = *(const float4*)(qkv + (size_t)((j0n + il) * B_ + b) * (3 * E_) + E_ + col0 + kq);
            }
#pragma unroll
            for (int it = 0; it < 6; it++) {
                int t = tid + 256 * it;
                int pl = t >> 3, kq = (t & 7) << 2;
                pr6[it] = (pl < 191)
                    ? *(const float4*)(rproj + (size_t)((pminN + pl) * B_ + b) * E_ + col0 + kq)
                    : make_float4(0.f, 0.f, 0.f, 0.f);
            }
        }
        __syncthreads();

#pragma unroll
        for (int mi = 0; mi < 2; mi++)
#pragma unroll
            for (int ng = 0; ng < 6; ng++) {
                int row = wi * 32 + mi * 16 + g;
                int cc = wj * 48 + ng * 8 + tg * 2;
                sm[AG + row * 196 + cc]           = accG[mi][ng][0];
                sm[AG + row * 196 + cc + 1]       = accG[mi][ng][1];
                sm[AG + (row + 8) * 196 + cc]     = accG[mi][ng][2];
                sm[AG + (row + 8) * 196 + cc + 1] = accG[mi][ng][3];
            }
        __syncthreads();

        float tmax[2][2] = {{-1e30f, -1e30f}, {-1e30f, -1e30f}};
#pragma unroll
        for (int mi = 0; mi < 2; mi++)
#pragma unroll
            for (int nj = 0; nj < 4; nj++) {
                int il = wi * 32 + mi * 16 + g;
                int jl = wj * 32 + nj * 8 + tg * 2;
                int il2 = il + 8;
                accA[mi][nj][0] += sm[AG + il * 196 + (jl - il + 63)];
                accA[mi][nj][1] += sm[AG + il * 196 + (jl + 1 - il + 63)];
                accA[mi][nj][2] += sm[AG + il2 * 196 + (jl - il2 + 63)];
                accA[mi][nj][3] += sm[AG + il2 * 196 + (jl + 1 - il2 + 63)];
                tmax[mi][0] = fmaxf(tmax[mi][0], fmaxf(accA[mi][nj][0], accA[mi][nj][1]));
                tmax[mi][1] = fmaxf(tmax[mi][1], fmaxf(accA[mi][nj][2], accA[mi][nj][3]));
            }
#pragma unroll
        for (int mi = 0; mi < 2; mi++)
#pragma unroll
            for (int rp = 0; rp < 2; rp++) {
                float v = tmax[mi][rp];
                v = fmaxf(v, __shfl_xor_sync(0xffffffffu, v, 1));
                v = fmaxf(v, __shfl_xor_sync(0xffffffffu, v, 2));
                tmax[mi][rp] = v;
            }
        if (tg == 0) {
#pragma unroll
            for (int mi = 0; mi < 2; mi++)
#pragma unroll
                for (int rp = 0; rp < 2; rp++) {
                    int row = wi * 32 + mi * 16 + g + rp * 8;
                    sm[ARMX + row * 4 + wj] = tmax[mi][rp];
                }
        }
        __syncthreads();

        float mnew[2][2], fsc[2][2];
#pragma unroll
        for (int mi = 0; mi < 2; mi++)
#pragma unroll
            for (int rp = 0; rp < 2; rp++) {
                int row = wi * 32 + mi * 16 + g + rp * 8;
                float mt = fmaxf(fmaxf(sm[ARMX + row * 4 + 0], sm[ARMX + row * 4 + 1]),
                                 fmaxf(sm[ARMX + row * 4 + 2], sm[ARMX + row * 4 + 3]));
                mnew[mi][rp] = fmaxf(m_run[mi][rp], mt);
                fsc[mi][rp] = __expf((m_run[mi][rp] - mnew[mi][rp]) * SC_);
            }

        float tsum[2][2] = {};
#pragma unroll
        for (int mi = 0; mi < 2; mi++)
#pragma unroll
            for (int nj = 0; nj < 4; nj++) {
                int il = wi * 32 + mi * 16 + g;
                int jl = wj * 32 + nj * 8 + tg * 2;
                float p0 = __expf((accA[mi][nj][0] - mnew[mi][0]) * SC_);
                float p1 = __expf((accA[mi][nj][1] - mnew[mi][0]) * SC_);
                float p2 = __expf((accA[mi][nj][2] - mnew[mi][1]) * SC_);
                float p3 = __expf((accA[mi][nj][3] - mnew[mi][1]) * SC_);
                tsum[mi][0] += p0 + p1;
                tsum[mi][1] += p2 + p3;
                sm[AP + il * 132 + jl]           = __uint_as_float(f2tf(p0));
                sm[AP + il * 132 + jl + 1]       = __uint_as_float(f2tf(p1));
                sm[AP + (il + 8) * 132 + jl]     = __uint_as_float(f2tf(p2));
                sm[AP + (il + 8) * 132 + jl + 1] = __uint_as_float(f2tf(p3));
            }
#pragma unroll
        for (int mi = 0; mi < 2; mi++)
#pragma unroll
            for (int rp = 0; rp < 2; rp++) {
                float v = tsum[mi][rp];
                v += __shfl_xor_sync(0xffffffffu, v, 1);
                v += __shfl_xor_sync(0xffffffffu, v, 2);
                tsum[mi][rp] = v;
            }
        if (tg == 0) {
#pragma unroll
            for (int mi = 0; mi < 2; mi++)
#pragma unroll
                for (int rp = 0; rp < 2; rp++) {
                    int row = wi * 32 + mi * 16 + g + rp * 8;
                    sm[ARSM + row * 4 + wj] = tsum[mi][rp];
                }
        }
        __syncthreads();

#pragma unroll
        for (int mi = 0; mi < 2; mi++)
#pragma unroll
            for (int rp = 0; rp < 2; rp++) {
                int row = wi * 32 + mi * 16 + g + rp * 8;
                float lt = sm[ARSM + row * 4 + 0] + sm[ARSM + row * 4 + 1]
                         + sm[ARSM + row * 4 + 2] + sm[ARSM + row * 4 + 3];
                l_run[mi][rp] = l_run[mi][rp] * fsc[mi][rp] + lt;
                m_run[mi][rp] = mnew[mi][rp];
            }
#pragma unroll
        for (int mi = 0; mi < 2; mi++)
#pragma unroll
            for (int nd = 0; nd < 2; nd++) {
                accO[mi][nd][0] *= fsc[mi][0];
                accO[mi][nd][1] *= fsc[mi][0];
                accO[mi][nd][2] *= fsc[mi][1];
                accO[mi][nd][3] *= fsc[mi][1];
            }

        for (int jc = 0; jc < 2; jc++) {
            __syncthreads();
#pragma unroll
            for (int it = 0; it < 4; it++) {
                int t = tid + 256 * it;
                int row = t >> 4, dq = (t & 15) << 2;
                float4 vv = *(const float4*)(qkv + (size_t)((j0 + jc * 64 + row) * B_ + b) * (3 * E_)
                                             + 2 * E_ + h * D_ + dq);
                float4 hh, ll;
                split2(vv.x, hh.x, ll.x); split2(vv.y, hh.y, ll.y);
                split2(vv.z, hh.z, ll.z); split2(vv.w, hh.w, ll.w);
                *(float4*)&sm[AVH + row * 72 + dq] = hh;
                *(float4*)&sm[AVL + row * 72 + dq] = ll;
            }
            __syncthreads();
#pragma unroll
            for (int ks = 0; ks < 8; ks++) {
                float a[2][4];
#pragma unroll
                for (int mi = 0; mi < 2; mi++) {
                    int r0 = (wi * 32 + mi * 16 + g) * 132 + jc * 64 + ks * 8 + tg;
                    a[mi][0] = sm[AP + r0];
                    a[mi][1] = sm[AP + r0 + 8 * 132];
                    a[mi][2] = sm[AP + r0 + 4];
                    a[mi][3] = sm[AP + r0 + 8 * 132 + 4];
                }
#pragma unroll
                for (int nd = 0; nd < 2; nd++) {
                    int col = wj * 16 + nd * 8 + g;
                    float bhf[2], blf[2];
                    bhf[0] = sm[AVH + (ks * 8 + tg) * 72 + col];
                    bhf[1] = sm[AVH + (ks * 8 + tg + 4) * 72 + col];
                    blf[0] = sm[AVL + (ks * 8 + tg) * 72 + col];
                    blf[1] = sm[AVL + (ks * 8 + tg + 4) * 72 + col];
#pragma unroll
                    for (int mi = 0; mi < 2; mi++) {
                        mma8(accO[mi][nd], a[mi], bhf);
                        mma8(accO[mi][nd], a[mi], blf);
                    }
                }
            }
        }
    }

    float inv[2][2];
#pragma unroll
    for (int mi = 0; mi < 2; mi++)
#pragma unroll
        for (int rp = 0; rp < 2; rp++)
            inv[mi][rp] = 1.0f / l_run[mi][rp];
#pragma unroll
    for (int mi = 0; mi < 2; mi++)
#pragma unroll
        for (int nd = 0; nd < 2; nd++) {
            int row = wi * 32 + mi * 16 + g;
            int col = h * D_ + wj * 16 + nd * 8 + tg * 2;
            float2 o0 = {accO[mi][nd][0] * inv[mi][0], accO[mi][nd][1] * inv[mi][0]};
            float2 o1 = {accO[mi][nd][2] * inv[mi][1], accO[mi][nd][3] * inv[mi][1]};
            *(float2*)(att + (size_t)((i0 + row) * B_ + b) * E_ + col) = o0;
            *(float2*)(att + (size_t)((i0 + row + 8) * B_ + b) * E_ + col) = o1;
        }
}

// ---------------- launch ----------------
extern "C" void kernel_launch(void* const* d_in, const int* in_sizes, int n_in,
                              void* d_out, int out_size)
{
    (void)in_sizes; (void)n_in; (void)out_size;
    const float* input  = (const float*)d_in[0];
    const float* pos    = (const float*)d_in[1];
    const float* factor = (const float*)d_in[2];
    const float* w_in   = (const float*)d_in[3];
    const float* w_pos  = (const float*)d_in[4];
    const float* w_out  = (const float*)d_in[5];
    const float* bw_in  = (const float*)d_in[6];
    const float* bw_pos = (const float*)d_in[7];
    const float* bw_out = (const float*)d_in[8];
    const float* rwb    = (const float*)d_in[9];
    const float* rrb    = (const float*)d_in[10];

    float *pWin, *pWpos, *pWout, *pbin, *pbpos, *pbout, *prw, *prr,
          *pqkv, *pr, *patt;
    cudaGetSymbolAddress((void**)&pWin,  g_Win);
    cudaGetSymbolAddress((void**)&pWpos, g_Wpos);
    cudaGetSymbolAddress((void**)&pWout, g_Wout);
    cudaGetSymbolAddress((void**)&pbin,  g_bin);
    cudaGetSymbolAddress((void**)&pbpos, g_bpos);
    cudaGetSymbolAddress((void**)&pbout, g_bout);
    cudaGetSymbolAddress((void**)&prw,   g_rw);
    cudaGetSymbolAddress((void**)&prr,   g_rr);
    cudaGetSymbolAddress((void**)&pqkv,  g_qkv);
    cudaGetSymbolAddress((void**)&pr,    g_r);
    cudaGetSymbolAddress((void**)&patt,  g_att);

    cudaFuncSetAttribute(gemm3,           cudaFuncAttributeMaxDynamicSharedMemorySize, GEMM_SMEM);
    cudaFuncSetAttribute(attn_fused_impl, cudaFuncAttributeMaxDynamicSharedMemorySize, ATTN_SMEM);

    // 1) hypernet
    hyper_all<<<(HN7 + 255) / 256, 256>>>(w_in, w_pos, w_out, bw_in, bw_pos, bw_out,
                                          rwb, rrb, factor,
                                          pWin, pWpos, pWout, pbin, pbpos, pbout, prw, prr);

    // 2) projections (3xtf32, reg prefetch + smem double-buffer)
    gemm3<<<dim3(3 * E_ / 128, TB_ / 128), 256, GEMM_SMEM>>>(input, pWin, pbin, pqkv, TB_, 3 * E_, E_);
    gemm3<<<dim3(E_ / 128, (RB_ + 127) / 128), 256, GEMM_SMEM>>>(pos, pWpos, pbpos, pr, RB_, E_, E_);

    // 3) fused attention (R13-identical)
    attn_fused_impl<<<dim3(T_ / 64, B_ * H_), 256, ATTN_SMEM>>>(pqkv, pr, prw, prr, patt);

    // 4) output projection -> d_out
    gemm3<<<dim3(E_ / 128, TB_ / 128), 256, GEMM_SMEM>>>(patt, pWout, pbout, (float*)d_out, TB_, E_, E_);
}

// round 15
// speedup vs baseline: 1.1333x; 1.0019x over previous
#include <cuda_runtime.h>
#include <math.h>

#define T_  1024
#define B_  2
#define E_  1024
#define H_  16
#define D_  64
#define TB_ 2048
#define RB_ 4094

// ---------------- scratch ----------------
__device__ float g_Win [3 * E_ * E_];
__device__ float g_Wpos[E_ * E_];
__device__ float g_Wout[E_ * E_];
__device__ float g_bin [3 * E_];
__device__ float g_bpos[E_];
__device__ float g_bout[E_];
__device__ float g_rw  [E_];
__device__ float g_rr  [E_];
__device__ float g_qkv [TB_ * 3 * E_];
__device__ float g_r   [RB_ * E_];
__device__ float g_att [TB_ * E_];

// ---------------- tf32 helpers ----------------
__device__ __forceinline__ unsigned f2tf(float f) {
    unsigned r; asm("cvt.rna.tf32.f32 %0, %1;" : "=r"(r) : "f"(f)); return r;
}
__device__ __forceinline__ void split2(float v, float& hi, float& lo) {
    hi = __uint_as_float(f2tf(v));
    lo = __uint_as_float(f2tf(v - hi));
}
__device__ __forceinline__ void mma8(float* c, const float* a, const float* b) {
    asm volatile("mma.sync.aligned.m16n8k8.row.col.f32.tf32.tf32.f32 "
                 "{%0,%1,%2,%3},{%4,%5,%6,%7},{%8,%9},{%0,%1,%2,%3};"
                 : "+f"(c[0]), "+f"(c[1]), "+f"(c[2]), "+f"(c[3])
                 : "r"(__float_as_uint(a[0])), "r"(__float_as_uint(a[1])),
                   "r"(__float_as_uint(a[2])), "r"(__float_as_uint(a[3])),
                   "r"(__float_as_uint(b[0])), "r"(__float_as_uint(b[1])));
}
__device__ __forceinline__ void mma3(float* c, const float* ah, const float* al,
                                     const float* bh, const float* bl) {
    mma8(c, ah, bh);
    mma8(c, ah, bl);
    mma8(c, al, bh);
}

// ---------------- cp.async helpers ----------------
__device__ __forceinline__ void cpa16(unsigned d, const void* s) {
    asm volatile("cp.async.cg.shared.global [%0], [%1], 16;" :: "r"(d), "l"(s));
}
__device__ __forceinline__ void cpa16z(unsigned d, const void* s) {
    asm volatile("cp.async.cg.shared.global [%0], [%1], 16, 0;" :: "r"(d), "l"(s));
}
#define CP_COMMIT() asm volatile("cp.async.commit_group;" ::: "memory")
#define CP_WAIT0()  asm volatile("cp.async.wait_group 0;" ::: "memory")

// ---------------- fused hypernet ----------------
#define HN0 3145728
#define HN1 (HN0 + 1048576)
#define HN2 (HN1 + 1048576)
#define HN3 (HN2 + 3072)
#define HN4 (HN3 + 1024)
#define HN5 (HN4 + 1024)
#define HN6 (HN5 + 1024)
#define HN7 (HN6 + 1024)

__global__ __launch_bounds__(256) void hyper_all(
    const float* __restrict__ w_in,  const float* __restrict__ w_pos,
    const float* __restrict__ w_out, const float* __restrict__ b_in,
    const float* __restrict__ b_pos, const float* __restrict__ b_out,
    const float* __restrict__ rwb,   const float* __restrict__ rrb,
    const float* __restrict__ f,
    float* __restrict__ oWin,  float* __restrict__ oWpos,
    float* __restrict__ oWout, float* __restrict__ obin,
    float* __restrict__ obpos, float* __restrict__ obout,
    float* __restrict__ orw,   float* __restrict__ orr)
{
    int idx = blockIdx.x * blockDim.x + threadIdx.x;
    if (idx >= HN7) return;
    const float* src; float* dst; int off;
    if      (idx < HN0) { src = w_in;  dst = oWin;  off = idx; }
    else if (idx < HN1) { src = w_pos; dst = oWpos; off = idx - HN0; }
    else if (idx < HN2) { src = w_out; dst = oWout; off = idx - HN1; }
    else if (idx < HN3) { src = b_in;  dst = obin;  off = idx - HN2; }
    else if (idx < HN4) { src = b_pos; dst = obpos; off = idx - HN3; }
    else if (idx < HN5) { src = b_out; dst = obout; off = idx - HN4; }
    else if (idx < HN6) { src = rwb;   dst = orw;   off = idx - HN5; }
    else                { src = rrb;   dst = orr;   off = idx - HN6; }
    const float4* wp = (const float4*)(src + (size_t)off * 8);
    float4 a = wp[0], b = wp[1];
    float4 f0 = *(const float4*)f;
    float4 f1 = *(const float4*)(f + 4);
    dst[off] = a.x*f0.x + a.y*f0.y + a.z*f0.z + a.w*f0.w
             + b.x*f1.x + b.y*f1.y + b.z*f1.z + b.w*f1.w;
}

// ---------------- 3xtf32 NT GEMM: cp.async raw fp32 tiles + consume-side split -
// buffer (floats): A 128x32 @stride 36 [0,4608), B 128x32 @stride 36 [4608,9216)
#define GBUF 9216
#define GEMM_SMEM (2 * GBUF * 4)

__global__ __launch_bounds__(256, 2) void gemm3(const float* __restrict__ A,
                                                const float* __restrict__ Bm,
                                                const float* __restrict__ bias,
                                                float* __restrict__ C,
                                                int M, int N, int K)
{
    extern __shared__ float sm[];
    int bm = blockIdx.y * 128, bn = blockIdx.x * 128;
    int tid = threadIdx.x;
    int w = tid >> 5, lane = tid & 31;
    int g = lane >> 2, tg = lane & 3;
    int wm = w & 1, wn = w >> 1;
    float acc[4][4][4] = {};

    unsigned sbase = (unsigned)__cvta_generic_to_shared(sm);

    // issue tile k0 into buffer buf
    auto issue_tile = [&](int k0, int buf) {
        unsigned bb = sbase + (unsigned)(buf * GBUF) * 4u;
#pragma unroll
        for (int it = 0; it < 4; it++) {
            int t = tid + 256 * it;
            int row = t >> 3, kq = (t & 7) << 2;
            int m = bm + row;
            unsigned da = bb + (unsigned)(row * 36 + kq) * 4u;
            if (m < M) cpa16(da, A + (size_t)m * K + k0 + kq);
            else       cpa16z(da, A);
            unsigned db = bb + (unsigned)(4608 + row * 36 + kq) * 4u;
            cpa16(db, Bm + (size_t)(bn + row) * K + k0 + kq);
        }
    };

    issue_tile(0, 0);
    CP_COMMIT();

    for (int k0 = 0; k0 < K; k0 += 32) {
        const int cur = (k0 >> 5) & 1;
        const float* bc = sm + cur * GBUF;

        CP_WAIT0();
        __syncthreads();

        if (k0 + 32 < K) {
            issue_tile(k0 + 32, cur ^ 1);
            CP_COMMIT();
        }

#pragma unroll
        for (int ks = 0; ks < 4; ks++) {
            float ah[4][4], al[4][4], bh[4][2], bl[4][2];
#pragma unroll
            for (int mi = 0; mi < 4; mi++) {
                int r0 = (wm * 64 + mi * 16 + g) * 36 + ks * 8 + tg;
                split2(bc[r0],            ah[mi][0], al[mi][0]);
                split2(bc[r0 + 8 * 36],   ah[mi][1], al[mi][1]);
                split2(bc[r0 + 4],        ah[mi][2], al[mi][2]);
                split2(bc[r0 + 8 * 36 + 4], ah[mi][3], al[mi][3]);
            }
#pragma unroll
            for (int ni = 0; ni < 4; ni++) {
                int r0 = 4608 + (wn * 32 + ni * 8 + g) * 36 + ks * 8 + tg;
                split2(bc[r0],     bh[ni][0], bl[ni][0]);
                split2(bc[r0 + 4], bh[ni][1], bl[ni][1]);
            }
#pragma unroll
            for (int mi = 0; mi < 4; mi++)
#pragma unroll
                for (int ni = 0; ni < 4; ni++)
                    mma3(acc[mi][ni], ah[mi], al[mi], bh[ni], bl[ni]);
        }
    }

#pragma unroll
    for (int mi = 0; mi < 4; mi++)
#pragma unroll
        for (int ni = 0; ni < 4; ni++) {
            int m0 = bm + wm * 64 + mi * 16 + g;
            int n0 = bn + wn * 32 + ni * 8 + tg * 2;
            float bb0 = bias[n0], bb1 = bias[n0 + 1];
            if (m0 < M) {
                float2 o = {acc[mi][ni][0] + bb0, acc[mi][ni][1] + bb1};
                *(float2*)(C + (size_t)m0 * N + n0) = o;
            }
            if (m0 + 8 < M) {
                float2 o = {acc[mi][ni][2] + bb0, acc[mi][ni][3] + bb1};
                *(float2*)(C + (size_t)(m0 + 8) * N + n0) = o;
            }
        }
}

// ---------------- fused attention (R13-identical) ------------------------------
#define QWH  0
#define QWL  4352
#define QRH  8704
#define QRL  13056
#define AKH  17408
#define AKL  22016
#define ARH  26624
#define ARL  33536
#define AG   17408
#define AP   17408
#define AVH  25856
#define AVL  30464
#define ARMX 40448
#define ARSM 40704
#define ATTN_SMEM (40960 * 4)
#define SC_ 0.125f

__global__ __launch_bounds__(256) void attn_fused_impl(const float* __restrict__ qkv,
                                                       const float* __restrict__ rproj,
                                                       const float* __restrict__ rw,
                                                       const float* __restrict__ rr,
                                                       float* __restrict__ att)
{
    extern __shared__ float sm[];
    const int bh = blockIdx.y;
    const int b = bh / H_, h = bh % H_;
    const int i0 = blockIdx.x * 64;
    const int tid = threadIdx.x;
    const int w = tid >> 5, lane = tid & 31;
    const int g = lane >> 2, tg = lane & 3;
    const int wi = w >> 2, wj = w & 3;

#pragma unroll
    for (int it = 0; it < 4; it++) {
        int idx = tid + 256 * it;
        int row = idx >> 4, kq = (idx & 15) << 2;
        float4 qv = *(const float4*)(qkv + (size_t)((i0 + row) * B_ + b) * (3 * E_) + h * D_ + kq);
        float4 rwv = *(const float4*)(rw + h * D_ + kq);
        float4 rrv = *(const float4*)(rr + h * D_ + kq);
        float4 hw, lw, hr, lr;
        split2(qv.x + rwv.x, hw.x, lw.x); split2(qv.y + rwv.y, hw.y, lw.y);
        split2(qv.z + rwv.z, hw.z, lw.z); split2(qv.w + rwv.w, hw.w, lw.w);
        split2(qv.x + rrv.x, hr.x, lr.x); split2(qv.y + rrv.y, hr.y, lr.y);
        split2(qv.z + rrv.z, hr.z, lr.z); split2(qv.w + rrv.w, hr.w, lr.w);
        *(float4*)&sm[QWH + row * 68 + kq] = hw;
        *(float4*)&sm[QWL + row * 68 + kq] = lw;
        *(float4*)&sm[QRH + row * 68 + kq] = hr;
        *(float4*)&sm[QRL + row * 68 + kq] = lr;
    }

    float m_run[2][2] = {{-1e30f, -1e30f}, {-1e30f, -1e30f}};
    float l_run[2][2] = {};
    float accO[2][2][4] = {};

    float4 pk[4], pr6[6];
    {
        const int col0 = h * D_;
        const int pmin0 = T_ - 64 - i0;
#pragma unroll
        for (int it = 0; it < 4; it++) {
            int t = tid + 256 * it;
            int il = t >> 3, kq = (t & 7) << 2;
            pk[it] = *(const float4*)(qkv + (size_t)(il * B_ + b) * (3 * E_) + E_ + col0 + kq);
        }
#pragma unroll
        for (int it = 0; it < 6; it++) {
            int t = tid + 256 * it;
            int pl = t >> 3, kq = (t & 7) << 2;
            pr6[it] = (pl < 191)
                ? *(const float4*)(rproj + (size_t)((pmin0 + pl) * B_ + b) * E_ + col0 + kq)
                : make_float4(0.f, 0.f, 0.f, 0.f);
        }
    }

    for (int j0 = 0; j0 < T_; j0 += 128) {
        const int pmin = j0 - i0 + (T_ - 64);
        float accA[2][4][4] = {};
        float accG[2][6][4] = {};

        for (int c = 0; c < 2; c++) {
            __syncthreads();
#pragma unroll
            for (int it = 0; it < 4; it++) {
                int t = tid + 256 * it;
                int il = t >> 3, kq = (t & 7) << 2;
                float4 hk, lk;
                split2(pk[it].x, hk.x, lk.x); split2(pk[it].y, hk.y, lk.y);
                split2(pk[it].z, hk.z, lk.z); split2(pk[it].w, hk.w, lk.w);
                *(float4*)&sm[AKH + il * 36 + kq] = hk;
                *(float4*)&sm[AKL + il * 36 + kq] = lk;
            }
#pragma unroll
            for (int it = 0; it < 6; it++) {
                int t = tid + 256 * it;
                int pl = t >> 3, kq = (t & 7) << 2;
                float4 hh, ll;
                split2(pr6[it].x, hh.x, ll.x); split2(pr6[it].y, hh.y, ll.y);
                split2(pr6[it].z, hh.z, ll.z); split2(pr6[it].w, hh.w, ll.w);
                *(float4*)&sm[ARH + pl * 36 + kq] = hh;
                *(float4*)&sm[ARL + pl * 36 + kq] = ll;
            }
            __syncthreads();

            if (c == 0) {
                const int col0n = h * D_ + 32;
#pragma unroll
                for (int it = 0; it < 4; it++) {
                    int t = tid + 256 * it;
                    int il = t >> 3, kq = (t & 7) << 2;
                    pk[it] = *(const float4*)(qkv + (size_t)((j0 + il) * B_ + b) * (3 * E_) + E_ + col0n + kq);
                }
#pragma unroll
                for (int it = 0; it < 6; it++) {
                    int t = tid + 256 * it;
                    int pl = t >> 3, kq = (t & 7) << 2;
                    pr6[it] = (pl < 191)
                        ? *(const float4*)(rproj + (size_t)((pmin + pl) * B_ + b) * E_ + col0n + kq)
                        : make_float4(0.f, 0.f, 0.f, 0.f);
                }
            }

#pragma unroll
            for (int ks = 0; ks < 4; ks++) {
                float aWh[2][4], aWl[2][4], aRh[2][4], aRl[2][4];
#pragma unroll
                for (int mi = 0; mi < 2; mi++) {
                    int rq = (wi * 32 + mi * 16 + g) * 68 + c * 32 + ks * 8 + tg;
                    aWh[mi][0] = sm[QWH + rq];
                    aWh[mi][1] = sm[QWH + rq + 8 * 68];
                    aWh[mi][2] = sm[QWH + rq + 4];
                    aWh[mi][3] = sm[QWH + rq + 8 * 68 + 4];
                    aWl[mi][0] = sm[QWL + rq];
                    aWl[mi][1] = sm[QWL + rq + 8 * 68];
                    aWl[mi][2] = sm[QWL + rq + 4];
                    aWl[mi][3] = sm[QWL + rq + 8 * 68 + 4];
                    aRh[mi][0] = sm[QRH + rq];
                    aRh[mi][1] = sm[QRH + rq + 8 * 68];
                    aRh[mi][2] = sm[QRH + rq + 4];
                    aRh[mi][3] = sm[QRH + rq + 8 * 68 + 4];
                    aRl[mi][0] = sm[QRL + rq];
                    aRl[mi][1] = sm[QRL + rq + 8 * 68];
                    aRl[mi][2] = sm[QRL + rq + 4];
                    aRl[mi][3] = sm[QRL + rq + 8 * 68 + 4];
                }
#pragma unroll
                for (int nj = 0; nj < 4; nj++) {
                    float bhf[2], blf[2];
                    int r0 = (wj * 32 + nj * 8 + g) * 36 + ks * 8 + tg;
                    bhf[0] = sm[AKH + r0]; bhf[1] = sm[AKH + r0 + 4];
                    blf[0] = sm[AKL + r0]; blf[1] = sm[AKL + r0 + 4];
                    mma3(accA[0][nj], aWh[0], aWl[0], bhf, blf);
                    mma3(accA[1][nj], aWh[1], aWl[1], bhf, blf);
                }
#pragma unroll
                for (int ng = 0; ng < 6; ng++) {
                    float bhf[2], blf[2];
                    int r0 = (wj * 48 + ng * 8 + g) * 36 + ks * 8 + tg;
                    bhf[0] = sm[ARH + r0]; bhf[1] = sm[ARH + r0 + 4];
                    blf[0] = sm[ARL + r0]; blf[1] = sm[ARL + r0 + 4];
                    mma3(accG[0][ng], aRh[0], aRl[0], bhf, blf);
                    mma3(accG[1][ng], aRh[1], aRl[1], bhf, blf);
                }
            }
        }

        if (j0 + 128 < T_) {
            const int j0n = j0 + 128;
            const int pminN = j0n - i0 + (T_ - 64);
            const int col0 = h * D_;
#pragma unroll
            for (int it = 0; it < 4; it++) {
                int t = tid + 256 * it;
                int il = t >> 3, kq = (t & 7) << 2;
                pk[it] = *(const float4*)(qkv + (size_t)((j0n + il) * B_ + b) * (3 * E_) + E_ + col0 + kq);
            }
#pragma unroll
            for (int it = 0; it < 6; it++) {
                int t = tid + 256 * it;
                int pl = t >> 3, kq = (t & 7) << 2;
                pr6[it] = (pl < 191)
                    ? *(const float4*)(rproj + (size_t)((pminN + pl) * B_ + b) * E_ + col0 + kq)
                    : make_float4(0.f, 0.f, 0.f, 0.f);
            }
        }
        __syncthreads();

#pragma unroll
        for (int mi = 0; mi < 2; mi++)
#pragma unroll
            for (int ng = 0; ng < 6; ng++) {
                int row = wi * 32 + mi * 16 + g;
                int cc = wj * 48 + ng * 8 + tg * 2;
                sm[AG + row * 196 + cc]           = accG[mi][ng][0];
                sm[AG + row * 196 + cc + 1]       = accG[mi][ng][1];
                sm[AG + (row + 8) * 196 + cc]     = accG[mi][ng][2];
                sm[AG + (row + 8) * 196 + cc + 1] = accG[mi][ng][3];
            }
        __syncthreads();

        float tmax[2][2] = {{-1e30f, -1e30f}, {-1e30f, -1e30f}};
#pragma unroll
        for (int mi = 0; mi < 2; mi++)
#pragma unroll
            for (int nj = 0; nj < 4; nj++) {
                int il = wi * 32 + mi * 16 + g;
                int jl = wj * 32 + nj * 8 + tg * 2;
                int il2 = il + 8;
                accA[mi][nj][0] += sm[AG + il * 196 + (jl - il + 63)];
                accA[mi][nj][1] += sm[AG + il * 196 + (jl + 1 - il + 63)];
                accA[mi][nj][2] += sm[AG + il2 * 196 + (jl - il2 + 63)];
                accA[mi][nj][3] += sm[AG + il2 * 196 + (jl + 1 - il2 + 63)];
                tmax[mi][0] = fmaxf(tmax[mi][0], fmaxf(accA[mi][nj][0], accA[mi][nj][1]));
                tmax[mi][1] = fmaxf(tmax[mi][1], fmaxf(accA[mi][nj][2], accA[mi][nj][3]));
            }
#pragma unroll
        for (int mi = 0; mi < 2; mi++)
#pragma unroll
            for (int rp = 0; rp < 2; rp++) {
                float v = tmax[mi][rp];
                v = fmaxf(v, __shfl_xor_sync(0xffffffffu, v, 1));
                v = fmaxf(v, __shfl_xor_sync(0xffffffffu, v, 2));
                tmax[mi][rp] = v;
            }
        if (tg == 0) {
#pragma unroll
            for (int mi = 0; mi < 2; mi++)
#pragma unroll
                for (int rp = 0; rp < 2; rp++) {
                    int row = wi * 32 + mi * 16 + g + rp * 8;
                    sm[ARMX + row * 4 + wj] = tmax[mi][rp];
                }
        }
        __syncthreads();

        float mnew[2][2], fsc[2][2];
#pragma unroll
        for (int mi = 0; mi < 2; mi++)
#pragma unroll
            for (int rp = 0; rp < 2; rp++) {
                int row = wi * 32 + mi * 16 + g + rp * 8;
                float mt = fmaxf(fmaxf(sm[ARMX + row * 4 + 0], sm[ARMX + row * 4 + 1]),
                                 fmaxf(sm[ARMX + row * 4 + 2], sm[ARMX + row * 4 + 3]));
                mnew[mi][rp] = fmaxf(m_run[mi][rp], mt);
                fsc[mi][rp] = __expf((m_run[mi][rp] - mnew[mi][rp]) * SC_);
            }

        float tsum[2][2] = {};
#pragma unroll
        for (int mi = 0; mi < 2; mi++)
#pragma unroll
            for (int nj = 0; nj < 4; nj++) {
                int il = wi * 32 + mi * 16 + g;
                int jl = wj * 32 + nj * 8 + tg * 2;
                float p0 = __expf((accA[mi][nj][0] - mnew[mi][0]) * SC_);
                float p1 = __expf((accA[mi][nj][1] - mnew[mi][0]) * SC_);
                float p2 = __expf((accA[mi][nj][2] - mnew[mi][1]) * SC_);
                float p3 = __expf((accA[mi][nj][3] - mnew[mi][1]) * SC_);
                tsum[mi][0] += p0 + p1;
                tsum[mi][1] += p2 + p3;
                sm[AP + il * 132 + jl]           = __uint_as_float(f2tf(p0));
                sm[AP + il * 132 + jl + 1]       = __uint_as_float(f2tf(p1));
                sm[AP + (il + 8) * 132 + jl]     = __uint_as_float(f2tf(p2));
                sm[AP + (il + 8) * 132 + jl + 1] = __uint_as_float(f2tf(p3));
            }
#pragma unroll
        for (int mi = 0; mi < 2; mi++)
#pragma unroll
            for (int rp = 0; rp < 2; rp++) {
                float v = tsum[mi][rp];
                v += __shfl_xor_sync(0xffffffffu, v, 1);
                v += __shfl_xor_sync(0xffffffffu, v, 2);
                tsum[mi][rp] = v;
            }
        if (tg == 0) {
#pragma unroll
            for (int mi = 0; mi < 2; mi++)
#pragma unroll
                for (int rp = 0; rp < 2; rp++) {
                    int row = wi * 32 + mi * 16 + g + rp * 8;
                    sm[ARSM + row * 4 + wj] = tsum[mi][rp];
                }
        }
        __syncthreads();

#pragma unroll
        for (int mi = 0; mi < 2; mi++)
#pragma unroll
            for (int rp = 0; rp < 2; rp++) {
                int row = wi * 32 + mi * 16 + g + rp * 8;
                float lt = sm[ARSM + row * 4 + 0] + sm[ARSM + row * 4 + 1]
                         + sm[ARSM + row * 4 + 2] + sm[ARSM + row * 4 + 3];
                l_run[mi][rp] = l_run[mi][rp] * fsc[mi][rp] + lt;
                m_run[mi][rp] = mnew[mi][rp];
            }
#pragma unroll
        for (int mi = 0; mi < 2; mi++)
#pragma unroll
            for (int nd = 0; nd < 2; nd++) {
                accO[mi][nd][0] *= fsc[mi][0];
                accO[mi][nd][1] *= fsc[mi][0];
                accO[mi][nd][2] *= fsc[mi][1];
                accO[mi][nd][3] *= fsc[mi][1];
            }

        for (int jc = 0; jc < 2; jc++) {
            __syncthreads();
#pragma unroll
            for (int it = 0; it < 4; it++) {
                int t = tid + 256 * it;
                int row = t >> 4, dq = (t & 15) << 2;
                float4 vv = *(const float4*)(qkv + (size_t)((j0 + jc * 64 + row) * B_ + b) * (3 * E_)
                                             + 2 * E_ + h * D_ + dq);
                float4 hh, ll;
                split2(vv.x, hh.x, ll.x); split2(vv.y, hh.y, ll.y);
                split2(vv.z, hh.z, ll.z); split2(vv.w, hh.w, ll.w);
                *(float4*)&sm[AVH + row * 72 + dq] = hh;
                *(float4*)&sm[AVL + row * 72 + dq] = ll;
            }
            __syncthreads();
#pragma unroll
            for (int ks = 0; ks < 8; ks++) {
                float a[2][4];
#pragma unroll
                for (int mi = 0; mi < 2; mi++) {
                    int r0 = (wi * 32 + mi * 16 + g) * 132 + jc * 64 + ks * 8 + tg;
                    a[mi][0] = sm[AP + r0];
                    a[mi][1] = sm[AP + r0 + 8 * 132];
                    a[mi][2] = sm[AP + r0 + 4];
                    a[mi][3] = sm[AP + r0 + 8 * 132 + 4];
                }
#pragma unroll
                for (int nd = 0; nd < 2; nd++) {
                    int col = wj * 16 + nd * 8 + g;
                    float bhf[2], blf[2];
                    bhf[0] = sm[AVH + (ks * 8 + tg) * 72 + col];
                    bhf[1] = sm[AVH + (ks * 8 + tg + 4) * 72 + col];
                    blf[0] = sm[AVL + (ks * 8 + tg) * 72 + col];
                    blf[1] = sm[AVL + (ks * 8 + tg + 4) * 72 + col];
#pragma unroll
                    for (int mi = 0; mi < 2; mi++) {
                        mma8(accO[mi][nd], a[mi], bhf);
                        mma8(accO[mi][nd], a[mi], blf);
                    }
                }
            }
        }
    }

    float inv[2][2];
#pragma unroll
    for (int mi = 0; mi < 2; mi++)
#pragma unroll
        for (int rp = 0; rp < 2; rp++)
            inv[mi][rp] = 1.0f / l_run[mi][rp];
#pragma unroll
    for (int mi = 0; mi < 2; mi++)
#pragma unroll
        for (int nd = 0; nd < 2; nd++) {
            int row = wi * 32 + mi * 16 + g;
            int col = h * D_ + wj * 16 + nd * 8 + tg * 2;
            float2 o0 = {accO[mi][nd][0] * inv[mi][0], accO[mi][nd][1] * inv[mi][0]};
            float2 o1 = {accO[mi][nd][2] * inv[mi][1], accO[mi][nd][3] * inv[mi][1]};
            *(float2*)(att + (size_t)((i0 + row) * B_ + b) * E_ + col) = o0;
            *(float2*)(att + (size_t)((i0 + row + 8) * B_ + b) * E_ + col) = o1;
        }
}

// ---------------- launch ----------------
extern "C" void kernel_launch(void* const* d_in, const int* in_sizes, int n_in,
                              void* d_out, int out_size)
{
    (void)in_sizes; (void)n_in; (void)out_size;
    const float* input  = (const float*)d_in[0];
    const float* pos    = (const float*)d_in[1];
    const float* factor = (const float*)d_in[2];
    const float* w_in   = (const float*)d_in[3];
    const float* w_pos  = (const float*)d_in[4];
    const float* w_out  = (const float*)d_in[5];
    const float* bw_in  = (const float*)d_in[6];
    const float* bw_pos = (const float*)d_in[7];
    const float* bw_out = (const float*)d_in[8];
    const float* rwb    = (const float*)d_in[9];
    const float* rrb    = (const float*)d_in[10];

    float *pWin, *pWpos, *pWout, *pbin, *pbpos, *pbout, *prw, *prr,
          *pqkv, *pr, *patt;
    cudaGetSymbolAddress((void**)&pWin,  g_Win);
    cudaGetSymbolAddress((void**)&pWpos, g_Wpos);
    cudaGetSymbolAddress((void**)&pWout, g_Wout);
    cudaGetSymbolAddress((void**)&pbin,  g_bin);
    cudaGetSymbolAddress((void**)&pbpos, g_bpos);
    cudaGetSymbolAddress((void**)&pbout, g_bout);
    cudaGetSymbolAddress((void**)&prw,   g_rw);
    cudaGetSymbolAddress((void**)&prr,   g_rr);
    cudaGetSymbolAddress((void**)&pqkv,  g_qkv);
    cudaGetSymbolAddress((void**)&pr,    g_r);
    cudaGetSymbolAddress((void**)&patt,  g_att);

    cudaFuncSetAttribute(gemm3,           cudaFuncAttributeMaxDynamicSharedMemorySize, GEMM_SMEM);
    cudaFuncSetAttribute(attn_fused_impl, cudaFuncAttributeMaxDynamicSharedMemorySize, ATTN_SMEM);

    // 1) hypernet
    hyper_all<<<(HN7 + 255) / 256, 256>>>(w_in, w_pos, w_out, bw_in, bw_pos, bw_out,
                                          rwb, rrb, factor,
                                          pWin, pWpos, pWout, pbin, pbpos, pbout, prw, prr);

    // 2) projections (3xtf32, cp.async pipeline, consume-side split, 2 CTAs/SM)
    gemm3<<<dim3(3 * E_ / 128, TB_ / 128), 256, GEMM_SMEM>>>(input, pWin, pbin, pqkv, TB_, 3 * E_, E_);
    gemm3<<<dim3(E_ / 128, (RB_ + 127) / 128), 256, GEMM_SMEM>>>(pos, pWpos, pbpos, pr, RB_, E_, E_);

    // 3) fused attention (R13-identical)
    attn_fused_impl<<<dim3(T_ / 64, B_ * H_), 256, ATTN_SMEM>>>(pqkv, pr, prw, prr, patt);

    // 4) output projection -> d_out
    gemm3<<<dim3(E_ / 128, TB_ / 128), 256, GEMM_SMEM>>>(patt, pWout, pbout, (float*)d_out, TB_, E_, E_);
}

// round 16
// speedup vs baseline: 1.1528x; 1.0171x over previous
#include <cuda_runtime.h>
#include <math.h>

#define T_  1024
#define B_  2
#define E_  1024
#define H_  16
#define D_  64
#define TB_ 2048
#define RB_ 4094

// ---------------- scratch ----------------
__device__ float g_Win [3 * E_ * E_];
__device__ float g_Wpos[E_ * E_];
__device__ float g_Wout[E_ * E_];
__device__ float g_bin [3 * E_];
__device__ float g_bpos[E_];
__device__ float g_bout[E_];
__device__ float g_rw  [E_];
__device__ float g_rr  [E_];
__device__ float g_qkv [TB_ * 3 * E_];
__device__ float g_r   [RB_ * E_];
__device__ float g_att [TB_ * E_];

// ---------------- tf32 helpers ----------------
__device__ __forceinline__ unsigned f2tf(float f) {
    unsigned r; asm("cvt.rna.tf32.f32 %0, %1;" : "=r"(r) : "f"(f)); return r;
}
__device__ __forceinline__ void split2(float v, float& hi, float& lo) {
    hi = __uint_as_float(f2tf(v));
    lo = __uint_as_float(f2tf(v - hi));
}
__device__ __forceinline__ void mma8(float* c, const float* a, const float* b) {
    asm volatile("mma.sync.aligned.m16n8k8.row.col.f32.tf32.tf32.f32 "
                 "{%0,%1,%2,%3},{%4,%5,%6,%7},{%8,%9},{%0,%1,%2,%3};"
                 : "+f"(c[0]), "+f"(c[1]), "+f"(c[2]), "+f"(c[3])
                 : "r"(__float_as_uint(a[0])), "r"(__float_as_uint(a[1])),
                   "r"(__float_as_uint(a[2])), "r"(__float_as_uint(a[3])),
                   "r"(__float_as_uint(b[0])), "r"(__float_as_uint(b[1])));
}
__device__ __forceinline__ void mma3(float* c, const float* ah, const float* al,
                                     const float* bh, const float* bl) {
    mma8(c, ah, bh);
    mma8(c, ah, bl);
    mma8(c, al, bh);
}
// ldmatrix x4 on fp32 data viewed as b16 tiles (4 regs = one tf32 A-frag or two B-frags)
__device__ __forceinline__ void ldsm4f(float* r, unsigned a) {
    unsigned x0, x1, x2, x3;
    asm volatile("ldmatrix.sync.aligned.m8n8.x4.shared.b16 {%0,%1,%2,%3}, [%4];"
                 : "=r"(x0), "=r"(x1), "=r"(x2), "=r"(x3) : "r"(a));
    r[0] = __uint_as_float(x0); r[1] = __uint_as_float(x1);
    r[2] = __uint_as_float(x2); r[3] = __uint_as_float(x3);
}

// ---------------- cp.async helpers ----------------
__device__ __forceinline__ void cpa16(unsigned d, const void* s) {
    asm volatile("cp.async.cg.shared.global [%0], [%1], 16;" :: "r"(d), "l"(s));
}
__device__ __forceinline__ void cpa16z(unsigned d, const void* s) {
    asm volatile("cp.async.cg.shared.global [%0], [%1], 16, 0;" :: "r"(d), "l"(s));
}
#define CP_COMMIT() asm volatile("cp.async.commit_group;" ::: "memory")
#define CP_WAIT0()  asm volatile("cp.async.wait_group 0;" ::: "memory")

// ---------------- fused hypernet ----------------
#define HN0 3145728
#define HN1 (HN0 + 1048576)
#define HN2 (HN1 + 1048576)
#define HN3 (HN2 + 3072)
#define HN4 (HN3 + 1024)
#define HN5 (HN4 + 1024)
#define HN6 (HN5 + 1024)
#define HN7 (HN6 + 1024)

__global__ __launch_bounds__(256) void hyper_all(
    const float* __restrict__ w_in,  const float* __restrict__ w_pos,
    const float* __restrict__ w_out, const float* __restrict__ b_in,
    const float* __restrict__ b_pos, const float* __restrict__ b_out,
    const float* __restrict__ rwb,   const float* __restrict__ rrb,
    const float* __restrict__ f,
    float* __restrict__ oWin,  float* __restrict__ oWpos,
    float* __restrict__ oWout, float* __restrict__ obin,
    float* __restrict__ obpos, float* __restrict__ obout,
    float* __restrict__ orw,   float* __restrict__ orr)
{
    int idx = blockIdx.x * blockDim.x + threadIdx.x;
    if (idx >= HN7) return;
    const float* src; float* dst; int off;
    if      (idx < HN0) { src = w_in;  dst = oWin;  off = idx; }
    else if (idx < HN1) { src = w_pos; dst = oWpos; off = idx - HN0; }
    else if (idx < HN2) { src = w_out; dst = oWout; off = idx - HN1; }
    else if (idx < HN3) { src = b_in;  dst = obin;  off = idx - HN2; }
    else if (idx < HN4) { src = b_pos; dst = obpos; off = idx - HN3; }
    else if (idx < HN5) { src = b_out; dst = obout; off = idx - HN4; }
    else if (idx < HN6) { src = rwb;   dst = orw;   off = idx - HN5; }
    else                { src = rrb;   dst = orr;   off = idx - HN6; }
    const float4* wp = (const float4*)(src + (size_t)off * 8);
    float4 a = wp[0], b = wp[1];
    float4 f0 = *(const float4*)f;
    float4 f1 = *(const float4*)(f + 4);
    dst[off] = a.x*f0.x + a.y*f0.y + a.z*f0.z + a.w*f0.w
             + b.x*f1.x + b.y*f1.y + b.z*f1.z + b.w*f1.w;
}

// ---------------- 3xtf32 NT GEMM: cp.async + LDSM fragments --------------------
#define GBUF 9216
#define GEMM_SMEM (2 * GBUF * 4)

__global__ __launch_bounds__(256, 2) void gemm3(const float* __restrict__ A,
                                                const float* __restrict__ Bm,
                                                const float* __restrict__ bias,
                                                float* __restrict__ C,
                                                int M, int N, int K)
{
    extern __shared__ float sm[];
    int bm = blockIdx.y * 128, bn = blockIdx.x * 128;
    int tid = threadIdx.x;
    int w = tid >> 5, lane = tid & 31;
    int g = lane >> 2, tg = lane & 3;
    int wm = w & 1, wn = w >> 1;
    float acc[4][4][4] = {};

    unsigned sb = (unsigned)__cvta_generic_to_shared(sm);
    const int lrow16 = lane & 15;
    const int lcol4  = (lane >> 4) << 2;
    const int bfrow  = ((lane >> 4) << 3) + (lane & 7);
    const int bfcol  = (lane & 8) ? 4 : 0;

    auto issue_tile = [&](int k0, int buf) {
        unsigned bb = sb + (unsigned)(buf * GBUF) * 4u;
#pragma unroll
        for (int it = 0; it < 4; it++) {
            int t = tid + 256 * it;
            int row = t >> 3, kq = (t & 7) << 2;
            int m = bm + row;
            unsigned da = bb + (unsigned)(row * 36 + kq) * 4u;
            if (m < M) cpa16(da, A + (size_t)m * K + k0 + kq);
            else       cpa16z(da, A);
            unsigned db = bb + (unsigned)(4608 + row * 36 + kq) * 4u;
            cpa16(db, Bm + (size_t)(bn + row) * K + k0 + kq);
        }
    };

    issue_tile(0, 0);
    CP_COMMIT();

    for (int k0 = 0; k0 < K; k0 += 32) {
        const int cur = (k0 >> 5) & 1;
        unsigned cb = sb + (unsigned)(cur * GBUF) * 4u;

        CP_WAIT0();
        __syncthreads();

        if (k0 + 32 < K) {
            issue_tile(k0 + 32, cur ^ 1);
            CP_COMMIT();
        }

#pragma unroll
        for (int ks = 0; ks < 4; ks++) {
            float ah[4][4], al[4][4], bh[4][2], bl[4][2];
#pragma unroll
            for (int mi = 0; mi < 4; mi++) {
                float av[4];
                unsigned ad = cb + (unsigned)((wm * 64 + mi * 16 + lrow16) * 36
                                              + ks * 8 + lcol4) * 4u;
                ldsm4f(av, ad);
                split2(av[0], ah[mi][0], al[mi][0]);
                split2(av[1], ah[mi][1], al[mi][1]);
                split2(av[2], ah[mi][2], al[mi][2]);
                split2(av[3], ah[mi][3], al[mi][3]);
            }
#pragma unroll
            for (int np = 0; np < 2; np++) {
                float bv[4];
                unsigned bd = cb + (unsigned)(4608 + (wn * 32 + np * 16 + bfrow) * 36
                                              + ks * 8 + bfcol) * 4u;
                ldsm4f(bv, bd);
                split2(bv[0], bh[2 * np][0],     bl[2 * np][0]);
                split2(bv[1], bh[2 * np][1],     bl[2 * np][1]);
                split2(bv[2], bh[2 * np + 1][0], bl[2 * np + 1][0]);
                split2(bv[3], bh[2 * np + 1][1], bl[2 * np + 1][1]);
            }
#pragma unroll
            for (int mi = 0; mi < 4; mi++)
#pragma unroll
                for (int ni = 0; ni < 4; ni++)
                    mma3(acc[mi][ni], ah[mi], al[mi], bh[ni], bl[ni]);
        }
    }

#pragma unroll
    for (int mi = 0; mi < 4; mi++)
#pragma unroll
        for (int ni = 0; ni < 4; ni++) {
            int m0 = bm + wm * 64 + mi * 16 + g;
            int n0 = bn + wn * 32 + ni * 8 + tg * 2;
            float bb0 = bias[n0], bb1 = bias[n0 + 1];
            if (m0 < M) {
                float2 o = {acc[mi][ni][0] + bb0, acc[mi][ni][1] + bb1};
                *(float2*)(C + (size_t)m0 * N + n0) = o;
            }
            if (m0 + 8 < M) {
                float2 o = {acc[mi][ni][2] + bb0, acc[mi][ni][3] + bb1};
                *(float2*)(C + (size_t)(m0 + 8) * N + n0) = o;
            }
        }
}

// ---------------- fused attention: R13 + LDSM fragment loads -------------------
#define QWH  0
#define QWL  4352
#define QRH  8704
#define QRL  13056
#define AKH  17408
#define AKL  22016
#define ARH  26624
#define ARL  33536
#define AG   17408
#define AP   17408
#define AVH  25856
#define AVL  30464
#define ARMX 40448
#define ARSM 40704
#define ATTN_SMEM (40960 * 4)
#define SC_ 0.125f

__global__ __launch_bounds__(256) void attn_fused_impl(const float* __restrict__ qkv,
                                                       const float* __restrict__ rproj,
                                                       const float* __restrict__ rw,
                                                       const float* __restrict__ rr,
                                                       float* __restrict__ att)
{
    extern __shared__ float sm[];
    const int bh = blockIdx.y;
    const int b = bh / H_, h = bh % H_;
    const int i0 = blockIdx.x * 64;
    const int tid = threadIdx.x;
    const int w = tid >> 5, lane = tid & 31;
    const int g = lane >> 2, tg = lane & 3;
    const int wi = w >> 2, wj = w & 3;

    unsigned sb = (unsigned)__cvta_generic_to_shared(sm);
    const int lrow16 = lane & 15;
    const int lcol4  = (lane >> 4) << 2;
    const int bfrow  = ((lane >> 4) << 3) + (lane & 7);
    const int bfcol  = (lane & 8) ? 4 : 0;

    // persistent q staging
#pragma unroll
    for (int it = 0; it < 4; it++) {
        int idx = tid + 256 * it;
        int row = idx >> 4, kq = (idx & 15) << 2;
        float4 qv = *(const float4*)(qkv + (size_t)((i0 + row) * B_ + b) * (3 * E_) + h * D_ + kq);
        float4 rwv = *(const float4*)(rw + h * D_ + kq);
        float4 rrv = *(const float4*)(rr + h * D_ + kq);
        float4 hw, lw, hr, lr;
        split2(qv.x + rwv.x, hw.x, lw.x); split2(qv.y + rwv.y, hw.y, lw.y);
        split2(qv.z + rwv.z, hw.z, lw.z); split2(qv.w + rwv.w, hw.w, lw.w);
        split2(qv.x + rrv.x, hr.x, lr.x); split2(qv.y + rrv.y, hr.y, lr.y);
        split2(qv.z + rrv.z, hr.z, lr.z); split2(qv.w + rrv.w, hr.w, lr.w);
        *(float4*)&sm[QWH + row * 68 + kq] = hw;
        *(float4*)&sm[QWL + row * 68 + kq] = lw;
        *(float4*)&sm[QRH + row * 68 + kq] = hr;
        *(float4*)&sm[QRL + row * 68 + kq] = lr;
    }

    float m_run[2][2] = {{-1e30f, -1e30f}, {-1e30f, -1e30f}};
    float l_run[2][2] = {};
    float accO[2][2][4] = {};

    float4 pk[4], pr6[6];
    {
        const int col0 = h * D_;
        const int pmin0 = T_ - 64 - i0;
#pragma unroll
        for (int it = 0; it < 4; it++) {
            int t = tid + 256 * it;
            int il = t >> 3, kq = (t & 7) << 2;
            pk[it] = *(const float4*)(qkv + (size_t)(il * B_ + b) * (3 * E_) + E_ + col0 + kq);
        }
#pragma unroll
        for (int it = 0; it < 6; it++) {
            int t = tid + 256 * it;
            int pl = t >> 3, kq = (t & 7) << 2;
            pr6[it] = (pl < 191)
                ? *(const float4*)(rproj + (size_t)((pmin0 + pl) * B_ + b) * E_ + col0 + kq)
                : make_float4(0.f, 0.f, 0.f, 0.f);
        }
    }

    for (int j0 = 0; j0 < T_; j0 += 128) {
        const int pmin = j0 - i0 + (T_ - 64);
        float accA[2][4][4] = {};
        float accG[2][6][4] = {};

        for (int c = 0; c < 2; c++) {
            __syncthreads();
#pragma unroll
            for (int it = 0; it < 4; it++) {
                int t = tid + 256 * it;
                int il = t >> 3, kq = (t & 7) << 2;
                float4 hk, lk;
                split2(pk[it].x, hk.x, lk.x); split2(pk[it].y, hk.y, lk.y);
                split2(pk[it].z, hk.z, lk.z); split2(pk[it].w, hk.w, lk.w);
                *(float4*)&sm[AKH + il * 36 + kq] = hk;
                *(float4*)&sm[AKL + il * 36 + kq] = lk;
            }
#pragma unroll
            for (int it = 0; it < 6; it++) {
                int t = tid + 256 * it;
                int pl = t >> 3, kq = (t & 7) << 2;
                float4 hh, ll;
                split2(pr6[it].x, hh.x, ll.x); split2(pr6[it].y, hh.y, ll.y);
                split2(pr6[it].z, hh.z, ll.z); split2(pr6[it].w, hh.w, ll.w);
                *(float4*)&sm[ARH + pl * 36 + kq] = hh;
                *(float4*)&sm[ARL + pl * 36 + kq] = ll;
            }
            __syncthreads();

            if (c == 0) {
                const int col0n = h * D_ + 32;
#pragma unroll
                for (int it = 0; it < 4; it++) {
                    int t = tid + 256 * it;
                    int il = t >> 3, kq = (t & 7) << 2;
                    pk[it] = *(const float4*)(qkv + (size_t)((j0 + il) * B_ + b) * (3 * E_) + E_ + col0n + kq);
                }
#pragma unroll
                for (int it = 0; it < 6; it++) {
                    int t = tid + 256 * it;
                    int pl = t >> 3, kq = (t & 7) << 2;
                    pr6[it] = (pl < 191)
                        ? *(const float4*)(rproj + (size_t)((pmin + pl) * B_ + b) * E_ + col0n + kq)
                        : make_float4(0.f, 0.f, 0.f, 0.f);
                }
            }

#pragma unroll
            for (int ks = 0; ks < 4; ks++) {
                float aWh[2][4], aWl[2][4], aRh[2][4], aRl[2][4];
#pragma unroll
                for (int mi = 0; mi < 2; mi++) {
                    unsigned rq = (unsigned)((wi * 32 + mi * 16 + lrow16) * 68
                                             + c * 32 + ks * 8 + lcol4) * 4u;
                    ldsm4f(aWh[mi], sb + (QWH * 4u) + rq);
                    ldsm4f(aWl[mi], sb + (QWL * 4u) + rq);
                    ldsm4f(aRh[mi], sb + (QRH * 4u) + rq);
                    ldsm4f(aRl[mi], sb + (QRL * 4u) + rq);
                }
#pragma unroll
                for (int np = 0; np < 2; np++) {
                    float bh2[4], bl2[4];
                    unsigned rb = (unsigned)((wj * 32 + np * 16 + bfrow) * 36
                                             + ks * 8 + bfcol) * 4u;
                    ldsm4f(bh2, sb + (AKH * 4u) + rb);
                    ldsm4f(bl2, sb + (AKL * 4u) + rb);
                    mma3(accA[0][2 * np],     aWh[0], aWl[0], bh2,     bl2);
                    mma3(accA[1][2 * np],     aWh[1], aWl[1], bh2,     bl2);
                    mma3(accA[0][2 * np + 1], aWh[0], aWl[0], bh2 + 2, bl2 + 2);
                    mma3(accA[1][2 * np + 1], aWh[1], aWl[1], bh2 + 2, bl2 + 2);
                }
#pragma unroll
                for (int np = 0; np < 3; np++) {
                    float bh2[4], bl2[4];
                    unsigned rb = (unsigned)((wj * 48 + np * 16 + bfrow) * 36
                                             + ks * 8 + bfcol) * 4u;
                    ldsm4f(bh2, sb + (ARH * 4u) + rb);
                    ldsm4f(bl2, sb + (ARL * 4u) + rb);
                    mma3(accG[0][2 * np],     aRh[0], aRl[0], bh2,     bl2);
                    mma3(accG[1][2 * np],     aRh[1], aRl[1], bh2,     bl2);
                    mma3(accG[0][2 * np + 1], aRh[0], aRl[0], bh2 + 2, bl2 + 2);
                    mma3(accG[1][2 * np + 1], aRh[1], aRl[1], bh2 + 2, bl2 + 2);
                }
            }
        }

        if (j0 + 128 < T_) {
            const int j0n = j0 + 128;
            const int pminN = j0n - i0 + (T_ - 64);
            const int col0 = h * D_;
#pragma unroll
            for (int it = 0; it < 4; it++) {
                int t = tid + 256 * it;
                int il = t >> 3, kq = (t & 7) << 2;
                pk[it] = *(const float4*)(qkv + (size_t)((j0n + il) * B_ + b) * (3 * E_) + E_ + col0 + kq);
            }
#pragma unroll
            for (int it = 0; it < 6; it++) {
                int t = tid + 256 * it;
                int pl = t >> 3, kq = (t & 7) << 2;
                pr6[it] = (pl < 191)
                    ? *(const float4*)(rproj + (size_t)((pminN + pl) * B_ + b) * E_ + col0 + kq)
                    : make_float4(0.f, 0.f, 0.f, 0.f);
            }
        }
        __syncthreads();

#pragma unroll
        for (int mi = 0; mi < 2; mi++)
#pragma unroll
            for (int ng = 0; ng < 6; ng++) {
                int row = wi * 32 + mi * 16 + g;
                int cc = wj * 48 + ng * 8 + tg * 2;
                sm[AG + row * 196 + cc]           = accG[mi][ng][0];
                sm[AG + row * 196 + cc + 1]       = accG[mi][ng][1];
                sm[AG + (row + 8) * 196 + cc]     = accG[mi][ng][2];
                sm[AG + (row + 8) * 196 + cc + 1] = accG[mi][ng][3];
            }
        __syncthreads();

        float tmax[2][2] = {{-1e30f, -1e30f}, {-1e30f, -1e30f}};
#pragma unroll
        for (int mi = 0; mi < 2; mi++)
#pragma unroll
            for (int nj = 0; nj < 4; nj++) {
                int il = wi * 32 + mi * 16 + g;
                int jl = wj * 32 + nj * 8 + tg * 2;
                int il2 = il + 8;
                accA[mi][nj][0] += sm[AG + il * 196 + (jl - il + 63)];
                accA[mi][nj][1] += sm[AG + il * 196 + (jl + 1 - il + 63)];
                accA[mi][nj][2] += sm[AG + il2 * 196 + (jl - il2 + 63)];
                accA[mi][nj][3] += sm[AG + il2 * 196 + (jl + 1 - il2 + 63)];
                tmax[mi][0] = fmaxf(tmax[mi][0], fmaxf(accA[mi][nj][0], accA[mi][nj][1]));
                tmax[mi][1] = fmaxf(tmax[mi][1], fmaxf(accA[mi][nj][2], accA[mi][nj][3]));
            }
#pragma unroll
        for (int mi = 0; mi < 2; mi++)
#pragma unroll
            for (int rp = 0; rp < 2; rp++) {
                float v = tmax[mi][rp];
                v = fmaxf(v, __shfl_xor_sync(0xffffffffu, v, 1));
                v = fmaxf(v, __shfl_xor_sync(0xffffffffu, v, 2));
                tmax[mi][rp] = v;
            }
        if (tg == 0) {
#pragma unroll
            for (int mi = 0; mi < 2; mi++)
#pragma unroll
                for (int rp = 0; rp < 2; rp++) {
                    int row = wi * 32 + mi * 16 + g + rp * 8;
                    sm[ARMX + row * 4 + wj] = tmax[mi][rp];
                }
        }
        __syncthreads();

        float mnew[2][2], fsc[2][2];
#pragma unroll
        for (int mi = 0; mi < 2; mi++)
#pragma unroll
            for (int rp = 0; rp < 2; rp++) {
                int row = wi * 32 + mi * 16 + g + rp * 8;
                float mt = fmaxf(fmaxf(sm[ARMX + row * 4 + 0], sm[ARMX + row * 4 + 1]),
                                 fmaxf(sm[ARMX + row * 4 + 2], sm[ARMX + row * 4 + 3]));
                mnew[mi][rp] = fmaxf(m_run[mi][rp], mt);
                fsc[mi][rp] = __expf((m_run[mi][rp] - mnew[mi][rp]) * SC_);
            }

        float tsum[2][2] = {};
#pragma unroll
        for (int mi = 0; mi < 2; mi++)
#pragma unroll
            for (int nj = 0; nj < 4; nj++) {
                int il = wi * 32 + mi * 16 + g;
                int jl = wj * 32 + nj * 8 + tg * 2;
                float p0 = __expf((accA[mi][nj][0] - mnew[mi][0]) * SC_);
                float p1 = __expf((accA[mi][nj][1] - mnew[mi][0]) * SC_);
                float p2 = __expf((accA[mi][nj][2] - mnew[mi][1]) * SC_);
                float p3 = __expf((accA[mi][nj][3] - mnew[mi][1]) * SC_);
                tsum[mi][0] += p0 + p1;
                tsum[mi][1] += p2 + p3;
                sm[AP + il * 132 + jl]           = __uint_as_float(f2tf(p0));
                sm[AP + il * 132 + jl + 1]       = __uint_as_float(f2tf(p1));
                sm[AP + (il + 8) * 132 + jl]     = __uint_as_float(f2tf(p2));
                sm[AP + (il + 8) * 132 + jl + 1] = __uint_as_float(f2tf(p3));
            }
#pragma unroll
        for (int mi = 0; mi < 2; mi++)
#pragma unroll
            for (int rp = 0; rp < 2; rp++) {
                float v = tsum[mi][rp];
                v += __shfl_xor_sync(0xffffffffu, v, 1);
                v += __shfl_xor_sync(0xffffffffu, v, 2);
                tsum[mi][rp] = v;
            }
        if (tg == 0) {
#pragma unroll
            for (int mi = 0; mi < 2; mi++)
#pragma unroll
                for (int rp = 0; rp < 2; rp++) {
                    int row = wi * 32 + mi * 16 + g + rp * 8;
                    sm[ARSM + row * 4 + wj] = tsum[mi][rp];
                }
        }
        __syncthreads();

#pragma unroll
        for (int mi = 0; mi < 2; mi++)
#pragma unroll
            for (int rp = 0; rp < 2; rp++) {
                int row = wi * 32 + mi * 16 + g + rp * 8;
                float lt = sm[ARSM + row * 4 + 0] + sm[ARSM + row * 4 + 1]
                         + sm[ARSM + row * 4 + 2] + sm[ARSM + row * 4 + 3];
                l_run[mi][rp] = l_run[mi][rp] * fsc[mi][rp] + lt;
                m_run[mi][rp] = mnew[mi][rp];
            }
#pragma unroll
        for (int mi = 0; mi < 2; mi++)
#pragma unroll
            for (int nd = 0; nd < 2; nd++) {
                accO[mi][nd][0] *= fsc[mi][0];
                accO[mi][nd][1] *= fsc[mi][0];
                accO[mi][nd][2] *= fsc[mi][1];
                accO[mi][nd][3] *= fsc[mi][1];
            }

        for (int jc = 0; jc < 2; jc++) {
            __syncthreads();
#pragma unroll
            for (int it = 0; it < 4; it++) {
                int t = tid + 256 * it;
                int row = t >> 4, dq = (t & 15) << 2;
                float4 vv = *(const float4*)(qkv + (size_t)((j0 + jc * 64 + row) * B_ + b) * (3 * E_)
                                             + 2 * E_ + h * D_ + dq);
                float4 hh, ll;
                split2(vv.x, hh.x, ll.x); split2(vv.y, hh.y, ll.y);
                split2(vv.z, hh.z, ll.z); split2(vv.w, hh.w, ll.w);
                *(float4*)&sm[AVH + row * 72 + dq] = hh;
                *(float4*)&sm[AVL + row * 72 + dq] = ll;
            }
            __syncthreads();
#pragma unroll
            for (int ks = 0; ks < 8; ks++) {
                float a[2][4];
#pragma unroll
                for (int mi = 0; mi < 2; mi++) {
                    unsigned r0 = (unsigned)((wi * 32 + mi * 16 + lrow16) * 132
                                             + jc * 64 + ks * 8 + lcol4) * 4u;
                    ldsm4f(a[mi], sb + (AP * 4u) + r0);
                }
#pragma unroll
                for (int nd = 0; nd < 2; nd++) {
                    int col = wj * 16 + nd * 8 + g;
                    float bhf[2], blf[2];
                    bhf[0] = sm[AVH + (ks * 8 + tg) * 72 + col];
                    bhf[1] = sm[AVH + (ks * 8 + tg + 4) * 72 + col];
                    blf[0] = sm[AVL + (ks * 8 + tg) * 72 + col];
                    blf[1] = sm[AVL + (ks * 8 + tg + 4) * 72 + col];
#pragma unroll
                    for (int mi = 0; mi < 2; mi++) {
                        mma8(accO[mi][nd], a[mi], bhf);
                        mma8(accO[mi][nd], a[mi], blf);
                    }
                }
            }
        }
    }

    float inv[2][2];
#pragma unroll
    for (int mi = 0; mi < 2; mi++)
#pragma unroll
        for (int rp = 0; rp < 2; rp++)
            inv[mi][rp] = 1.0f / l_run[mi][rp];
#pragma unroll
    for (int mi = 0; mi < 2; mi++)
#pragma unroll
        for (int nd = 0; nd < 2; nd++) {
            int row = wi * 32 + mi * 16 + g;
            int col = h * D_ + wj * 16 + nd * 8 + tg * 2;
            float2 o0 = {accO[mi][nd][0] * inv[mi][0], accO[mi][nd][1] * inv[mi][0]};
            float2 o1 = {accO[mi][nd][2] * inv[mi][1], accO[mi][nd][3] * inv[mi][1]};
            *(float2*)(att + (size_t)((i0 + row) * B_ + b) * E_ + col) = o0;
            *(float2*)(att + (size_t)((i0 + row + 8) * B_ + b) * E_ + col) = o1;
        }
}

// ---------------- launch ----------------
extern "C" void kernel_launch(void* const* d_in, const int* in_sizes, int n_in,
                              void* d_out, int out_size)
{
    (void)in_sizes; (void)n_in; (void)out_size;
    const float* input  = (const float*)d_in[0];
    const float* pos    = (const float*)d_in[1];
    const float* factor = (const float*)d_in[2];
    const float* w_in   = (const float*)d_in[3];
    const float* w_pos  = (const float*)d_in[4];
    const float* w_out  = (const float*)d_in[5];
    const float* bw_in  = (const float*)d_in[6];
    const float* bw_pos = (const float*)d_in[7];
    const float* bw_out = (const float*)d_in[8];
    const float* rwb    = (const float*)d_in[9];
    const float* rrb    = (const float*)d_in[10];

    float *pWin, *pWpos, *pWout, *pbin, *pbpos, *pbout, *prw, *prr,
          *pqkv, *pr, *patt;
    cudaGetSymbolAddress((void**)&pWin,  g_Win);
    cudaGetSymbolAddress((void**)&pWpos, g_Wpos);
    cudaGetSymbolAddress((void**)&pWout, g_Wout);
    cudaGetSymbolAddress((void**)&pbin,  g_bin);
    cudaGetSymbolAddress((void**)&pbpos, g_bpos);
    cudaGetSymbolAddress((void**)&pbout, g_bout);
    cudaGetSymbolAddress((void**)&prw,   g_rw);
    cudaGetSymbolAddress((void**)&prr,   g_rr);
    cudaGetSymbolAddress((void**)&pqkv,  g_qkv);
    cudaGetSymbolAddress((void**)&pr,    g_r);
    cudaGetSymbolAddress((void**)&patt,  g_att);

    cudaFuncSetAttribute(gemm3,           cudaFuncAttributeMaxDynamicSharedMemorySize, GEMM_SMEM);
    cudaFuncSetAttribute(attn_fused_impl, cudaFuncAttributeMaxDynamicSharedMemorySize, ATTN_SMEM);

    // 1) hypernet
    hyper_all<<<(HN7 + 255) / 256, 256>>>(w_in, w_pos, w_out, bw_in, bw_pos, bw_out,
                                          rwb, rrb, factor,
                                          pWin, pWpos, pWout, pbin, pbpos, pbout, prw, prr);

    // 2) projections (3xtf32, cp.async + LDSM)
    gemm3<<<dim3(3 * E_ / 128, TB_ / 128), 256, GEMM_SMEM>>>(input, pWin, pbin, pqkv, TB_, 3 * E_, E_);
    gemm3<<<dim3(E_ / 128, (RB_ + 127) / 128), 256, GEMM_SMEM>>>(pos, pWpos, pbpos, pr, RB_, E_, E_);

    // 3) fused attention (LDSM fragments)
    attn_fused_impl<<<dim3(T_ / 64, B_ * H_), 256, ATTN_SMEM>>>(pqkv, pr, prw, prr, patt);

    // 4) output projection -> d_out
    gemm3<<<dim3(E_ / 128, TB_ / 128), 256, GEMM_SMEM>>>(patt, pWout, pbout, (float*)d_out, TB_, E_, E_);
}

// round 17
// speedup vs baseline: 1.3064x; 1.1333x over previous
#include <cuda_runtime.h>
#include <math.h>

#define T_  1024
#define B_  2
#define E_  1024
#define H_  16
#define D_  64
#define TB_ 2048
#define RB_ 4094

// ---------------- scratch ----------------
__device__ float g_Win [3 * E_ * E_];
__device__ float g_Wpos[E_ * E_];
__device__ float g_Wout[E_ * E_];
__device__ float g_bin [3 * E_];
__device__ float g_bpos[E_];
__device__ float g_bout[E_];
__device__ float g_rw  [E_];
__device__ float g_rr  [E_];
__device__ float g_qkv [TB_ * 3 * E_];
__device__ float g_r   [RB_ * E_];
__device__ float g_att [TB_ * E_];

// ---------------- tf32 helpers ----------------
// cheap split: hi = truncate-to-19-bit(v) via mask, lo = v - hi (exact).
// lo is fed to HMMA raw; HW reads upper 19 bits (truncation), residual ~2^-21|v|.
__device__ __forceinline__ void split2(float v, float& hi, float& lo) {
    hi = __uint_as_float(__float_as_uint(v) & 0xFFFFE000u);
    lo = v - hi;
}
__device__ __forceinline__ void mma8(float* c, const float* a, const float* b) {
    asm volatile("mma.sync.aligned.m16n8k8.row.col.f32.tf32.tf32.f32 "
                 "{%0,%1,%2,%3},{%4,%5,%6,%7},{%8,%9},{%0,%1,%2,%3};"
                 : "+f"(c[0]), "+f"(c[1]), "+f"(c[2]), "+f"(c[3])
                 : "r"(__float_as_uint(a[0])), "r"(__float_as_uint(a[1])),
                   "r"(__float_as_uint(a[2])), "r"(__float_as_uint(a[3])),
                   "r"(__float_as_uint(b[0])), "r"(__float_as_uint(b[1])));
}
__device__ __forceinline__ void mma3(float* c, const float* ah, const float* al,
                                     const float* bh, const float* bl) {
    mma8(c, ah, bh);
    mma8(c, ah, bl);
    mma8(c, al, bh);
}
__device__ __forceinline__ void ldsm4f(float* r, unsigned a) {
    unsigned x0, x1, x2, x3;
    asm volatile("ldmatrix.sync.aligned.m8n8.x4.shared.b16 {%0,%1,%2,%3}, [%4];"
                 : "=r"(x0), "=r"(x1), "=r"(x2), "=r"(x3) : "r"(a));
    r[0] = __uint_as_float(x0); r[1] = __uint_as_float(x1);
    r[2] = __uint_as_float(x2); r[3] = __uint_as_float(x3);
}

// ---------------- cp.async helpers ----------------
__device__ __forceinline__ void cpa16(unsigned d, const void* s) {
    asm volatile("cp.async.cg.shared.global [%0], [%1], 16;" :: "r"(d), "l"(s));
}
__device__ __forceinline__ void cpa16z(unsigned d, const void* s) {
    asm volatile("cp.async.cg.shared.global [%0], [%1], 16, 0;" :: "r"(d), "l"(s));
}
#define CP_COMMIT() asm volatile("cp.async.commit_group;" ::: "memory")
#define CP_WAIT0()  asm volatile("cp.async.wait_group 0;" ::: "memory")

// ---------------- fused hypernet ----------------
#define HN0 3145728
#define HN1 (HN0 + 1048576)
#define HN2 (HN1 + 1048576)
#define HN3 (HN2 + 3072)
#define HN4 (HN3 + 1024)
#define HN5 (HN4 + 1024)
#define HN6 (HN5 + 1024)
#define HN7 (HN6 + 1024)

__global__ __launch_bounds__(256) void hyper_all(
    const float* __restrict__ w_in,  const float* __restrict__ w_pos,
    const float* __restrict__ w_out, const float* __restrict__ b_in,
    const float* __restrict__ b_pos, const float* __restrict__ b_out,
    const float* __restrict__ rwb,   const float* __restrict__ rrb,
    const float* __restrict__ f,
    float* __restrict__ oWin,  float* __restrict__ oWpos,
    float* __restrict__ oWout, float* __restrict__ obin,
    float* __restrict__ obpos, float* __restrict__ obout,
    float* __restrict__ orw,   float* __restrict__ orr)
{
    int idx = blockIdx.x * blockDim.x + threadIdx.x;
    if (idx >= HN7) return;
    const float* src; float* dst; int off;
    if      (idx < HN0) { src = w_in;  dst = oWin;  off = idx; }
    else if (idx < HN1) { src = w_pos; dst = oWpos; off = idx - HN0; }
    else if (idx < HN2) { src = w_out; dst = oWout; off = idx - HN1; }
    else if (idx < HN3) { src = b_in;  dst = obin;  off = idx - HN2; }
    else if (idx < HN4) { src = b_pos; dst = obpos; off = idx - HN3; }
    else if (idx < HN5) { src = b_out; dst = obout; off = idx - HN4; }
    else if (idx < HN6) { src = rwb;   dst = orw;   off = idx - HN5; }
    else                { src = rrb;   dst = orr;   off = idx - HN6; }
    const float4* wp = (const float4*)(src + (size_t)off * 8);
    float4 a = wp[0], b = wp[1];
    float4 f0 = *(const float4*)f;
    float4 f1 = *(const float4*)(f + 4);
    dst[off] = a.x*f0.x + a.y*f0.y + a.z*f0.z + a.w*f0.w
             + b.x*f1.x + b.y*f1.y + b.z*f1.z + b.w*f1.w;
}

// ---------------- 3xtf32 NT GEMM: cp.async + LDSM + cheap split ----------------
#define GBUF 9216
#define GEMM_SMEM (2 * GBUF * 4)

__global__ __launch_bounds__(256, 2) void gemm3(const float* __restrict__ A,
                                                const float* __restrict__ Bm,
                                                const float* __restrict__ bias,
                                                float* __restrict__ C,
                                                int M, int N, int K)
{
    extern __shared__ float sm[];
    int bm = blockIdx.y * 128, bn = blockIdx.x * 128;
    int tid = threadIdx.x;
    int w = tid >> 5, lane = tid & 31;
    int g = lane >> 2, tg = lane & 3;
    int wm = w & 1, wn = w >> 1;
    float acc[4][4][4] = {};

    unsigned sb = (unsigned)__cvta_generic_to_shared(sm);
    const int lrow16 = lane & 15;
    const int lcol4  = (lane >> 4) << 2;
    const int bfrow  = ((lane >> 4) << 3) + (lane & 7);
    const int bfcol  = (lane & 8) ? 4 : 0;

    auto issue_tile = [&](int k0, int buf) {
        unsigned bb = sb + (unsigned)(buf * GBUF) * 4u;
#pragma unroll
        for (int it = 0; it < 4; it++) {
            int t = tid + 256 * it;
            int row = t >> 3, kq = (t & 7) << 2;
            int m = bm + row;
            unsigned da = bb + (unsigned)(row * 36 + kq) * 4u;
            if (m < M) cpa16(da, A + (size_t)m * K + k0 + kq);
            else       cpa16z(da, A);
            unsigned db = bb + (unsigned)(4608 + row * 36 + kq) * 4u;
            cpa16(db, Bm + (size_t)(bn + row) * K + k0 + kq);
        }
    };

    issue_tile(0, 0);
    CP_COMMIT();

    for (int k0 = 0; k0 < K; k0 += 32) {
        const int cur = (k0 >> 5) & 1;
        unsigned cb = sb + (unsigned)(cur * GBUF) * 4u;

        CP_WAIT0();
        __syncthreads();

        if (k0 + 32 < K) {
            issue_tile(k0 + 32, cur ^ 1);
            CP_COMMIT();
        }

#pragma unroll
        for (int ks = 0; ks < 4; ks++) {
            float ah[4][4], al[4][4], bh[4][2], bl[4][2];
#pragma unroll
            for (int mi = 0; mi < 4; mi++) {
                float av[4];
                unsigned ad = cb + (unsigned)((wm * 64 + mi * 16 + lrow16) * 36
                                              + ks * 8 + lcol4) * 4u;
                ldsm4f(av, ad);
                split2(av[0], ah[mi][0], al[mi][0]);
                split2(av[1], ah[mi][1], al[mi][1]);
                split2(av[2], ah[mi][2], al[mi][2]);
                split2(av[3], ah[mi][3], al[mi][3]);
            }
#pragma unroll
            for (int np = 0; np < 2; np++) {
                float bv[4];
                unsigned bd = cb + (unsigned)(4608 + (wn * 32 + np * 16 + bfrow) * 36
                                              + ks * 8 + bfcol) * 4u;
                ldsm4f(bv, bd);
                split2(bv[0], bh[2 * np][0],     bl[2 * np][0]);
                split2(bv[1], bh[2 * np][1],     bl[2 * np][1]);
                split2(bv[2], bh[2 * np + 1][0], bl[2 * np + 1][0]);
                split2(bv[3], bh[2 * np + 1][1], bl[2 * np + 1][1]);
            }
#pragma unroll
            for (int mi = 0; mi < 4; mi++)
#pragma unroll
                for (int ni = 0; ni < 4; ni++)
                    mma3(acc[mi][ni], ah[mi], al[mi], bh[ni], bl[ni]);
        }
    }

#pragma unroll
    for (int mi = 0; mi < 4; mi++)
#pragma unroll
        for (int ni = 0; ni < 4; ni++) {
            int m0 = bm + wm * 64 + mi * 16 + g;
            int n0 = bn + wn * 32 + ni * 8 + tg * 2;
            float bb0 = bias[n0], bb1 = bias[n0 + 1];
            if (m0 < M) {
                float2 o = {acc[mi][ni][0] + bb0, acc[mi][ni][1] + bb1};
                *(float2*)(C + (size_t)m0 * N + n0) = o;
            }
            if (m0 + 8 < M) {
                float2 o = {acc[mi][ni][2] + bb0, acc[mi][ni][3] + bb1};
                *(float2*)(C + (size_t)(m0 + 8) * N + n0) = o;
            }
        }
}

// ---------------- fused attention: LDSM + cheap split --------------------------
#define QWH  0
#define QWL  4352
#define QRH  8704
#define QRL  13056
#define AKH  17408
#define AKL  22016
#define ARH  26624
#define ARL  33536
#define AG   17408
#define AP   17408
#define AVH  25856
#define AVL  30464
#define ARMX 40448
#define ARSM 40704
#define ATTN_SMEM (40960 * 4)
#define SC_ 0.125f

__global__ __launch_bounds__(256) void attn_fused_impl(const float* __restrict__ qkv,
                                                       const float* __restrict__ rproj,
                                                       const float* __restrict__ rw,
                                                       const float* __restrict__ rr,
                                                       float* __restrict__ att)
{
    extern __shared__ float sm[];
    const int bh = blockIdx.y;
    const int b = bh / H_, h = bh % H_;
    const int i0 = blockIdx.x * 64;
    const int tid = threadIdx.x;
    const int w = tid >> 5, lane = tid & 31;
    const int g = lane >> 2, tg = lane & 3;
    const int wi = w >> 2, wj = w & 3;

    unsigned sb = (unsigned)__cvta_generic_to_shared(sm);
    const int lrow16 = lane & 15;
    const int lcol4  = (lane >> 4) << 2;
    const int bfrow  = ((lane >> 4) << 3) + (lane & 7);
    const int bfcol  = (lane & 8) ? 4 : 0;

    // persistent q staging
#pragma unroll
    for (int it = 0; it < 4; it++) {
        int idx = tid + 256 * it;
        int row = idx >> 4, kq = (idx & 15) << 2;
        float4 qv = *(const float4*)(qkv + (size_t)((i0 + row) * B_ + b) * (3 * E_) + h * D_ + kq);
        float4 rwv = *(const float4*)(rw + h * D_ + kq);
        float4 rrv = *(const float4*)(rr + h * D_ + kq);
        float4 hw, lw, hr, lr;
        split2(qv.x + rwv.x, hw.x, lw.x); split2(qv.y + rwv.y, hw.y, lw.y);
        split2(qv.z + rwv.z, hw.z, lw.z); split2(qv.w + rwv.w, hw.w, lw.w);
        split2(qv.x + rrv.x, hr.x, lr.x); split2(qv.y + rrv.y, hr.y, lr.y);
        split2(qv.z + rrv.z, hr.z, lr.z); split2(qv.w + rrv.w, hr.w, lr.w);
        *(float4*)&sm[QWH + row * 68 + kq] = hw;
        *(float4*)&sm[QWL + row * 68 + kq] = lw;
        *(float4*)&sm[QRH + row * 68 + kq] = hr;
        *(float4*)&sm[QRL + row * 68 + kq] = lr;
    }

    float m_run[2][2] = {{-1e30f, -1e30f}, {-1e30f, -1e30f}};
    float l_run[2][2] = {};
    float accO[2][2][4] = {};

    float4 pk[4], pr6[6];
    {
        const int col0 = h * D_;
        const int pmin0 = T_ - 64 - i0;
#pragma unroll
        for (int it = 0; it < 4; it++) {
            int t = tid + 256 * it;
            int il = t >> 3, kq = (t & 7) << 2;
            pk[it] = *(const float4*)(qkv + (size_t)(il * B_ + b) * (3 * E_) + E_ + col0 + kq);
        }
#pragma unroll
        for (int it = 0; it < 6; it++) {
            int t = tid + 256 * it;
            int pl = t >> 3, kq = (t & 7) << 2;
            pr6[it] = (pl < 191)
                ? *(const float4*)(rproj + (size_t)((pmin0 + pl) * B_ + b) * E_ + col0 + kq)
                : make_float4(0.f, 0.f, 0.f, 0.f);
        }
    }

    for (int j0 = 0; j0 < T_; j0 += 128) {
        const int pmin = j0 - i0 + (T_ - 64);
        float accA[2][4][4] = {};
        float accG[2][6][4] = {};

        for (int c = 0; c < 2; c++) {
            __syncthreads();
#pragma unroll
            for (int it = 0; it < 4; it++) {
                int t = tid + 256 * it;
                int il = t >> 3, kq = (t & 7) << 2;
                float4 hk, lk;
                split2(pk[it].x, hk.x, lk.x); split2(pk[it].y, hk.y, lk.y);
                split2(pk[it].z, hk.z, lk.z); split2(pk[it].w, hk.w, lk.w);
                *(float4*)&sm[AKH + il * 36 + kq] = hk;
                *(float4*)&sm[AKL + il * 36 + kq] = lk;
            }
#pragma unroll
            for (int it = 0; it < 6; it++) {
                int t = tid + 256 * it;
                int pl = t >> 3, kq = (t & 7) << 2;
                float4 hh, ll;
                split2(pr6[it].x, hh.x, ll.x); split2(pr6[it].y, hh.y, ll.y);
                split2(pr6[it].z, hh.z, ll.z); split2(pr6[it].w, hh.w, ll.w);
                *(float4*)&sm[ARH + pl * 36 + kq] = hh;
                *(float4*)&sm[ARL + pl * 36 + kq] = ll;
            }
            __syncthreads();

            if (c == 0) {
                const int col0n = h * D_ + 32;
#pragma unroll
                for (int it = 0; it < 4; it++) {
                    int t = tid + 256 * it;
                    int il = t >> 3, kq = (t & 7) << 2;
                    pk[it] = *(const float4*)(qkv + (size_t)((j0 + il) * B_ + b) * (3 * E_) + E_ + col0n + kq);
                }
#pragma unroll
                for (int it = 0; it < 6; it++) {
                    int t = tid + 256 * it;
                    int pl = t >> 3, kq = (t & 7) << 2;
                    pr6[it] = (pl < 191)
                        ? *(const float4*)(rproj + (size_t)((pmin + pl) * B_ + b) * E_ + col0n + kq)
                        : make_float4(0.f, 0.f, 0.f, 0.f);
                }
            }

#pragma unroll
            for (int ks = 0; ks < 4; ks++) {
                float aWh[2][4], aWl[2][4], aRh[2][4], aRl[2][4];
#pragma unroll
                for (int mi = 0; mi < 2; mi++) {
                    unsigned rq = (unsigned)((wi * 32 + mi * 16 + lrow16) * 68
                                             + c * 32 + ks * 8 + lcol4) * 4u;
                    ldsm4f(aWh[mi], sb + (QWH * 4u) + rq);
                    ldsm4f(aWl[mi], sb + (QWL * 4u) + rq);
                    ldsm4f(aRh[mi], sb + (QRH * 4u) + rq);
                    ldsm4f(aRl[mi], sb + (QRL * 4u) + rq);
                }
#pragma unroll
                for (int np = 0; np < 2; np++) {
                    float bh2[4], bl2[4];
                    unsigned rb = (unsigned)((wj * 32 + np * 16 + bfrow) * 36
                                             + ks * 8 + bfcol) * 4u;
                    ldsm4f(bh2, sb + (AKH * 4u) + rb);
                    ldsm4f(bl2, sb + (AKL * 4u) + rb);
                    mma3(accA[0][2 * np],     aWh[0], aWl[0], bh2,     bl2);
                    mma3(accA[1][2 * np],     aWh[1], aWl[1], bh2,     bl2);
                    mma3(accA[0][2 * np + 1], aWh[0], aWl[0], bh2 + 2, bl2 + 2);
                    mma3(accA[1][2 * np + 1], aWh[1], aWl[1], bh2 + 2, bl2 + 2);
                }
#pragma unroll
                for (int np = 0; np < 3; np++) {
                    float bh2[4], bl2[4];
                    unsigned rb = (unsigned)((wj * 48 + np * 16 + bfrow) * 36
                                             + ks * 8 + bfcol) * 4u;
                    ldsm4f(bh2, sb + (ARH * 4u) + rb);
                    ldsm4f(bl2, sb + (ARL * 4u) + rb);
                    mma3(accG[0][2 * np],     aRh[0], aRl[0], bh2,     bl2);
                    mma3(accG[1][2 * np],     aRh[1], aRl[1], bh2,     bl2);
                    mma3(accG[0][2 * np + 1], aRh[0], aRl[0], bh2 + 2, bl2 + 2);
                    mma3(accG[1][2 * np + 1], aRh[1], aRl[1], bh2 + 2, bl2 + 2);
                }
            }
        }

        if (j0 + 128 < T_) {
            const int j0n = j0 + 128;
            const int pminN = j0n - i0 + (T_ - 64);
            const int col0 = h * D_;
#pragma unroll
            for (int it = 0; it < 4; it++) {
                int t = tid + 256 * it;
                int il = t >> 3, kq = (t & 7) << 2;
                pk[it] = *(const float4*)(qkv + (size_t)((j0n + il) * B_ + b) * (3 * E_) + E_ + col0 + kq);
            }
#pragma unroll
            for (int it = 0; it < 6; it++) {
                int t = tid + 256 * it;
                int pl = t >> 3, kq = (t & 7) << 2;
                pr6[it] = (pl < 191)
                    ? *(const float4*)(rproj + (size_t)((pminN + pl) * B_ + b) * E_ + col0 + kq)
                    : make_float4(0.f, 0.f, 0.f, 0.f);
            }
        }
        __syncthreads();

#pragma unroll
        for (int mi = 0; mi < 2; mi++)
#pragma unroll
            for (int ng = 0; ng < 6; ng++) {
                int row = wi * 32 + mi * 16 + g;
                int cc = wj * 48 + ng * 8 + tg * 2;
                sm[AG + row * 196 + cc]           = accG[mi][ng][0];
                sm[AG + row * 196 + cc + 1]       = accG[mi][ng][1];
                sm[AG + (row + 8) * 196 + cc]     = accG[mi][ng][2];
                sm[AG + (row + 8) * 196 + cc + 1] = accG[mi][ng][3];
            }
        __syncthreads();

        float tmax[2][2] = {{-1e30f, -1e30f}, {-1e30f, -1e30f}};
#pragma unroll
        for (int mi = 0; mi < 2; mi++)
#pragma unroll
            for (int nj = 0; nj < 4; nj++) {
                int il = wi * 32 + mi * 16 + g;
                int jl = wj * 32 + nj * 8 + tg * 2;
                int il2 = il + 8;
                accA[mi][nj][0] += sm[AG + il * 196 + (jl - il + 63)];
                accA[mi][nj][1] += sm[AG + il * 196 + (jl + 1 - il + 63)];
                accA[mi][nj][2] += sm[AG + il2 * 196 + (jl - il2 + 63)];
                accA[mi][nj][3] += sm[AG + il2 * 196 + (jl + 1 - il2 + 63)];
                tmax[mi][0] = fmaxf(tmax[mi][0], fmaxf(accA[mi][nj][0], accA[mi][nj][1]));
                tmax[mi][1] = fmaxf(tmax[mi][1], fmaxf(accA[mi][nj][2], accA[mi][nj][3]));
            }
#pragma unroll
        for (int mi = 0; mi < 2; mi++)
#pragma unroll
            for (int rp = 0; rp < 2; rp++) {
                float v = tmax[mi][rp];
                v = fmaxf(v, __shfl_xor_sync(0xffffffffu, v, 1));
                v = fmaxf(v, __shfl_xor_sync(0xffffffffu, v, 2));
                tmax[mi][rp] = v;
            }
        if (tg == 0) {
#pragma unroll
            for (int mi = 0; mi < 2; mi++)
#pragma unroll
                for (int rp = 0; rp < 2; rp++) {
                    int row = wi * 32 + mi * 16 + g + rp * 8;
                    sm[ARMX + row * 4 + wj] = tmax[mi][rp];
                }
        }
        __syncthreads();

        float mnew[2][2], fsc[2][2];
#pragma unroll
        for (int mi = 0; mi < 2; mi++)
#pragma unroll
            for (int rp = 0; rp < 2; rp++) {
                int row = wi * 32 + mi * 16 + g + rp * 8;
                float mt = fmaxf(fmaxf(sm[ARMX + row * 4 + 0], sm[ARMX + row * 4 + 1]),
                                 fmaxf(sm[ARMX + row * 4 + 2], sm[ARMX + row * 4 + 3]));
                mnew[mi][rp] = fmaxf(m_run[mi][rp], mt);
                fsc[mi][rp] = __expf((m_run[mi][rp] - mnew[mi][rp]) * SC_);
            }

        float tsum[2][2] = {};
#pragma unroll
        for (int mi = 0; mi < 2; mi++)
#pragma unroll
            for (int nj = 0; nj < 4; nj++) {
                int il = wi * 32 + mi * 16 + g;
                int jl = wj * 32 + nj * 8 + tg * 2;
                float p0 = __expf((accA[mi][nj][0] - mnew[mi][0]) * SC_);
                float p1 = __expf((accA[mi][nj][1] - mnew[mi][0]) * SC_);
                float p2 = __expf((accA[mi][nj][2] - mnew[mi][1]) * SC_);
                float p3 = __expf((accA[mi][nj][3] - mnew[mi][1]) * SC_);
                tsum[mi][0] += p0 + p1;
                tsum[mi][1] += p2 + p3;
                sm[AP + il * 132 + jl]           = p0;
                sm[AP + il * 132 + jl + 1]       = p1;
                sm[AP + (il + 8) * 132 + jl]     = p2;
                sm[AP + (il + 8) * 132 + jl + 1] = p3;
            }
#pragma unroll
        for (int mi = 0; mi < 2; mi++)
#pragma unroll
            for (int rp = 0; rp < 2; rp++) {
                float v = tsum[mi][rp];
                v += __shfl_xor_sync(0xffffffffu, v, 1);
                v += __shfl_xor_sync(0xffffffffu, v, 2);
                tsum[mi][rp] = v;
            }
        if (tg == 0) {
#pragma unroll
            for (int mi = 0; mi < 2; mi++)
#pragma unroll
                for (int rp = 0; rp < 2; rp++) {
                    int row = wi * 32 + mi * 16 + g + rp * 8;
                    sm[ARSM + row * 4 + wj] = tsum[mi][rp];
                }
        }
        __syncthreads();

#pragma unroll
        for (int mi = 0; mi < 2; mi++)
#pragma unroll
            for (int rp = 0; rp < 2; rp++) {
                int row = wi * 32 + mi * 16 + g + rp * 8;
                float lt = sm[ARSM + row * 4 + 0] + sm[ARSM + row * 4 + 1]
                         + sm[ARSM + row * 4 + 2] + sm[ARSM + row * 4 + 3];
                l_run[mi][rp] = l_run[mi][rp] * fsc[mi][rp] + lt;
                m_run[mi][rp] = mnew[mi][rp];
            }
#pragma unroll
        for (int mi = 0; mi < 2; mi++)
#pragma unroll
            for (int nd = 0; nd < 2; nd++) {
                accO[mi][nd][0] *= fsc[mi][0];
                accO[mi][nd][1] *= fsc[mi][0];
                accO[mi][nd][2] *= fsc[mi][1];
                accO[mi][nd][3] *= fsc[mi][1];
            }

        for (int jc = 0; jc < 2; jc++) {
            __syncthreads();
#pragma unroll
            for (int it = 0; it < 4; it++) {
                int t = tid + 256 * it;
                int row = t >> 4, dq = (t & 15) << 2;
                float4 vv = *(const float4*)(qkv + (size_t)((j0 + jc * 64 + row) * B_ + b) * (3 * E_)
                                             + 2 * E_ + h * D_ + dq);
                float4 hh, ll;
                split2(vv.x, hh.x, ll.x); split2(vv.y, hh.y, ll.y);
                split2(vv.z, hh.z, ll.z); split2(vv.w, hh.w, ll.w);
                *(float4*)&sm[AVH + row * 72 + dq] = hh;
                *(float4*)&sm[AVL + row * 72 + dq] = ll;
            }
            __syncthreads();
#pragma unroll
            for (int ks = 0; ks < 8; ks++) {
                float a[2][4];
#pragma unroll
                for (int mi = 0; mi < 2; mi++) {
                    unsigned r0 = (unsigned)((wi * 32 + mi * 16 + lrow16) * 132
                                             + jc * 64 + ks * 8 + lcol4) * 4u;
                    ldsm4f(a[mi], sb + (AP * 4u) + r0);
                }
#pragma unroll
                for (int nd = 0; nd < 2; nd++) {
                    int col = wj * 16 + nd * 8 + g;
                    float bhf[2], blf[2];
                    bhf[0] = sm[AVH + (ks * 8 + tg) * 72 + col];
                    bhf[1] = sm[AVH + (ks * 8 + tg + 4) * 72 + col];
                    blf[0] = sm[AVL + (ks * 8 + tg) * 72 + col];
                    blf[1] = sm[AVL + (ks * 8 + tg + 4) * 72 + col];
#pragma unroll
                    for (int mi = 0; mi < 2; mi++) {
                        mma8(accO[mi][nd], a[mi], bhf);
                        mma8(accO[mi][nd], a[mi], blf);
                    }
                }
            }
        }
    }

    float inv[2][2];
#pragma unroll
    for (int mi = 0; mi < 2; mi++)
#pragma unroll
        for (int rp = 0; rp < 2; rp++)
            inv[mi][rp] = 1.0f / l_run[mi][rp];
#pragma unroll
    for (int mi = 0; mi < 2; mi++)
#pragma unroll
        for (int nd = 0; nd < 2; nd++) {
            int row = wi * 32 + mi * 16 + g;
            int col = h * D_ + wj * 16 + nd * 8 + tg * 2;
            float2 o0 = {accO[mi][nd][0] * inv[mi][0], accO[mi][nd][1] * inv[mi][0]};
            float2 o1 = {accO[mi][nd][2] * inv[mi][1], accO[mi][nd][3] * inv[mi][1]};
            *(float2*)(att + (size_t)((i0 + row) * B_ + b) * E_ + col) = o0;
            *(float2*)(att + (size_t)((i0 + row + 8) * B_ + b) * E_ + col) = o1;
        }
}

// ---------------- launch ----------------
extern "C" void kernel_launch(void* const* d_in, const int* in_sizes, int n_in,
                              void* d_out, int out_size)
{
    (void)in_sizes; (void)n_in; (void)out_size;
    const float* input  = (const float*)d_in[0];
    const float* pos    = (const float*)d_in[1];
    const float* factor = (const float*)d_in[2];
    const float* w_in   = (const float*)d_in[3];
    const float* w_pos  = (const float*)d_in[4];
    const float* w_out  = (const float*)d_in[5];
    const float* bw_in  = (const float*)d_in[6];
    const float* bw_pos = (const float*)d_in[7];
    const float* bw_out = (const float*)d_in[8];
    const float* rwb    = (const float*)d_in[9];
    const float* rrb    = (const float*)d_in[10];

    float *pWin, *pWpos, *pWout, *pbin, *pbpos, *pbout, *prw, *prr,
          *pqkv, *pr, *patt;
    cudaGetSymbolAddress((void**)&pWin,  g_Win);
    cudaGetSymbolAddress((void**)&pWpos, g_Wpos);
    cudaGetSymbolAddress((void**)&pWout, g_Wout);
    cudaGetSymbolAddress((void**)&pbin,  g_bin);
    cudaGetSymbolAddress((void**)&pbpos, g_bpos);
    cudaGetSymbolAddress((void**)&pbout, g_bout);
    cudaGetSymbolAddress((void**)&prw,   g_rw);
    cudaGetSymbolAddress((void**)&prr,   g_rr);
    cudaGetSymbolAddress((void**)&pqkv,  g_qkv);
    cudaGetSymbolAddress((void**)&pr,    g_r);
    cudaGetSymbolAddress((void**)&patt,  g_att);

    cudaFuncSetAttribute(gemm3,           cudaFuncAttributeMaxDynamicSharedMemorySize, GEMM_SMEM);
    cudaFuncSetAttribute(attn_fused_impl, cudaFuncAttributeMaxDynamicSharedMemorySize, ATTN_SMEM);

    // 1) hypernet
    hyper_all<<<(HN7 + 255) / 256, 256>>>(w_in, w_pos, w_out, bw_in, bw_pos, bw_out,
                                          rwb, rrb, factor,
                                          pWin, pWpos, pWout, pbin, pbpos, pbout, prw, prr);

    // 2) projections (3xtf32, cp.async + LDSM + cheap split)
    gemm3<<<dim3(3 * E_ / 128, TB_ / 128), 256, GEMM_SMEM>>>(input, pWin, pbin, pqkv, TB_, 3 * E_, E_);
    gemm3<<<dim3(E_ / 128, (RB_ + 127) / 128), 256, GEMM_SMEM>>>(pos, pWpos, pbpos, pr, RB_, E_, E_);

    // 3) fused attention (cheap split, raw-P store)
    attn_fused_impl<<<dim3(T_ / 64, B_ * H_), 256, ATTN_SMEM>>>(pqkv, pr, prw, prr, patt);

    // 4) output projection -> d_out
    gemm3<<<dim3(E_ / 128, TB_ / 128), 256, GEMM_SMEM>>>(patt, pWout, pbout, (float*)d_out, TB_, E_, E_);
}